// round 10
// baseline (speedup 1.0000x reference)
#include <cuda_runtime.h>
#include <cuda_bf16.h>
#include <cuda_fp16.h>
#include <cstdint>

// ===========================================================================
// ICNN forward + input-gradient.
// Chain + head: bf16 hi/lo pairs, 3 MMA products (proven: rel_err 2.8e-4).
// Tails only: fp16 pair x fp16 single weights, 2 products (tail errors are
// NOT chain-amplified; per-layer 16^-(9-l) power-of-2 scale avoids overflow).
// ===========================================================================

typedef __nv_bfloat16 bf16;
typedef __half f16;

#define NEG_SLOPE 0.2f
constexpr int Bsz = 8192;
constexpr int Dd  = 128;
constexpr int Hh  = 512;
constexpr int Ll  = 10;
constexpr int LH  = Ll * Hh;  // 5120

// ---------------- static device scratch ------------------------------------
__device__ bf16 g_xh[(size_t)Bsz * Dd], g_xl[(size_t)Bsz * Dd];
__device__ bf16 g_Wqh[(size_t)LH * Dd], g_Wql[(size_t)LH * Dd];
__device__ bf16 g_Wlh[(size_t)LH * Dd], g_Wll[(size_t)LH * Dd];
__device__ bf16 g_Wzh[(size_t)(Ll - 1) * Hh * Hh], g_Wzl[(size_t)(Ll - 1) * Hh * Hh];
__device__ bf16 g_WzTh[(size_t)(Ll - 1) * Hh * Hh], g_WzTl[(size_t)(Ll - 1) * Hh * Hh];
__device__ f16  g_Bc16[(size_t)Ll * Dd * 1024];
__device__ float g_U[(size_t)Bsz * LH];
__device__ float g_P[(size_t)Bsz * LH];
__device__ unsigned char g_F[(size_t)Bsz * LH];
__device__ bf16 g_zAh[(size_t)Bsz * Hh], g_zAl[(size_t)Bsz * Hh];
__device__ bf16 g_zBh[(size_t)Bsz * Hh], g_zBl[(size_t)Bsz * Hh];
__device__ f16 g_Ach0[(size_t)Bsz * 1024], g_Acl0[(size_t)Bsz * 1024];
__device__ f16 g_Ach1[(size_t)Bsz * 1024], g_Acl1[(size_t)Bsz * 1024];
__device__ float g_gx[(size_t)Bsz * Dd];
__device__ float g_S[Bsz];

// ---------------- helpers ---------------------------------------------------
__device__ __forceinline__ uint32_t smem_u32(const void* p) {
  uint32_t a;
  asm("{ .reg .u64 t; cvta.to.shared.u64 t, %1; cvt.u32.u64 %0, t; }"
      : "=r"(a) : "l"(p));
  return a;
}
__device__ __forceinline__ void cpa16(uint32_t s, const void* g) {
  asm volatile("cp.async.cg.shared.global [%0], [%1], 16;" ::"r"(s), "l"(g));
}
__device__ __forceinline__ void cpa_commit() {
  asm volatile("cp.async.commit_group;" ::: "memory");
}
__device__ __forceinline__ void cpa_wait0() {
  asm volatile("cp.async.wait_group 0;" ::: "memory");
}
__device__ __forceinline__ void ldsm4(uint32_t addr, uint32_t* r) {
  asm volatile("ldmatrix.sync.aligned.m8n8.x4.shared.b16 {%0,%1,%2,%3}, [%4];"
               : "=r"(r[0]), "=r"(r[1]), "=r"(r[2]), "=r"(r[3]) : "r"(addr));
}
__device__ __forceinline__ void mma_bf16(float* c, const uint32_t* a,
                                         const uint32_t* b) {
  asm volatile(
      "mma.sync.aligned.m16n8k16.row.col.f32.bf16.bf16.f32 "
      "{%0,%1,%2,%3}, {%4,%5,%6,%7}, {%8,%9}, {%0,%1,%2,%3};"
      : "+f"(c[0]), "+f"(c[1]), "+f"(c[2]), "+f"(c[3])
      : "r"(a[0]), "r"(a[1]), "r"(a[2]), "r"(a[3]), "r"(b[0]), "r"(b[1]));
}
__device__ __forceinline__ void mma_f16(float* c, const uint32_t* a,
                                        const uint32_t* b) {
  asm volatile(
      "mma.sync.aligned.m16n8k16.row.col.f32.f16.f16.f32 "
      "{%0,%1,%2,%3}, {%4,%5,%6,%7}, {%8,%9}, {%0,%1,%2,%3};"
      : "+f"(c[0]), "+f"(c[1]), "+f"(c[2]), "+f"(c[3])
      : "r"(a[0]), "r"(a[1]), "r"(a[2]), "r"(a[3]), "r"(b[0]), "r"(b[1]));
}
__device__ __forceinline__ void bsplit(float v, bf16& h, bf16& l) {
  h = __float2bfloat16(v);
  l = __float2bfloat16(v - __bfloat162float(h));
}
__device__ __forceinline__ void hsplit(float v, f16& h, f16& l) {
  h = __float2half_rn(v);
  l = __float2half_rn(v - __half2float(h));
}

// ---------------- epilogue params -------------------------------------------
struct EpiP {
  const float* U;
  const float* Pc;
  unsigned char* F;
  bf16* zh;
  bf16* zl;
  f16* ach;
  f16* acl;
  float* gx;
  int coff;
  float ascale;  // EPI3: Acat write scale = 16^-(9-l)
  float tscale;  // EPI4: gx accumulate scale = 16^(9-l)
};

// EPI: 2=fwd layer; 3=bwd layer; 4=gx accum (tail)
template <int EPI>
__device__ __forceinline__ void epi_pair(int m, int n, float d0, float d1,
                                         const EpiP& ep) {
  if (EPI == 2) {
    size_t idx = (size_t)m * LH + ep.coff + n;
    float2 pc = *reinterpret_cast<const float2*>(&ep.Pc[idx]);
    float a0 = d0 + pc.x, a1 = d1 + pc.y;
    bool p0 = (a0 >= 0.f), p1 = (a1 >= 0.f);
    uchar2 f2;
    f2.x = p0 ? 1 : 0;
    f2.y = p1 ? 1 : 0;
    *reinterpret_cast<uchar2*>(&ep.F[idx]) = f2;
    float z0 = p0 ? a0 : NEG_SLOPE * a0;
    float z1 = p1 ? a1 : NEG_SLOPE * a1;
    bf16 h0, l0, h1, l1;
    bsplit(z0, h0, l0);
    bsplit(z1, h1, l1);
    __nv_bfloat162 hv, lv;
    hv.x = h0; hv.y = h1;
    lv.x = l0; lv.y = l1;
    *reinterpret_cast<__nv_bfloat162*>(&ep.zh[(size_t)m * Hh + n]) = hv;
    *reinterpret_cast<__nv_bfloat162*>(&ep.zl[(size_t)m * Hh + n]) = lv;
  } else if (EPI == 3) {
    size_t idx = (size_t)m * LH + ep.coff + n;
    uchar2 f2 = *reinterpret_cast<const uchar2*>(&ep.F[idx]);
    float f0 = f2.x ? 1.f : NEG_SLOPE;
    float f1 = f2.y ? 1.f : NEG_SLOPE;
    float ga0 = d0 * f0, ga1 = d1 * f1;
    // z buffers (next bwd layer input): bf16 pair, unscaled
    bf16 gh0, gl0, gh1, gl1;
    bsplit(ga0, gh0, gl0);
    bsplit(ga1, gh1, gl1);
    __nv_bfloat162 bv;
    bv.x = gh0; bv.y = gh1;
    *reinterpret_cast<__nv_bfloat162*>(&ep.zh[(size_t)m * Hh + n]) = bv;
    bv.x = gl0; bv.y = gl1;
    *reinterpret_cast<__nv_bfloat162*>(&ep.zl[(size_t)m * Hh + n]) = bv;
    // Acat (tail input): fp16 pair, scaled by 16^-(9-l)
    float2 uu = *reinterpret_cast<const float2*>(&ep.U[idx]);
    float as0 = ga0 * ep.ascale, as1 = ga1 * ep.ascale;
    float g10 = 2.f * as0 * uu.x, g11 = 2.f * as1 * uu.y;
    f16 th0, tl0, th1, tl1;
    size_t ai = (size_t)m * 1024 + n;
    __half2 hv;
    hsplit(g10, th0, tl0);
    hsplit(g11, th1, tl1);
    hv.x = th0; hv.y = th1;
    *reinterpret_cast<__half2*>(&ep.ach[ai]) = hv;
    hv.x = tl0; hv.y = tl1;
    *reinterpret_cast<__half2*>(&ep.acl[ai]) = hv;
    hsplit(as0, th0, tl0);
    hsplit(as1, th1, tl1);
    hv.x = th0; hv.y = th1;
    *reinterpret_cast<__half2*>(&ep.ach[ai + Hh]) = hv;
    hv.x = tl0; hv.y = tl1;
    *reinterpret_cast<__half2*>(&ep.acl[ai + Hh]) = hv;
  } else {  // EPI == 4
    atomicAdd(&ep.gx[(size_t)m * Dd + n], d0 * ep.tscale);
    atomicAdd(&ep.gx[(size_t)m * Dd + n + 1], d1 * ep.tscale);
  }
}

// ---------------- chain GEMM (bf16, 3 products) ------------------------------
// C[128,128]/CTA = (Ah+Al)[M,K] @ (Bh+Bl)[N,K]^T.
// 8 warps, warp tile 32x64. BK=32 double-buffered cp.async.
template <int EPI>
__global__ __launch_bounds__(256) void mma_gemm(
    const bf16* __restrict__ Ah, const bf16* __restrict__ Al,
    const bf16* __restrict__ Bh, const bf16* __restrict__ Bl, int Kc, int lda,
    int ldb, EpiP ep) {
  extern __shared__ char smc[];
  const uint32_t sb = smem_u32(smc);
  const int tid = threadIdx.x, lane = tid & 31, wid = tid >> 5;
  const int m0 = blockIdx.y * 128, n0 = blockIdx.x * 128;
  const int wm = (wid & 3) * 32, wn = (wid >> 2) * 64;
  constexpr uint32_t PL = 10240;
  constexpr uint32_t STG = 40960;

  const int lr = tid >> 1;
  const int lc = (tid & 1) * 2;

  const bf16* pA0 = Ah + (size_t)(m0 + lr) * lda + lc * 8;
  const bf16* pA1 = Al + (size_t)(m0 + lr) * lda + lc * 8;
  const bf16* pB0 = Bh + (size_t)(n0 + lr) * ldb + lc * 8;
  const bf16* pB1 = Bl + (size_t)(n0 + lr) * ldb + lc * 8;

  auto stage_load = [&](int s, int k0) {
    uint32_t base = sb + (uint32_t)s * STG + (uint32_t)lr * 80 + lc * 16;
    cpa16(base, pA0 + k0);
    cpa16(base + 16, pA0 + k0 + 8);
    cpa16(base + PL, pA1 + k0);
    cpa16(base + PL + 16, pA1 + k0 + 8);
    cpa16(base + 2 * PL, pB0 + k0);
    cpa16(base + 2 * PL + 16, pB0 + k0 + 8);
    cpa16(base + 3 * PL, pB1 + k0);
    cpa16(base + 3 * PL + 16, pB1 + k0 + 8);
    cpa_commit();
  };

  float acc[2][8][4];
#pragma unroll
  for (int i = 0; i < 2; i++)
#pragma unroll
    for (int j = 0; j < 8; j++)
#pragma unroll
      for (int q = 0; q < 4; q++) acc[i][j][q] = 0.f;

  const int nk = Kc / 32;
  stage_load(0, 0);
  cpa_wait0();
  __syncthreads();

  const int g3 = lane >> 3, r8 = lane & 7;

  for (int kb = 0; kb < nk; ++kb) {
    const int s = kb & 1;
    if (kb + 1 < nk) stage_load(s ^ 1, (kb + 1) * 32);
    const uint32_t ab = sb + (uint32_t)s * STG;
#pragma unroll
    for (int k16 = 0; k16 < 32; k16 += 16) {
      uint32_t Ahf[2][4], Alf[2][4], Bhf[8][2], Blf[8][2];
#pragma unroll
      for (int mi = 0; mi < 2; mi++) {
        uint32_t row = wm + mi * 16 + (g3 & 1) * 8 + r8;
        uint32_t col = k16 + (g3 >> 1) * 8;
        uint32_t ad = ab + row * 80 + col * 2;
        ldsm4(ad, Ahf[mi]);
        ldsm4(ad + PL, Alf[mi]);
      }
#pragma unroll
      for (int pi = 0; pi < 4; pi++) {
        uint32_t row = wn + (2 * pi + (g3 >> 1)) * 8 + r8;
        uint32_t col = k16 + (g3 & 1) * 8;
        uint32_t ad = ab + 2 * PL + row * 80 + col * 2;
        uint32_t t[4];
        ldsm4(ad, t);
        Bhf[2 * pi][0] = t[0];
        Bhf[2 * pi][1] = t[1];
        Bhf[2 * pi + 1][0] = t[2];
        Bhf[2 * pi + 1][1] = t[3];
        ldsm4(ad + PL, t);
        Blf[2 * pi][0] = t[0];
        Blf[2 * pi][1] = t[1];
        Blf[2 * pi + 1][0] = t[2];
        Blf[2 * pi + 1][1] = t[3];
      }
#pragma unroll
      for (int mi = 0; mi < 2; mi++)
#pragma unroll
        for (int ni = 0; ni < 8; ni++) {
          mma_bf16(acc[mi][ni], Ahf[mi], Bhf[ni]);
          mma_bf16(acc[mi][ni], Ahf[mi], Blf[ni]);
          mma_bf16(acc[mi][ni], Alf[mi], Bhf[ni]);
        }
    }
    cpa_wait0();
    __syncthreads();
  }

  // ---- stage accumulators to smem ----
  float* cs = reinterpret_cast<float*>(smc);
  const int g = lane >> 2, t4 = lane & 3;
#pragma unroll
  for (int mi = 0; mi < 2; mi++)
#pragma unroll
    for (int ni = 0; ni < 8; ni++) {
      int r = wm + mi * 16 + g;
      int c = wn + ni * 8 + t4 * 2;
      *reinterpret_cast<float2*>(&cs[r * 132 + c]) =
          make_float2(acc[mi][ni][0], acc[mi][ni][1]);
      *reinterpret_cast<float2*>(&cs[(r + 8) * 132 + c]) =
          make_float2(acc[mi][ni][2], acc[mi][ni][3]);
    }
  __syncthreads();

#pragma unroll 4
  for (int rr = 0; rr < 16; ++rr) {
    int row = wid * 16 + rr;
    int m = m0 + row;
#pragma unroll
    for (int i = 0; i < 2; ++i) {
      int c = 2 * lane + 64 * i;
      float d0 = cs[row * 132 + c];
      float d1 = cs[row * 132 + c + 1];
      epi_pair<EPI>(m, n0 + c, d0, d1, ep);
    }
  }
}

// ---------------- tail GEMM (fp16, 2 products) -------------------------------
// gx[128-col block] += (Ah+Al)[M,K] @ B16[N,K]^T * tscale.
// CTA tile 128x64, 8 warps warp tile 32x32, BK=32 double-buffered.
__global__ __launch_bounds__(256) void tail_gemm(
    const f16* __restrict__ Ah, const f16* __restrict__ Al,
    const f16* __restrict__ Bm, int Kc, int lda, int ldb, EpiP ep) {
  extern __shared__ char smc[];
  const uint32_t sb = smem_u32(smc);
  const int tid = threadIdx.x, lane = tid & 31, wid = tid >> 5;
  const int m0 = blockIdx.y * 128, n0 = blockIdx.x * 64;
  const int wm = (wid & 3) * 32, wn = (wid >> 2) * 32;
  const int kstart = blockIdx.z * Kc;
  constexpr uint32_t PA = 10240;
  constexpr uint32_t PB = 5120;
  constexpr uint32_t STG = 2 * PA + PB;  // 25600

  const int lr = tid >> 1;
  const int lc = (tid & 1) * 2;
  const f16* pA0 = Ah + (size_t)(m0 + lr) * lda + lc * 8;
  const f16* pA1 = Al + (size_t)(m0 + lr) * lda + lc * 8;
  const int br = (tid & 127) >> 1, bcp = (tid & 1) * 2;
  const f16* pB = Bm + (size_t)(n0 + br) * ldb + bcp * 8;
  const uint32_t bOff = 2 * PA + (uint32_t)br * 80 + bcp * 16;

  auto stage_load = [&](int s, int k0) {
    uint32_t base = sb + (uint32_t)s * STG;
    uint32_t aA = base + (uint32_t)lr * 80 + lc * 16;
    cpa16(aA, pA0 + k0);
    cpa16(aA + 16, pA0 + k0 + 8);
    cpa16(aA + PA, pA1 + k0);
    cpa16(aA + PA + 16, pA1 + k0 + 8);
    if (tid < 128) {
      uint32_t aB = base + bOff;
      cpa16(aB, pB + k0);
      cpa16(aB + 16, pB + k0 + 8);
    }
    cpa_commit();
  };

  float acc[2][4][4];
#pragma unroll
  for (int i = 0; i < 2; i++)
#pragma unroll
    for (int j = 0; j < 4; j++)
#pragma unroll
      for (int q = 0; q < 4; q++) acc[i][j][q] = 0.f;

  const int nk = Kc / 32;
  stage_load(0, kstart);
  cpa_wait0();
  __syncthreads();

  const int g3 = lane >> 3, r8 = lane & 7;

  for (int kb = 0; kb < nk; ++kb) {
    const int s = kb & 1;
    if (kb + 1 < nk) stage_load(s ^ 1, kstart + (kb + 1) * 32);
    const uint32_t ab = sb + (uint32_t)s * STG;
#pragma unroll
    for (int k16 = 0; k16 < 32; k16 += 16) {
      uint32_t Ahf[2][4], Alf[2][4], Bf[4][2];
#pragma unroll
      for (int mi = 0; mi < 2; mi++) {
        uint32_t row = wm + mi * 16 + (g3 & 1) * 8 + r8;
        uint32_t col = k16 + (g3 >> 1) * 8;
        uint32_t ad = ab + row * 80 + col * 2;
        ldsm4(ad, Ahf[mi]);
        ldsm4(ad + PA, Alf[mi]);
      }
#pragma unroll
      for (int pi = 0; pi < 2; pi++) {
        uint32_t row = wn + (2 * pi + (g3 >> 1)) * 8 + r8;
        uint32_t col = k16 + (g3 & 1) * 8;
        uint32_t ad = ab + 2 * PA + row * 80 + col * 2;
        uint32_t t[4];
        ldsm4(ad, t);
        Bf[2 * pi][0] = t[0];
        Bf[2 * pi][1] = t[1];
        Bf[2 * pi + 1][0] = t[2];
        Bf[2 * pi + 1][1] = t[3];
      }
#pragma unroll
      for (int mi = 0; mi < 2; mi++)
#pragma unroll
        for (int ni = 0; ni < 4; ni++)
          mma_f16(acc[mi][ni], Ahf[mi], Bf[ni]);
#pragma unroll
      for (int mi = 0; mi < 2; mi++)
#pragma unroll
        for (int ni = 0; ni < 4; ni++)
          mma_f16(acc[mi][ni], Alf[mi], Bf[ni]);
    }
    cpa_wait0();
    __syncthreads();
  }

  // stage + coalesced atomic epilogue
  float* cs = reinterpret_cast<float*>(smc);
  const int g = lane >> 2, t4 = lane & 3;
#pragma unroll
  for (int mi = 0; mi < 2; mi++)
#pragma unroll
    for (int ni = 0; ni < 4; ni++) {
      int r = wm + mi * 16 + g;
      int c = wn + ni * 8 + t4 * 2;
      *reinterpret_cast<float2*>(&cs[r * 68 + c]) =
          make_float2(acc[mi][ni][0], acc[mi][ni][1]);
      *reinterpret_cast<float2*>(&cs[(r + 8) * 68 + c]) =
          make_float2(acc[mi][ni][2], acc[mi][ni][3]);
    }
  __syncthreads();

#pragma unroll 4
  for (int rr = 0; rr < 16; ++rr) {
    int row = wid * 16 + rr;
    int m = m0 + row;
    int c = 2 * lane;
    float d0 = cs[row * 68 + c];
    float d1 = cs[row * 68 + c + 1];
    epi_pair<4>(m, n0 + c, d0, d1, ep);
  }
}

// ---------------- fused head GEMM (bf16, dual accumulators) ------------------
__global__ __launch_bounds__(256) void head_gemm(
    const bf16* __restrict__ Axh, const bf16* __restrict__ Axl,
    const bf16* __restrict__ Wqh, const bf16* __restrict__ Wql,
    const bf16* __restrict__ Wlh, const bf16* __restrict__ Wll,
    const float* __restrict__ blv, float* __restrict__ U,
    float* __restrict__ P, unsigned char* __restrict__ F,
    bf16* __restrict__ zh, bf16* __restrict__ zl) {
  extern __shared__ char smc[];
  const uint32_t sb = smem_u32(smc);
  const int tid = threadIdx.x, lane = tid & 31, wid = tid >> 5;
  const int m0 = blockIdx.y * 128, n0 = blockIdx.x * 64;
  const int wm = (wid & 3) * 32, wn = (wid >> 2) * 32;
  constexpr uint32_t PA = 10240;
  constexpr uint32_t PB = 5120;
  constexpr uint32_t STG = 2 * PA + 4 * PB;  // 40960

  const int lr = tid >> 1, lc = (tid & 1) * 2;
  const bf16* pA0 = Axh + (size_t)(m0 + lr) * Dd + lc * 8;
  const bf16* pA1 = Axl + (size_t)(m0 + lr) * Dd + lc * 8;
  const int br = (tid & 127) >> 1, bcp = (tid & 1) * 2;
  const int bw = tid >> 7;
  const bf16* pB0 = (bw ? Wlh : Wqh) + (size_t)(n0 + br) * Dd + bcp * 8;
  const bf16* pB1 = (bw ? Wll : Wql) + (size_t)(n0 + br) * Dd + bcp * 8;
  const uint32_t bOff = 2 * PA + (uint32_t)bw * 2 * PB + (uint32_t)br * 80 + bcp * 16;

  auto stage_load = [&](int s, int k0) {
    uint32_t base = sb + (uint32_t)s * STG;
    uint32_t aA = base + (uint32_t)lr * 80 + lc * 16;
    cpa16(aA, pA0 + k0);
    cpa16(aA + 16, pA0 + k0 + 8);
    cpa16(aA + PA, pA1 + k0);
    cpa16(aA + PA + 16, pA1 + k0 + 8);
    uint32_t aB = base + bOff;
    cpa16(aB, pB0 + k0);
    cpa16(aB + 16, pB0 + k0 + 8);
    cpa16(aB + PB, pB1 + k0);
    cpa16(aB + PB + 16, pB1 + k0 + 8);
    cpa_commit();
  };

  float accq[2][4][4], accl[2][4][4];
#pragma unroll
  for (int i = 0; i < 2; i++)
#pragma unroll
    for (int j = 0; j < 4; j++)
#pragma unroll
      for (int q = 0; q < 4; q++) accq[i][j][q] = accl[i][j][q] = 0.f;

  constexpr int nk = Dd / 32;
  stage_load(0, 0);
  cpa_wait0();
  __syncthreads();

  const int g3 = lane >> 3, r8 = lane & 7;

  for (int kb = 0; kb < nk; ++kb) {
    const int s = kb & 1;
    if (kb + 1 < nk) stage_load(s ^ 1, (kb + 1) * 32);
    const uint32_t ab = sb + (uint32_t)s * STG;
#pragma unroll
    for (int k16 = 0; k16 < 32; k16 += 16) {
      uint32_t Ahf[2][4], Alf[2][4];
      uint32_t Bqh_[4][2], Bql_[4][2], Blh_[4][2], Bll_[4][2];
#pragma unroll
      for (int mi = 0; mi < 2; mi++) {
        uint32_t row = wm + mi * 16 + (g3 & 1) * 8 + r8;
        uint32_t col = k16 + (g3 >> 1) * 8;
        uint32_t ad = ab + row * 80 + col * 2;
        ldsm4(ad, Ahf[mi]);
        ldsm4(ad + PA, Alf[mi]);
      }
#pragma unroll
      for (int pi = 0; pi < 2; pi++) {
        uint32_t row = wn + (2 * pi + (g3 >> 1)) * 8 + r8;
        uint32_t col = k16 + (g3 & 1) * 8;
        uint32_t adq = ab + 2 * PA + row * 80 + col * 2;
        uint32_t t[4];
        ldsm4(adq, t);
        Bqh_[2 * pi][0] = t[0]; Bqh_[2 * pi][1] = t[1];
        Bqh_[2 * pi + 1][0] = t[2]; Bqh_[2 * pi + 1][1] = t[3];
        ldsm4(adq + PB, t);
        Bql_[2 * pi][0] = t[0]; Bql_[2 * pi][1] = t[1];
        Bql_[2 * pi + 1][0] = t[2]; Bql_[2 * pi + 1][1] = t[3];
        ldsm4(adq + 2 * PB, t);
        Blh_[2 * pi][0] = t[0]; Blh_[2 * pi][1] = t[1];
        Blh_[2 * pi + 1][0] = t[2]; Blh_[2 * pi + 1][1] = t[3];
        ldsm4(adq + 3 * PB, t);
        Bll_[2 * pi][0] = t[0]; Bll_[2 * pi][1] = t[1];
        Bll_[2 * pi + 1][0] = t[2]; Bll_[2 * pi + 1][1] = t[3];
      }
#pragma unroll
      for (int mi = 0; mi < 2; mi++)
#pragma unroll
        for (int ni = 0; ni < 4; ni++) {
          mma_bf16(accq[mi][ni], Ahf[mi], Bqh_[ni]);
          mma_bf16(accq[mi][ni], Ahf[mi], Bql_[ni]);
          mma_bf16(accq[mi][ni], Alf[mi], Bqh_[ni]);
          mma_bf16(accl[mi][ni], Ahf[mi], Blh_[ni]);
          mma_bf16(accl[mi][ni], Ahf[mi], Bll_[ni]);
          mma_bf16(accl[mi][ni], Alf[mi], Blh_[ni]);
        }
    }
    cpa_wait0();
    __syncthreads();
  }

  float* cs = reinterpret_cast<float*>(smc);
  const int g = lane >> 2, t4 = lane & 3;
#pragma unroll
  for (int mi = 0; mi < 2; mi++)
#pragma unroll
    for (int ni = 0; ni < 4; ni++) {
      int r = wm + mi * 16 + g;
      int c = wn + ni * 8 + t4 * 2;
      *reinterpret_cast<float2*>(&cs[r * 132 + c]) =
          make_float2(accq[mi][ni][0], accq[mi][ni][1]);
      *reinterpret_cast<float2*>(&cs[(r + 8) * 132 + c]) =
          make_float2(accq[mi][ni][2], accq[mi][ni][3]);
      *reinterpret_cast<float2*>(&cs[r * 132 + 64 + c]) =
          make_float2(accl[mi][ni][0], accl[mi][ni][1]);
      *reinterpret_cast<float2*>(&cs[(r + 8) * 132 + 64 + c]) =
          make_float2(accl[mi][ni][2], accl[mi][ni][3]);
    }
  __syncthreads();

  const bool inZ = (n0 < Hh);
#pragma unroll 4
  for (int rr = 0; rr < 16; ++rr) {
    int row = wid * 16 + rr;
    int m = m0 + row;
    int c = 2 * lane;
    int n = n0 + c;
    float u0 = cs[row * 132 + c], u1 = cs[row * 132 + c + 1];
    float v0 = cs[row * 132 + 64 + c], v1 = cs[row * 132 + 64 + c + 1];
    size_t idx = (size_t)m * LH + n;
    *reinterpret_cast<float2*>(&U[idx]) = make_float2(u0, u1);
    float2 b2 = *reinterpret_cast<const float2*>(&blv[n]);
    float p0 = u0 * u0 + v0 + b2.x;
    float p1 = u1 * u1 + v1 + b2.y;
    *reinterpret_cast<float2*>(&P[idx]) = make_float2(p0, p1);
    if (inZ) {
      bool s0 = (p0 >= 0.f), s1 = (p1 >= 0.f);
      uchar2 f2;
      f2.x = s0 ? 1 : 0;
      f2.y = s1 ? 1 : 0;
      *reinterpret_cast<uchar2*>(&F[idx]) = f2;
      float z0 = s0 ? p0 : NEG_SLOPE * p0;
      float z1 = s1 ? p1 : NEG_SLOPE * p1;
      bf16 h0, l0, h1, l1;
      bsplit(z0, h0, l0);
      bsplit(z1, h1, l1);
      __nv_bfloat162 hv, lv;
      hv.x = h0; hv.y = h1;
      lv.x = l0; lv.y = l1;
      *reinterpret_cast<__nv_bfloat162*>(&zh[(size_t)m * Hh + n]) = hv;
      *reinterpret_cast<__nv_bfloat162*>(&zl[(size_t)m * Hh + n]) = lv;
    }
  }
}

// ---------------- prep / elementwise ----------------------------------------
__global__ void k_split3(const float* __restrict__ x, const float* __restrict__ Wq,
                         const float* __restrict__ Wl, bf16* __restrict__ xh,
                         bf16* __restrict__ xl, bf16* __restrict__ qh,
                         bf16* __restrict__ ql, bf16* __restrict__ lh,
                         bf16* __restrict__ ll) {
  int i = blockIdx.x * 256 + threadIdx.x;
  const int n1 = Bsz * Dd, n2 = LH * Dd;
  bf16 h, l;
  if (i < n1) {
    bsplit(x[i], h, l);
    xh[i] = h; xl[i] = l;
  } else if (i < n1 + n2) {
    int j = i - n1;
    bsplit(Wq[j], h, l);
    qh[j] = h; ql[j] = l;
  } else if (i < n1 + 2 * n2) {
    int j = i - n1 - n2;
    bsplit(Wl[j], h, l);
    lh[j] = h; ll[j] = l;
  }
}

__global__ void k_split(const float* __restrict__ in, bf16* __restrict__ h,
                        bf16* __restrict__ l, int n) {
  int i = blockIdx.x * 256 + threadIdx.x;
  if (i < n) {
    bf16 hh, ll;
    bsplit(in[i], hh, ll);
    h[i] = hh;
    l[i] = ll;
  }
}

__global__ void k_wzT(const float* __restrict__ Wz, bf16* __restrict__ h,
                      bf16* __restrict__ l) {
  int i = blockIdx.x * 256 + threadIdx.x;
  int lay = i / (Hh * Hh);
  int r = i % (Hh * Hh);
  int o = r / Hh, ii = r % Hh;
  size_t dst = (size_t)lay * Hh * Hh + (size_t)ii * Hh + o;
  bf16 hh, ll;
  bsplit(Wz[i], hh, ll);
  h[dst] = hh;
  l[dst] = ll;
}

__global__ void k_bcat16(const float* __restrict__ Wq, const float* __restrict__ Wl,
                         f16* __restrict__ o) {
  int i = blockIdx.x * 256 + threadIdx.x;
  int lay = i / (Dd * 1024);
  int r = i % (Dd * 1024);
  int d = r / 1024, k = r % 1024;
  float v = (k < Hh) ? Wq[((size_t)lay * Hh + k) * Dd + d]
                     : Wl[((size_t)lay * Hh + (k - Hh)) * Dd + d];
  o[i] = __float2half_rn(v);
}

__global__ void k_dotzero(const float* __restrict__ x, const float* __restrict__ wq,
                          float* __restrict__ S, float* __restrict__ gx) {
  int gid = blockIdx.x * 256 + threadIdx.x;
  if (gid < Bsz * Dd) gx[gid] = 0.f;
  int w = gid / 32, lane = gid % 32;
  if (w < Bsz) {
    float s = 0.f;
    for (int d = lane; d < Dd; d += 32) s += x[(size_t)w * Dd + d] * wq[d];
#pragma unroll
    for (int o = 16; o; o >>= 1) s += __shfl_xor_sync(0xFFFFFFFFu, s, o);
    if (lane == 0) S[w] = s;
  }
}

__global__ void k_bwinit(const unsigned char* __restrict__ F,
                         const float* __restrict__ U,
                         const float* __restrict__ wz_out,
                         bf16* __restrict__ zh, bf16* __restrict__ zl,
                         f16* __restrict__ ach, f16* __restrict__ acl) {
  int i = blockIdx.x * 256 + threadIdx.x;
  int m = i / Hh, h = i % Hh;
  size_t idx = (size_t)m * LH + (size_t)(Ll - 1) * Hh + h;
  float f = F[idx] ? 1.f : NEG_SLOPE;
  float ga = wz_out[h] * f;
  bf16 gh, gl;
  bsplit(ga, gh, gl);
  zh[i] = gh;
  zl[i] = gl;
  float g1 = 2.f * ga * U[idx];  // scale 16^0 at l=9
  f16 h1, l1;
  size_t ai = (size_t)m * 1024 + h;
  hsplit(g1, h1, l1);
  ach[ai] = h1;
  acl[ai] = l1;
  hsplit(ga, h1, l1);
  ach[ai + Hh] = h1;
  acl[ai + Hh] = l1;
}

__global__ void k_final(const float* __restrict__ gx, const float* __restrict__ S,
                        const float* __restrict__ wq, const float* __restrict__ wl,
                        const float* __restrict__ x, float* __restrict__ out) {
  int i = blockIdx.x * 256 + threadIdx.x;
  int m = i >> 7, n = i & 127;
  out[i] = 0.5f * (gx[i] + 2.f * S[m] * wq[n] + wl[n]) + 0.5f * x[i];
}

// ---------------- host driver ------------------------------------------------
constexpr uint32_t SMEM_SZ = 81920;
constexpr uint32_t SMEM_TAIL = 51200;

extern "C" void kernel_launch(void* const* d_in, const int* in_sizes, int n_in,
                              void* d_out, int out_size) {
  const float* x = (const float*)d_in[0];
  const float* Wq = (const float*)d_in[1];
  const float* Wl = (const float*)d_in[2];
  const float* bl = (const float*)d_in[3];
  const float* Wz = (const float*)d_in[4];
  const float* wz_out = (const float*)d_in[5];
  const float* wq_out = (const float*)d_in[6];
  const float* wl_out = (const float*)d_in[7];
  float* out = (float*)d_out;

  bf16 *xh, *xl, *Wqh, *Wql, *Wlh, *Wll, *Wzh, *Wzl, *WzTh, *WzTl;
  bf16 *zAh, *zAl, *zBh, *zBl;
  f16 *Bc16, *Ach[2], *Acl[2];
  float *U, *P, *gx, *S;
  unsigned char* F;
  cudaGetSymbolAddress((void**)&xh, g_xh);
  cudaGetSymbolAddress((void**)&xl, g_xl);
  cudaGetSymbolAddress((void**)&Wqh, g_Wqh);
  cudaGetSymbolAddress((void**)&Wql, g_Wql);
  cudaGetSymbolAddress((void**)&Wlh, g_Wlh);
  cudaGetSymbolAddress((void**)&Wll, g_Wll);
  cudaGetSymbolAddress((void**)&Wzh, g_Wzh);
  cudaGetSymbolAddress((void**)&Wzl, g_Wzl);
  cudaGetSymbolAddress((void**)&WzTh, g_WzTh);
  cudaGetSymbolAddress((void**)&WzTl, g_WzTl);
  cudaGetSymbolAddress((void**)&Bc16, g_Bc16);
  cudaGetSymbolAddress((void**)&U, g_U);
  cudaGetSymbolAddress((void**)&P, g_P);
  cudaGetSymbolAddress((void**)&F, g_F);
  cudaGetSymbolAddress((void**)&zAh, g_zAh);
  cudaGetSymbolAddress((void**)&zAl, g_zAl);
  cudaGetSymbolAddress((void**)&zBh, g_zBh);
  cudaGetSymbolAddress((void**)&zBl, g_zBl);
  cudaGetSymbolAddress((void**)&Ach[0], g_Ach0);
  cudaGetSymbolAddress((void**)&Acl[0], g_Acl0);
  cudaGetSymbolAddress((void**)&Ach[1], g_Ach1);
  cudaGetSymbolAddress((void**)&Acl[1], g_Acl1);
  cudaGetSymbolAddress((void**)&gx, g_gx);
  cudaGetSymbolAddress((void**)&S, g_S);

  static bool s_init = false;
  static cudaStream_t st1, st2;
  static cudaEvent_t evStart, evWz, evWzT, evBw[10], evTail[10];
  if (!s_init) {
    cudaStreamCreateWithFlags(&st1, cudaStreamNonBlocking);
    cudaStreamCreateWithFlags(&st2, cudaStreamNonBlocking);
    cudaEventCreateWithFlags(&evStart, cudaEventDisableTiming);
    cudaEventCreateWithFlags(&evWz, cudaEventDisableTiming);
    cudaEventCreateWithFlags(&evWzT, cudaEventDisableTiming);
    for (int i = 0; i < 10; i++) {
      cudaEventCreateWithFlags(&evBw[i], cudaEventDisableTiming);
      cudaEventCreateWithFlags(&evTail[i], cudaEventDisableTiming);
    }
    cudaFuncSetAttribute(mma_gemm<2>, cudaFuncAttributeMaxDynamicSharedMemorySize, SMEM_SZ);
    cudaFuncSetAttribute(mma_gemm<3>, cudaFuncAttributeMaxDynamicSharedMemorySize, SMEM_SZ);
    cudaFuncSetAttribute(tail_gemm, cudaFuncAttributeMaxDynamicSharedMemorySize, SMEM_TAIL);
    cudaFuncSetAttribute(head_gemm, cudaFuncAttributeMaxDynamicSharedMemorySize, SMEM_SZ);
    s_init = true;
  }

  cudaEventRecord(evStart, 0);
  cudaStreamWaitEvent(st1, evStart, 0);
  cudaStreamWaitEvent(st2, evStart, 0);

  {
    int tot = Bsz * Dd + 2 * LH * Dd;
    k_split3<<<(tot + 255) / 256, 256>>>(x, Wq, Wl, xh, xl, Wqh, Wql, Wlh, Wll);
  }
  k_split<<<((Ll - 1) * Hh * Hh + 255) / 256, 256, 0, st1>>>(
      Wz, Wzh, Wzl, (Ll - 1) * Hh * Hh);
  cudaEventRecord(evWz, st1);

  head_gemm<<<dim3(LH / 64, Bsz / 128), 256, SMEM_SZ>>>(
      xh, xl, Wqh, Wql, Wlh, Wll, bl, U, P, F, zAh, zAl);

  bf16* zh2[2] = {zAh, zBh};
  bf16* zl2[2] = {zAl, zBl};
  cudaStreamWaitEvent(0, evWz, 0);
  for (int l = 1; l < Ll; ++l) {
    EpiP ep = {};
    ep.Pc = P;
    ep.F = F;
    ep.coff = l * Hh;
    ep.zh = zh2[l & 1];
    ep.zl = zl2[l & 1];
    mma_gemm<2><<<dim3(Hh / 128, Bsz / 128, 1), 256, SMEM_SZ>>>(
        zh2[(l - 1) & 1], zl2[(l - 1) & 1], Wzh + (size_t)(l - 1) * Hh * Hh,
        Wzl + (size_t)(l - 1) * Hh * Hh, Hh, Hh, Hh, ep);
  }

  k_wzT<<<((Ll - 1) * Hh * Hh + 255) / 256, 256, 0, st1>>>(Wz, WzTh, WzTl);
  cudaEventRecord(evWzT, st1);
  k_bcat16<<<(Ll * Dd * 1024 + 255) / 256, 256, 0, st2>>>(Wq, Wl, Bc16);
  k_dotzero<<<(Bsz * Dd + 255) / 256, 256, 0, st2>>>(x, wq_out, S, gx);

  k_bwinit<<<(Bsz * Hh + 255) / 256, 256>>>(F, U, wz_out, zh2[0], zl2[0],
                                            Ach[1], Acl[1]);
  cudaEventRecord(evBw[9], 0);

  cudaStreamWaitEvent(st2, evBw[9], 0);
  {
    EpiP ep = {};
    ep.gx = gx;
    ep.tscale = 1.f;
    tail_gemm<<<dim3(Dd / 64, Bsz / 128, 2), 256, SMEM_TAIL, st2>>>(
        Ach[1], Acl[1], Bc16 + (size_t)(Ll - 1) * Dd * 1024, 512, 1024, 1024,
        ep);
    cudaEventRecord(evTail[9], st2);
  }

  cudaStreamWaitEvent(0, evWzT, 0);
  int cur = 0;
  for (int l = Ll - 2; l >= 0; --l) {
    if (l + 2 <= 9) cudaStreamWaitEvent(0, evTail[l + 2], 0);
    {
      EpiP ep = {};
      ep.F = F;
      ep.U = U;
      ep.coff = l * Hh;
      ep.zh = zh2[cur ^ 1];
      ep.zl = zl2[cur ^ 1];
      ep.ach = Ach[l & 1];
      ep.acl = Acl[l & 1];
      float as = 1.f;
      for (int t = 0; t < 9 - l; ++t) as *= 0.0625f;
      ep.ascale = as;  // 16^-(9-l)
      mma_gemm<3><<<dim3(Hh / 128, Bsz / 128, 1), 256, SMEM_SZ>>>(
          zh2[cur], zl2[cur], WzTh + (size_t)l * Hh * Hh,
          WzTl + (size_t)l * Hh * Hh, Hh, Hh, Hh, ep);
      cur ^= 1;
    }
    cudaEventRecord(evBw[l], 0);
    cudaStreamWaitEvent(st2, evBw[l], 0);
    {
      EpiP ep = {};
      ep.gx = gx;
      float ts = 1.f;
      for (int t = 0; t < 9 - l; ++t) ts *= 16.f;
      ep.tscale = ts;  // 16^(9-l)
      tail_gemm<<<dim3(Dd / 64, Bsz / 128, 2), 256, SMEM_TAIL, st2>>>(
          Ach[l & 1], Acl[l & 1], Bc16 + (size_t)l * Dd * 1024, 512, 1024,
          1024, ep);
      cudaEventRecord(evTail[l], st2);
    }
  }

  cudaStreamWaitEvent(0, evTail[0], 0);
  k_final<<<(Bsz * Dd + 255) / 256, 256>>>(gx, S, wq_out, wl_out, x, out);
}

// round 11
// speedup vs baseline: 1.2816x; 1.2816x over previous
#include <cuda_runtime.h>
#include <cuda_bf16.h>
#include <cuda_fp16.h>
#include <cstdint>

// ===========================================================================
// ICNN forward + input-gradient.
// Chain + head: bf16 hi/lo pairs, 3 MMA products (rel_err 2.8e-4 class).
// Tails: fp16 pair x fp16 single weights, 2 products (not chain-amplified).
// Round 11: __launch_bounds__(256,2) pins chain/head kernels at <=128 regs
// => 2 CTAs/SM (R10's merged epilogue pushed regs to 142 => 1 CTA/SM,
// tensor pipe starved at 23.9%, layer 88us vs 65.6us).
// ===========================================================================

typedef __nv_bfloat16 bf16;
typedef __half f16;

#define NEG_SLOPE 0.2f
constexpr int Bsz = 8192;
constexpr int Dd  = 128;
constexpr int Hh  = 512;
constexpr int Ll  = 10;
constexpr int LH  = Ll * Hh;  // 5120

// ---------------- static device scratch ------------------------------------
__device__ bf16 g_xh[(size_t)Bsz * Dd], g_xl[(size_t)Bsz * Dd];
__device__ bf16 g_Wqh[(size_t)LH * Dd], g_Wql[(size_t)LH * Dd];
__device__ bf16 g_Wlh[(size_t)LH * Dd], g_Wll[(size_t)LH * Dd];
__device__ bf16 g_Wzh[(size_t)(Ll - 1) * Hh * Hh], g_Wzl[(size_t)(Ll - 1) * Hh * Hh];
__device__ bf16 g_WzTh[(size_t)(Ll - 1) * Hh * Hh], g_WzTl[(size_t)(Ll - 1) * Hh * Hh];
__device__ f16  g_Bc16[(size_t)Ll * Dd * 1024];
__device__ float g_U[(size_t)Bsz * LH];
__device__ float g_P[(size_t)Bsz * LH];
__device__ unsigned char g_F[(size_t)Bsz * LH];
__device__ bf16 g_zAh[(size_t)Bsz * Hh], g_zAl[(size_t)Bsz * Hh];
__device__ bf16 g_zBh[(size_t)Bsz * Hh], g_zBl[(size_t)Bsz * Hh];
__device__ f16 g_Ach0[(size_t)Bsz * 1024], g_Acl0[(size_t)Bsz * 1024];
__device__ f16 g_Ach1[(size_t)Bsz * 1024], g_Acl1[(size_t)Bsz * 1024];
__device__ float g_gx[(size_t)Bsz * Dd];
__device__ float g_S[Bsz];

// ---------------- helpers ---------------------------------------------------
__device__ __forceinline__ uint32_t smem_u32(const void* p) {
  uint32_t a;
  asm("{ .reg .u64 t; cvta.to.shared.u64 t, %1; cvt.u32.u64 %0, t; }"
      : "=r"(a) : "l"(p));
  return a;
}
__device__ __forceinline__ void cpa16(uint32_t s, const void* g) {
  asm volatile("cp.async.cg.shared.global [%0], [%1], 16;" ::"r"(s), "l"(g));
}
__device__ __forceinline__ void cpa_commit() {
  asm volatile("cp.async.commit_group;" ::: "memory");
}
__device__ __forceinline__ void cpa_wait0() {
  asm volatile("cp.async.wait_group 0;" ::: "memory");
}
__device__ __forceinline__ void ldsm4(uint32_t addr, uint32_t* r) {
  asm volatile("ldmatrix.sync.aligned.m8n8.x4.shared.b16 {%0,%1,%2,%3}, [%4];"
               : "=r"(r[0]), "=r"(r[1]), "=r"(r[2]), "=r"(r[3]) : "r"(addr));
}
__device__ __forceinline__ void mma_bf16(float* c, const uint32_t* a,
                                         const uint32_t* b) {
  asm volatile(
      "mma.sync.aligned.m16n8k16.row.col.f32.bf16.bf16.f32 "
      "{%0,%1,%2,%3}, {%4,%5,%6,%7}, {%8,%9}, {%0,%1,%2,%3};"
      : "+f"(c[0]), "+f"(c[1]), "+f"(c[2]), "+f"(c[3])
      : "r"(a[0]), "r"(a[1]), "r"(a[2]), "r"(a[3]), "r"(b[0]), "r"(b[1]));
}
__device__ __forceinline__ void mma_f16(float* c, const uint32_t* a,
                                        const uint32_t* b) {
  asm volatile(
      "mma.sync.aligned.m16n8k16.row.col.f32.f16.f16.f32 "
      "{%0,%1,%2,%3}, {%4,%5,%6,%7}, {%8,%9}, {%0,%1,%2,%3};"
      : "+f"(c[0]), "+f"(c[1]), "+f"(c[2]), "+f"(c[3])
      : "r"(a[0]), "r"(a[1]), "r"(a[2]), "r"(a[3]), "r"(b[0]), "r"(b[1]));
}
__device__ __forceinline__ void bsplit(float v, bf16& h, bf16& l) {
  h = __float2bfloat16(v);
  l = __float2bfloat16(v - __bfloat162float(h));
}
__device__ __forceinline__ void hsplit(float v, f16& h, f16& l) {
  h = __float2half_rn(v);
  l = __float2half_rn(v - __half2float(h));
}

// ---------------- epilogue params -------------------------------------------
struct EpiP {
  const float* U;
  const float* Pc;
  unsigned char* F;
  bf16* zh;
  bf16* zl;
  f16* ach;
  f16* acl;
  float* gx;
  int coff;
  float ascale;  // EPI3: Acat write scale = 16^-(9-l)
  float tscale;  // EPI4: gx accumulate scale = 16^(9-l)
};

// EPI: 2=fwd layer; 3=bwd layer; 4=gx accum (tail)
template <int EPI>
__device__ __forceinline__ void epi_pair(int m, int n, float d0, float d1,
                                         const EpiP& ep) {
  if (EPI == 2) {
    size_t idx = (size_t)m * LH + ep.coff + n;
    float2 pc = *reinterpret_cast<const float2*>(&ep.Pc[idx]);
    float a0 = d0 + pc.x, a1 = d1 + pc.y;
    bool p0 = (a0 >= 0.f), p1 = (a1 >= 0.f);
    uchar2 f2;
    f2.x = p0 ? 1 : 0;
    f2.y = p1 ? 1 : 0;
    *reinterpret_cast<uchar2*>(&ep.F[idx]) = f2;
    float z0 = p0 ? a0 : NEG_SLOPE * a0;
    float z1 = p1 ? a1 : NEG_SLOPE * a1;
    bf16 h0, l0, h1, l1;
    bsplit(z0, h0, l0);
    bsplit(z1, h1, l1);
    __nv_bfloat162 hv, lv;
    hv.x = h0; hv.y = h1;
    lv.x = l0; lv.y = l1;
    *reinterpret_cast<__nv_bfloat162*>(&ep.zh[(size_t)m * Hh + n]) = hv;
    *reinterpret_cast<__nv_bfloat162*>(&ep.zl[(size_t)m * Hh + n]) = lv;
  } else if (EPI == 3) {
    size_t idx = (size_t)m * LH + ep.coff + n;
    uchar2 f2 = *reinterpret_cast<const uchar2*>(&ep.F[idx]);
    float f0 = f2.x ? 1.f : NEG_SLOPE;
    float f1 = f2.y ? 1.f : NEG_SLOPE;
    float ga0 = d0 * f0, ga1 = d1 * f1;
    bf16 gh0, gl0, gh1, gl1;
    bsplit(ga0, gh0, gl0);
    bsplit(ga1, gh1, gl1);
    __nv_bfloat162 bv;
    bv.x = gh0; bv.y = gh1;
    *reinterpret_cast<__nv_bfloat162*>(&ep.zh[(size_t)m * Hh + n]) = bv;
    bv.x = gl0; bv.y = gl1;
    *reinterpret_cast<__nv_bfloat162*>(&ep.zl[(size_t)m * Hh + n]) = bv;
    float2 uu = *reinterpret_cast<const float2*>(&ep.U[idx]);
    float as0 = ga0 * ep.ascale, as1 = ga1 * ep.ascale;
    float g10 = 2.f * as0 * uu.x, g11 = 2.f * as1 * uu.y;
    f16 th0, tl0, th1, tl1;
    size_t ai = (size_t)m * 1024 + n;
    __half2 hv;
    hsplit(g10, th0, tl0);
    hsplit(g11, th1, tl1);
    hv.x = th0; hv.y = th1;
    *reinterpret_cast<__half2*>(&ep.ach[ai]) = hv;
    hv.x = tl0; hv.y = tl1;
    *reinterpret_cast<__half2*>(&ep.acl[ai]) = hv;
    hsplit(as0, th0, tl0);
    hsplit(as1, th1, tl1);
    hv.x = th0; hv.y = th1;
    *reinterpret_cast<__half2*>(&ep.ach[ai + Hh]) = hv;
    hv.x = tl0; hv.y = tl1;
    *reinterpret_cast<__half2*>(&ep.acl[ai + Hh]) = hv;
  } else {  // EPI == 4
    atomicAdd(&ep.gx[(size_t)m * Dd + n], d0 * ep.tscale);
    atomicAdd(&ep.gx[(size_t)m * Dd + n + 1], d1 * ep.tscale);
  }
}

// ---------------- chain GEMM (bf16, 3 products) ------------------------------
// C[128,128]/CTA = (Ah+Al)[M,K] @ (Bh+Bl)[N,K]^T.
// 8 warps, warp tile 32x64. BK=32 double-buffered cp.async. 2 CTAs/SM pinned.
template <int EPI>
__global__ __launch_bounds__(256, 2) void mma_gemm(
    const bf16* __restrict__ Ah, const bf16* __restrict__ Al,
    const bf16* __restrict__ Bh, const bf16* __restrict__ Bl, int Kc, int lda,
    int ldb, EpiP ep) {
  extern __shared__ char smc[];
  const uint32_t sb = smem_u32(smc);
  const int tid = threadIdx.x, lane = tid & 31, wid = tid >> 5;
  const int m0 = blockIdx.y * 128, n0 = blockIdx.x * 128;
  const int wm = (wid & 3) * 32, wn = (wid >> 2) * 64;
  constexpr uint32_t PL = 10240;
  constexpr uint32_t STG = 40960;

  const int lr = tid >> 1;
  const int lc = (tid & 1) * 2;

  const bf16* pA0 = Ah + (size_t)(m0 + lr) * lda + lc * 8;
  const bf16* pA1 = Al + (size_t)(m0 + lr) * lda + lc * 8;
  const bf16* pB0 = Bh + (size_t)(n0 + lr) * ldb + lc * 8;
  const bf16* pB1 = Bl + (size_t)(n0 + lr) * ldb + lc * 8;

  auto stage_load = [&](int s, int k0) {
    uint32_t base = sb + (uint32_t)s * STG + (uint32_t)lr * 80 + lc * 16;
    cpa16(base, pA0 + k0);
    cpa16(base + 16, pA0 + k0 + 8);
    cpa16(base + PL, pA1 + k0);
    cpa16(base + PL + 16, pA1 + k0 + 8);
    cpa16(base + 2 * PL, pB0 + k0);
    cpa16(base + 2 * PL + 16, pB0 + k0 + 8);
    cpa16(base + 3 * PL, pB1 + k0);
    cpa16(base + 3 * PL + 16, pB1 + k0 + 8);
    cpa_commit();
  };

  float acc[2][8][4];
#pragma unroll
  for (int i = 0; i < 2; i++)
#pragma unroll
    for (int j = 0; j < 8; j++)
#pragma unroll
      for (int q = 0; q < 4; q++) acc[i][j][q] = 0.f;

  const int nk = Kc / 32;
  stage_load(0, 0);
  cpa_wait0();
  __syncthreads();

  const int g3 = lane >> 3, r8 = lane & 7;

  for (int kb = 0; kb < nk; ++kb) {
    const int s = kb & 1;
    if (kb + 1 < nk) stage_load(s ^ 1, (kb + 1) * 32);
    const uint32_t ab = sb + (uint32_t)s * STG;
#pragma unroll
    for (int k16 = 0; k16 < 32; k16 += 16) {
      uint32_t Ahf[2][4], Alf[2][4], Bhf[8][2], Blf[8][2];
#pragma unroll
      for (int mi = 0; mi < 2; mi++) {
        uint32_t row = wm + mi * 16 + (g3 & 1) * 8 + r8;
        uint32_t col = k16 + (g3 >> 1) * 8;
        uint32_t ad = ab + row * 80 + col * 2;
        ldsm4(ad, Ahf[mi]);
        ldsm4(ad + PL, Alf[mi]);
      }
#pragma unroll
      for (int pi = 0; pi < 4; pi++) {
        uint32_t row = wn + (2 * pi + (g3 >> 1)) * 8 + r8;
        uint32_t col = k16 + (g3 & 1) * 8;
        uint32_t ad = ab + 2 * PL + row * 80 + col * 2;
        uint32_t t[4];
        ldsm4(ad, t);
        Bhf[2 * pi][0] = t[0];
        Bhf[2 * pi][1] = t[1];
        Bhf[2 * pi + 1][0] = t[2];
        Bhf[2 * pi + 1][1] = t[3];
        ldsm4(ad + PL, t);
        Blf[2 * pi][0] = t[0];
        Blf[2 * pi][1] = t[1];
        Blf[2 * pi + 1][0] = t[2];
        Blf[2 * pi + 1][1] = t[3];
      }
#pragma unroll
      for (int mi = 0; mi < 2; mi++)
#pragma unroll
        for (int ni = 0; ni < 8; ni++) {
          mma_bf16(acc[mi][ni], Ahf[mi], Bhf[ni]);
          mma_bf16(acc[mi][ni], Ahf[mi], Blf[ni]);
          mma_bf16(acc[mi][ni], Alf[mi], Bhf[ni]);
        }
    }
    cpa_wait0();
    __syncthreads();
  }

  // ---- stage accumulators to smem ----
  float* cs = reinterpret_cast<float*>(smc);
  const int g = lane >> 2, t4 = lane & 3;
#pragma unroll
  for (int mi = 0; mi < 2; mi++)
#pragma unroll
    for (int ni = 0; ni < 8; ni++) {
      int r = wm + mi * 16 + g;
      int c = wn + ni * 8 + t4 * 2;
      *reinterpret_cast<float2*>(&cs[r * 132 + c]) =
          make_float2(acc[mi][ni][0], acc[mi][ni][1]);
      *reinterpret_cast<float2*>(&cs[(r + 8) * 132 + c]) =
          make_float2(acc[mi][ni][2], acc[mi][ni][3]);
    }
  __syncthreads();

#pragma unroll 4
  for (int rr = 0; rr < 16; ++rr) {
    int row = wid * 16 + rr;
    int m = m0 + row;
#pragma unroll
    for (int i = 0; i < 2; ++i) {
      int c = 2 * lane + 64 * i;
      float d0 = cs[row * 132 + c];
      float d1 = cs[row * 132 + c + 1];
      epi_pair<EPI>(m, n0 + c, d0, d1, ep);
    }
  }
}

// ---------------- tail GEMM (fp16, 2 products) -------------------------------
__global__ __launch_bounds__(256, 2) void tail_gemm(
    const f16* __restrict__ Ah, const f16* __restrict__ Al,
    const f16* __restrict__ Bm, int Kc, int lda, int ldb, EpiP ep) {
  extern __shared__ char smc[];
  const uint32_t sb = smem_u32(smc);
  const int tid = threadIdx.x, lane = tid & 31, wid = tid >> 5;
  const int m0 = blockIdx.y * 128, n0 = blockIdx.x * 64;
  const int wm = (wid & 3) * 32, wn = (wid >> 2) * 32;
  const int kstart = blockIdx.z * Kc;
  constexpr uint32_t PA = 10240;
  constexpr uint32_t PB = 5120;
  constexpr uint32_t STG = 2 * PA + PB;  // 25600

  const int lr = tid >> 1;
  const int lc = (tid & 1) * 2;
  const f16* pA0 = Ah + (size_t)(m0 + lr) * lda + lc * 8;
  const f16* pA1 = Al + (size_t)(m0 + lr) * lda + lc * 8;
  const int br = (tid & 127) >> 1, bcp = (tid & 1) * 2;
  const f16* pB = Bm + (size_t)(n0 + br) * ldb + bcp * 8;
  const uint32_t bOff = 2 * PA + (uint32_t)br * 80 + bcp * 16;

  auto stage_load = [&](int s, int k0) {
    uint32_t base = sb + (uint32_t)s * STG;
    uint32_t aA = base + (uint32_t)lr * 80 + lc * 16;
    cpa16(aA, pA0 + k0);
    cpa16(aA + 16, pA0 + k0 + 8);
    cpa16(aA + PA, pA1 + k0);
    cpa16(aA + PA + 16, pA1 + k0 + 8);
    if (tid < 128) {
      uint32_t aB = base + bOff;
      cpa16(aB, pB + k0);
      cpa16(aB + 16, pB + k0 + 8);
    }
    cpa_commit();
  };

  float acc[2][4][4];
#pragma unroll
  for (int i = 0; i < 2; i++)
#pragma unroll
    for (int j = 0; j < 4; j++)
#pragma unroll
      for (int q = 0; q < 4; q++) acc[i][j][q] = 0.f;

  const int nk = Kc / 32;
  stage_load(0, kstart);
  cpa_wait0();
  __syncthreads();

  const int g3 = lane >> 3, r8 = lane & 7;

  for (int kb = 0; kb < nk; ++kb) {
    const int s = kb & 1;
    if (kb + 1 < nk) stage_load(s ^ 1, kstart + (kb + 1) * 32);
    const uint32_t ab = sb + (uint32_t)s * STG;
#pragma unroll
    for (int k16 = 0; k16 < 32; k16 += 16) {
      uint32_t Ahf[2][4], Alf[2][4], Bf[4][2];
#pragma unroll
      for (int mi = 0; mi < 2; mi++) {
        uint32_t row = wm + mi * 16 + (g3 & 1) * 8 + r8;
        uint32_t col = k16 + (g3 >> 1) * 8;
        uint32_t ad = ab + row * 80 + col * 2;
        ldsm4(ad, Ahf[mi]);
        ldsm4(ad + PA, Alf[mi]);
      }
#pragma unroll
      for (int pi = 0; pi < 2; pi++) {
        uint32_t row = wn + (2 * pi + (g3 >> 1)) * 8 + r8;
        uint32_t col = k16 + (g3 & 1) * 8;
        uint32_t ad = ab + 2 * PA + row * 80 + col * 2;
        uint32_t t[4];
        ldsm4(ad, t);
        Bf[2 * pi][0] = t[0];
        Bf[2 * pi][1] = t[1];
        Bf[2 * pi + 1][0] = t[2];
        Bf[2 * pi + 1][1] = t[3];
      }
#pragma unroll
      for (int mi = 0; mi < 2; mi++)
#pragma unroll
        for (int ni = 0; ni < 4; ni++)
          mma_f16(acc[mi][ni], Ahf[mi], Bf[ni]);
#pragma unroll
      for (int mi = 0; mi < 2; mi++)
#pragma unroll
        for (int ni = 0; ni < 4; ni++)
          mma_f16(acc[mi][ni], Alf[mi], Bf[ni]);
    }
    cpa_wait0();
    __syncthreads();
  }

  float* cs = reinterpret_cast<float*>(smc);
  const int g = lane >> 2, t4 = lane & 3;
#pragma unroll
  for (int mi = 0; mi < 2; mi++)
#pragma unroll
    for (int ni = 0; ni < 4; ni++) {
      int r = wm + mi * 16 + g;
      int c = wn + ni * 8 + t4 * 2;
      *reinterpret_cast<float2*>(&cs[r * 68 + c]) =
          make_float2(acc[mi][ni][0], acc[mi][ni][1]);
      *reinterpret_cast<float2*>(&cs[(r + 8) * 68 + c]) =
          make_float2(acc[mi][ni][2], acc[mi][ni][3]);
    }
  __syncthreads();

#pragma unroll 4
  for (int rr = 0; rr < 16; ++rr) {
    int row = wid * 16 + rr;
    int m = m0 + row;
    int c = 2 * lane;
    float d0 = cs[row * 68 + c];
    float d1 = cs[row * 68 + c + 1];
    epi_pair<4>(m, n0 + c, d0, d1, ep);
  }
}

// ---------------- fused head GEMM (bf16, dual accumulators) ------------------
__global__ __launch_bounds__(256, 2) void head_gemm(
    const bf16* __restrict__ Axh, const bf16* __restrict__ Axl,
    const bf16* __restrict__ Wqh, const bf16* __restrict__ Wql,
    const bf16* __restrict__ Wlh, const bf16* __restrict__ Wll,
    const float* __restrict__ blv, float* __restrict__ U,
    float* __restrict__ P, unsigned char* __restrict__ F,
    bf16* __restrict__ zh, bf16* __restrict__ zl) {
  extern __shared__ char smc[];
  const uint32_t sb = smem_u32(smc);
  const int tid = threadIdx.x, lane = tid & 31, wid = tid >> 5;
  const int m0 = blockIdx.y * 128, n0 = blockIdx.x * 64;
  const int wm = (wid & 3) * 32, wn = (wid >> 2) * 32;
  constexpr uint32_t PA = 10240;
  constexpr uint32_t PB = 5120;
  constexpr uint32_t STG = 2 * PA + 4 * PB;  // 40960

  const int lr = tid >> 1, lc = (tid & 1) * 2;
  const bf16* pA0 = Axh + (size_t)(m0 + lr) * Dd + lc * 8;
  const bf16* pA1 = Axl + (size_t)(m0 + lr) * Dd + lc * 8;
  const int br = (tid & 127) >> 1, bcp = (tid & 1) * 2;
  const int bw = tid >> 7;
  const bf16* pB0 = (bw ? Wlh : Wqh) + (size_t)(n0 + br) * Dd + bcp * 8;
  const bf16* pB1 = (bw ? Wll : Wql) + (size_t)(n0 + br) * Dd + bcp * 8;
  const uint32_t bOff = 2 * PA + (uint32_t)bw * 2 * PB + (uint32_t)br * 80 + bcp * 16;

  auto stage_load = [&](int s, int k0) {
    uint32_t base = sb + (uint32_t)s * STG;
    uint32_t aA = base + (uint32_t)lr * 80 + lc * 16;
    cpa16(aA, pA0 + k0);
    cpa16(aA + 16, pA0 + k0 + 8);
    cpa16(aA + PA, pA1 + k0);
    cpa16(aA + PA + 16, pA1 + k0 + 8);
    uint32_t aB = base + bOff;
    cpa16(aB, pB0 + k0);
    cpa16(aB + 16, pB0 + k0 + 8);
    cpa16(aB + PB, pB1 + k0);
    cpa16(aB + PB + 16, pB1 + k0 + 8);
    cpa_commit();
  };

  float accq[2][4][4], accl[2][4][4];
#pragma unroll
  for (int i = 0; i < 2; i++)
#pragma unroll
    for (int j = 0; j < 4; j++)
#pragma unroll
      for (int q = 0; q < 4; q++) accq[i][j][q] = accl[i][j][q] = 0.f;

  constexpr int nk = Dd / 32;
  stage_load(0, 0);
  cpa_wait0();
  __syncthreads();

  const int g3 = lane >> 3, r8 = lane & 7;

  for (int kb = 0; kb < nk; ++kb) {
    const int s = kb & 1;
    if (kb + 1 < nk) stage_load(s ^ 1, (kb + 1) * 32);
    const uint32_t ab = sb + (uint32_t)s * STG;
#pragma unroll
    for (int k16 = 0; k16 < 32; k16 += 16) {
      uint32_t Ahf[2][4], Alf[2][4];
      uint32_t Bqh_[4][2], Bql_[4][2], Blh_[4][2], Bll_[4][2];
#pragma unroll
      for (int mi = 0; mi < 2; mi++) {
        uint32_t row = wm + mi * 16 + (g3 & 1) * 8 + r8;
        uint32_t col = k16 + (g3 >> 1) * 8;
        uint32_t ad = ab + row * 80 + col * 2;
        ldsm4(ad, Ahf[mi]);
        ldsm4(ad + PA, Alf[mi]);
      }
#pragma unroll
      for (int pi = 0; pi < 2; pi++) {
        uint32_t row = wn + (2 * pi + (g3 >> 1)) * 8 + r8;
        uint32_t col = k16 + (g3 & 1) * 8;
        uint32_t adq = ab + 2 * PA + row * 80 + col * 2;
        uint32_t t[4];
        ldsm4(adq, t);
        Bqh_[2 * pi][0] = t[0]; Bqh_[2 * pi][1] = t[1];
        Bqh_[2 * pi + 1][0] = t[2]; Bqh_[2 * pi + 1][1] = t[3];
        ldsm4(adq + PB, t);
        Bql_[2 * pi][0] = t[0]; Bql_[2 * pi][1] = t[1];
        Bql_[2 * pi + 1][0] = t[2]; Bql_[2 * pi + 1][1] = t[3];
        ldsm4(adq + 2 * PB, t);
        Blh_[2 * pi][0] = t[0]; Blh_[2 * pi][1] = t[1];
        Blh_[2 * pi + 1][0] = t[2]; Blh_[2 * pi + 1][1] = t[3];
        ldsm4(adq + 3 * PB, t);
        Bll_[2 * pi][0] = t[0]; Bll_[2 * pi][1] = t[1];
        Bll_[2 * pi + 1][0] = t[2]; Bll_[2 * pi + 1][1] = t[3];
      }
#pragma unroll
      for (int mi = 0; mi < 2; mi++)
#pragma unroll
        for (int ni = 0; ni < 4; ni++) {
          mma_bf16(accq[mi][ni], Ahf[mi], Bqh_[ni]);
          mma_bf16(accq[mi][ni], Ahf[mi], Bql_[ni]);
          mma_bf16(accq[mi][ni], Alf[mi], Bqh_[ni]);
          mma_bf16(accl[mi][ni], Ahf[mi], Blh_[ni]);
          mma_bf16(accl[mi][ni], Ahf[mi], Bll_[ni]);
          mma_bf16(accl[mi][ni], Alf[mi], Blh_[ni]);
        }
    }
    cpa_wait0();
    __syncthreads();
  }

  float* cs = reinterpret_cast<float*>(smc);
  const int g = lane >> 2, t4 = lane & 3;
#pragma unroll
  for (int mi = 0; mi < 2; mi++)
#pragma unroll
    for (int ni = 0; ni < 4; ni++) {
      int r = wm + mi * 16 + g;
      int c = wn + ni * 8 + t4 * 2;
      *reinterpret_cast<float2*>(&cs[r * 132 + c]) =
          make_float2(accq[mi][ni][0], accq[mi][ni][1]);
      *reinterpret_cast<float2*>(&cs[(r + 8) * 132 + c]) =
          make_float2(accq[mi][ni][2], accq[mi][ni][3]);
      *reinterpret_cast<float2*>(&cs[r * 132 + 64 + c]) =
          make_float2(accl[mi][ni][0], accl[mi][ni][1]);
      *reinterpret_cast<float2*>(&cs[(r + 8) * 132 + 64 + c]) =
          make_float2(accl[mi][ni][2], accl[mi][ni][3]);
    }
  __syncthreads();

  const bool inZ = (n0 < Hh);
#pragma unroll 4
  for (int rr = 0; rr < 16; ++rr) {
    int row = wid * 16 + rr;
    int m = m0 + row;
    int c = 2 * lane;
    int n = n0 + c;
    float u0 = cs[row * 132 + c], u1 = cs[row * 132 + c + 1];
    float v0 = cs[row * 132 + 64 + c], v1 = cs[row * 132 + 64 + c + 1];
    size_t idx = (size_t)m * LH + n;
    *reinterpret_cast<float2*>(&U[idx]) = make_float2(u0, u1);
    float2 b2 = *reinterpret_cast<const float2*>(&blv[n]);
    float p0 = u0 * u0 + v0 + b2.x;
    float p1 = u1 * u1 + v1 + b2.y;
    *reinterpret_cast<float2*>(&P[idx]) = make_float2(p0, p1);
    if (inZ) {
      bool s0 = (p0 >= 0.f), s1 = (p1 >= 0.f);
      uchar2 f2;
      f2.x = s0 ? 1 : 0;
      f2.y = s1 ? 1 : 0;
      *reinterpret_cast<uchar2*>(&F[idx]) = f2;
      float z0 = s0 ? p0 : NEG_SLOPE * p0;
      float z1 = s1 ? p1 : NEG_SLOPE * p1;
      bf16 h0, l0, h1, l1;
      bsplit(z0, h0, l0);
      bsplit(z1, h1, l1);
      __nv_bfloat162 hv, lv;
      hv.x = h0; hv.y = h1;
      lv.x = l0; lv.y = l1;
      *reinterpret_cast<__nv_bfloat162*>(&zh[(size_t)m * Hh + n]) = hv;
      *reinterpret_cast<__nv_bfloat162*>(&zl[(size_t)m * Hh + n]) = lv;
    }
  }
}

// ---------------- prep / elementwise ----------------------------------------
__global__ void k_split3(const float* __restrict__ x, const float* __restrict__ Wq,
                         const float* __restrict__ Wl, bf16* __restrict__ xh,
                         bf16* __restrict__ xl, bf16* __restrict__ qh,
                         bf16* __restrict__ ql, bf16* __restrict__ lh,
                         bf16* __restrict__ ll) {
  int i = blockIdx.x * 256 + threadIdx.x;
  const int n1 = Bsz * Dd, n2 = LH * Dd;
  bf16 h, l;
  if (i < n1) {
    bsplit(x[i], h, l);
    xh[i] = h; xl[i] = l;
  } else if (i < n1 + n2) {
    int j = i - n1;
    bsplit(Wq[j], h, l);
    qh[j] = h; ql[j] = l;
  } else if (i < n1 + 2 * n2) {
    int j = i - n1 - n2;
    bsplit(Wl[j], h, l);
    lh[j] = h; ll[j] = l;
  }
}

__global__ void k_split(const float* __restrict__ in, bf16* __restrict__ h,
                        bf16* __restrict__ l, int n) {
  int i = blockIdx.x * 256 + threadIdx.x;
  if (i < n) {
    bf16 hh, ll;
    bsplit(in[i], hh, ll);
    h[i] = hh;
    l[i] = ll;
  }
}

__global__ void k_wzT(const float* __restrict__ Wz, bf16* __restrict__ h,
                      bf16* __restrict__ l) {
  int i = blockIdx.x * 256 + threadIdx.x;
  int lay = i / (Hh * Hh);
  int r = i % (Hh * Hh);
  int o = r / Hh, ii = r % Hh;
  size_t dst = (size_t)lay * Hh * Hh + (size_t)ii * Hh + o;
  bf16 hh, ll;
  bsplit(Wz[i], hh, ll);
  h[dst] = hh;
  l[dst] = ll;
}

__global__ void k_bcat16(const float* __restrict__ Wq, const float* __restrict__ Wl,
                         f16* __restrict__ o) {
  int i = blockIdx.x * 256 + threadIdx.x;
  int lay = i / (Dd * 1024);
  int r = i % (Dd * 1024);
  int d = r / 1024, k = r % 1024;
  float v = (k < Hh) ? Wq[((size_t)lay * Hh + k) * Dd + d]
                     : Wl[((size_t)lay * Hh + (k - Hh)) * Dd + d];
  o[i] = __float2half_rn(v);
}

__global__ void k_dotzero(const float* __restrict__ x, const float* __restrict__ wq,
                          float* __restrict__ S, float* __restrict__ gx) {
  int gid = blockIdx.x * 256 + threadIdx.x;
  if (gid < Bsz * Dd) gx[gid] = 0.f;
  int w = gid / 32, lane = gid % 32;
  if (w < Bsz) {
    float s = 0.f;
    for (int d = lane; d < Dd; d += 32) s += x[(size_t)w * Dd + d] * wq[d];
#pragma unroll
    for (int o = 16; o; o >>= 1) s += __shfl_xor_sync(0xFFFFFFFFu, s, o);
    if (lane == 0) S[w] = s;
  }
}

__global__ void k_bwinit(const unsigned char* __restrict__ F,
                         const float* __restrict__ U,
                         const float* __restrict__ wz_out,
                         bf16* __restrict__ zh, bf16* __restrict__ zl,
                         f16* __restrict__ ach, f16* __restrict__ acl) {
  int i = blockIdx.x * 256 + threadIdx.x;
  int m = i / Hh, h = i % Hh;
  size_t idx = (size_t)m * LH + (size_t)(Ll - 1) * Hh + h;
  float f = F[idx] ? 1.f : NEG_SLOPE;
  float ga = wz_out[h] * f;
  bf16 gh, gl;
  bsplit(ga, gh, gl);
  zh[i] = gh;
  zl[i] = gl;
  float g1 = 2.f * ga * U[idx];
  f16 h1, l1;
  size_t ai = (size_t)m * 1024 + h;
  hsplit(g1, h1, l1);
  ach[ai] = h1;
  acl[ai] = l1;
  hsplit(ga, h1, l1);
  ach[ai + Hh] = h1;
  acl[ai + Hh] = l1;
}

__global__ void k_final(const float* __restrict__ gx, const float* __restrict__ S,
                        const float* __restrict__ wq, const float* __restrict__ wl,
                        const float* __restrict__ x, float* __restrict__ out) {
  int i = blockIdx.x * 256 + threadIdx.x;
  int m = i >> 7, n = i & 127;
  out[i] = 0.5f * (gx[i] + 2.f * S[m] * wq[n] + wl[n]) + 0.5f * x[i];
}

// ---------------- host driver ------------------------------------------------
constexpr uint32_t SMEM_SZ = 81920;
constexpr uint32_t SMEM_TAIL = 51200;

extern "C" void kernel_launch(void* const* d_in, const int* in_sizes, int n_in,
                              void* d_out, int out_size) {
  const float* x = (const float*)d_in[0];
  const float* Wq = (const float*)d_in[1];
  const float* Wl = (const float*)d_in[2];
  const float* bl = (const float*)d_in[3];
  const float* Wz = (const float*)d_in[4];
  const float* wz_out = (const float*)d_in[5];
  const float* wq_out = (const float*)d_in[6];
  const float* wl_out = (const float*)d_in[7];
  float* out = (float*)d_out;

  bf16 *xh, *xl, *Wqh, *Wql, *Wlh, *Wll, *Wzh, *Wzl, *WzTh, *WzTl;
  bf16 *zAh, *zAl, *zBh, *zBl;
  f16 *Bc16, *Ach[2], *Acl[2];
  float *U, *P, *gx, *S;
  unsigned char* F;
  cudaGetSymbolAddress((void**)&xh, g_xh);
  cudaGetSymbolAddress((void**)&xl, g_xl);
  cudaGetSymbolAddress((void**)&Wqh, g_Wqh);
  cudaGetSymbolAddress((void**)&Wql, g_Wql);
  cudaGetSymbolAddress((void**)&Wlh, g_Wlh);
  cudaGetSymbolAddress((void**)&Wll, g_Wll);
  cudaGetSymbolAddress((void**)&Wzh, g_Wzh);
  cudaGetSymbolAddress((void**)&Wzl, g_Wzl);
  cudaGetSymbolAddress((void**)&WzTh, g_WzTh);
  cudaGetSymbolAddress((void**)&WzTl, g_WzTl);
  cudaGetSymbolAddress((void**)&Bc16, g_Bc16);
  cudaGetSymbolAddress((void**)&U, g_U);
  cudaGetSymbolAddress((void**)&P, g_P);
  cudaGetSymbolAddress((void**)&F, g_F);
  cudaGetSymbolAddress((void**)&zAh, g_zAh);
  cudaGetSymbolAddress((void**)&zAl, g_zAl);
  cudaGetSymbolAddress((void**)&zBh, g_zBh);
  cudaGetSymbolAddress((void**)&zBl, g_zBl);
  cudaGetSymbolAddress((void**)&Ach[0], g_Ach0);
  cudaGetSymbolAddress((void**)&Acl[0], g_Acl0);
  cudaGetSymbolAddress((void**)&Ach[1], g_Ach1);
  cudaGetSymbolAddress((void**)&Acl[1], g_Acl1);
  cudaGetSymbolAddress((void**)&gx, g_gx);
  cudaGetSymbolAddress((void**)&S, g_S);

  static bool s_init = false;
  static cudaStream_t st1, st2;
  static cudaEvent_t evStart, evWz, evWzT, evBw[10], evTail[10];
  if (!s_init) {
    cudaStreamCreateWithFlags(&st1, cudaStreamNonBlocking);
    cudaStreamCreateWithFlags(&st2, cudaStreamNonBlocking);
    cudaEventCreateWithFlags(&evStart, cudaEventDisableTiming);
    cudaEventCreateWithFlags(&evWz, cudaEventDisableTiming);
    cudaEventCreateWithFlags(&evWzT, cudaEventDisableTiming);
    for (int i = 0; i < 10; i++) {
      cudaEventCreateWithFlags(&evBw[i], cudaEventDisableTiming);
      cudaEventCreateWithFlags(&evTail[i], cudaEventDisableTiming);
    }
    cudaFuncSetAttribute(mma_gemm<2>, cudaFuncAttributeMaxDynamicSharedMemorySize, SMEM_SZ);
    cudaFuncSetAttribute(mma_gemm<3>, cudaFuncAttributeMaxDynamicSharedMemorySize, SMEM_SZ);
    cudaFuncSetAttribute(tail_gemm, cudaFuncAttributeMaxDynamicSharedMemorySize, SMEM_TAIL);
    cudaFuncSetAttribute(head_gemm, cudaFuncAttributeMaxDynamicSharedMemorySize, SMEM_SZ);
    s_init = true;
  }

  cudaEventRecord(evStart, 0);
  cudaStreamWaitEvent(st1, evStart, 0);
  cudaStreamWaitEvent(st2, evStart, 0);

  {
    int tot = Bsz * Dd + 2 * LH * Dd;
    k_split3<<<(tot + 255) / 256, 256>>>(x, Wq, Wl, xh, xl, Wqh, Wql, Wlh, Wll);
  }
  k_split<<<((Ll - 1) * Hh * Hh + 255) / 256, 256, 0, st1>>>(
      Wz, Wzh, Wzl, (Ll - 1) * Hh * Hh);
  cudaEventRecord(evWz, st1);

  head_gemm<<<dim3(LH / 64, Bsz / 128), 256, SMEM_SZ>>>(
      xh, xl, Wqh, Wql, Wlh, Wll, bl, U, P, F, zAh, zAl);

  bf16* zh2[2] = {zAh, zBh};
  bf16* zl2[2] = {zAl, zBl};
  cudaStreamWaitEvent(0, evWz, 0);
  for (int l = 1; l < Ll; ++l) {
    EpiP ep = {};
    ep.Pc = P;
    ep.F = F;
    ep.coff = l * Hh;
    ep.zh = zh2[l & 1];
    ep.zl = zl2[l & 1];
    mma_gemm<2><<<dim3(Hh / 128, Bsz / 128, 1), 256, SMEM_SZ>>>(
        zh2[(l - 1) & 1], zl2[(l - 1) & 1], Wzh + (size_t)(l - 1) * Hh * Hh,
        Wzl + (size_t)(l - 1) * Hh * Hh, Hh, Hh, Hh, ep);
  }

  k_wzT<<<((Ll - 1) * Hh * Hh + 255) / 256, 256, 0, st1>>>(Wz, WzTh, WzTl);
  cudaEventRecord(evWzT, st1);
  k_bcat16<<<(Ll * Dd * 1024 + 255) / 256, 256, 0, st2>>>(Wq, Wl, Bc16);
  k_dotzero<<<(Bsz * Dd + 255) / 256, 256, 0, st2>>>(x, wq_out, S, gx);

  k_bwinit<<<(Bsz * Hh + 255) / 256, 256>>>(F, U, wz_out, zh2[0], zl2[0],
                                            Ach[1], Acl[1]);
  cudaEventRecord(evBw[9], 0);

  cudaStreamWaitEvent(st2, evBw[9], 0);
  {
    EpiP ep = {};
    ep.gx = gx;
    ep.tscale = 1.f;
    tail_gemm<<<dim3(Dd / 64, Bsz / 128, 2), 256, SMEM_TAIL, st2>>>(
        Ach[1], Acl[1], Bc16 + (size_t)(Ll - 1) * Dd * 1024, 512, 1024, 1024,
        ep);
    cudaEventRecord(evTail[9], st2);
  }

  cudaStreamWaitEvent(0, evWzT, 0);
  int cur = 0;
  for (int l = Ll - 2; l >= 0; --l) {
    if (l + 2 <= 9) cudaStreamWaitEvent(0, evTail[l + 2], 0);
    {
      EpiP ep = {};
      ep.F = F;
      ep.U = U;
      ep.coff = l * Hh;
      ep.zh = zh2[cur ^ 1];
      ep.zl = zl2[cur ^ 1];
      ep.ach = Ach[l & 1];
      ep.acl = Acl[l & 1];
      float as = 1.f;
      for (int t = 0; t < 9 - l; ++t) as *= 0.0625f;
      ep.ascale = as;  // 16^-(9-l)
      mma_gemm<3><<<dim3(Hh / 128, Bsz / 128, 1), 256, SMEM_SZ>>>(
          zh2[cur], zl2[cur], WzTh + (size_t)l * Hh * Hh,
          WzTl + (size_t)l * Hh * Hh, Hh, Hh, Hh, ep);
      cur ^= 1;
    }
    cudaEventRecord(evBw[l], 0);
    cudaStreamWaitEvent(st2, evBw[l], 0);
    {
      EpiP ep = {};
      ep.gx = gx;
      float ts = 1.f;
      for (int t = 0; t < 9 - l; ++t) ts *= 16.f;
      ep.tscale = ts;  // 16^(9-l)
      tail_gemm<<<dim3(Dd / 64, Bsz / 128, 2), 256, SMEM_TAIL, st2>>>(
          Ach[l & 1], Acl[l & 1], Bc16 + (size_t)l * Dd * 1024, 512, 1024,
          1024, ep);
      cudaEventRecord(evTail[l], st2);
    }
  }

  cudaStreamWaitEvent(0, evTail[0], 0);
  k_final<<<(Bsz * Dd + 255) / 256, 256>>>(gx, S, wq_out, wl_out, x, out);
}

// round 12
// speedup vs baseline: 1.3788x; 1.0759x over previous
#include <cuda_runtime.h>
#include <cuda_bf16.h>
#include <cstdint>

// ===========================================================================
// ICNN forward + input-gradient via mma.sync bf16 (2-way split, 3 products).
// Round 12: R5 numerics restored (bf16 Acat/tails); head split into 10
// per-layer column slices on a side stream so fwd layer l waits only on
// head slice l — head work streams into the fwd chain's idle CTA slots.
// ===========================================================================

typedef __nv_bfloat16 bf16;

#define NEG_SLOPE 0.2f
constexpr int Bsz = 8192;
constexpr int Dd  = 128;
constexpr int Hh  = 512;
constexpr int Ll  = 10;
constexpr int LH  = Ll * Hh;  // 5120

// ---------------- static device scratch ------------------------------------
__device__ bf16 g_xh[(size_t)Bsz * Dd], g_xl[(size_t)Bsz * Dd];
__device__ bf16 g_Wqh[(size_t)LH * Dd], g_Wql[(size_t)LH * Dd];
__device__ bf16 g_Wlh[(size_t)LH * Dd], g_Wll[(size_t)LH * Dd];
__device__ bf16 g_Wzh[(size_t)(Ll - 1) * Hh * Hh], g_Wzl[(size_t)(Ll - 1) * Hh * Hh];
__device__ bf16 g_WzTh[(size_t)(Ll - 1) * Hh * Hh], g_WzTl[(size_t)(Ll - 1) * Hh * Hh];
__device__ bf16 g_Bch[(size_t)Ll * Dd * 1024], g_Bcl[(size_t)Ll * Dd * 1024];
__device__ float g_U[(size_t)Bsz * LH];
__device__ float g_P[(size_t)Bsz * LH];
__device__ unsigned char g_F[(size_t)Bsz * LH];
__device__ bf16 g_zAh[(size_t)Bsz * Hh], g_zAl[(size_t)Bsz * Hh];
__device__ bf16 g_zBh[(size_t)Bsz * Hh], g_zBl[(size_t)Bsz * Hh];
__device__ bf16 g_Ach0[(size_t)Bsz * 1024], g_Acl0[(size_t)Bsz * 1024];
__device__ bf16 g_Ach1[(size_t)Bsz * 1024], g_Acl1[(size_t)Bsz * 1024];
__device__ float g_gx[(size_t)Bsz * Dd];
__device__ float g_S[Bsz];

// ---------------- helpers ---------------------------------------------------
__device__ __forceinline__ uint32_t smem_u32(const void* p) {
  uint32_t a;
  asm("{ .reg .u64 t; cvta.to.shared.u64 t, %1; cvt.u32.u64 %0, t; }"
      : "=r"(a) : "l"(p));
  return a;
}
__device__ __forceinline__ void cpa16(uint32_t s, const void* g) {
  asm volatile("cp.async.cg.shared.global [%0], [%1], 16;" ::"r"(s), "l"(g));
}
__device__ __forceinline__ void cpa_commit() {
  asm volatile("cp.async.commit_group;" ::: "memory");
}
__device__ __forceinline__ void cpa_wait0() {
  asm volatile("cp.async.wait_group 0;" ::: "memory");
}
__device__ __forceinline__ void ldsm4(uint32_t addr, uint32_t* r) {
  asm volatile("ldmatrix.sync.aligned.m8n8.x4.shared.b16 {%0,%1,%2,%3}, [%4];"
               : "=r"(r[0]), "=r"(r[1]), "=r"(r[2]), "=r"(r[3]) : "r"(addr));
}
__device__ __forceinline__ void mma_bf16(float* c, const uint32_t* a,
                                         const uint32_t* b) {
  asm volatile(
      "mma.sync.aligned.m16n8k16.row.col.f32.bf16.bf16.f32 "
      "{%0,%1,%2,%3}, {%4,%5,%6,%7}, {%8,%9}, {%0,%1,%2,%3};"
      : "+f"(c[0]), "+f"(c[1]), "+f"(c[2]), "+f"(c[3])
      : "r"(a[0]), "r"(a[1]), "r"(a[2]), "r"(a[3]), "r"(b[0]), "r"(b[1]));
}
__device__ __forceinline__ void bsplit(float v, bf16& h, bf16& l) {
  h = __float2bfloat16(v);
  l = __float2bfloat16(v - __bfloat162float(h));
}

// ---------------- epilogue params -------------------------------------------
struct EpiP {
  const float* U;
  const float* Pc;
  unsigned char* F;
  bf16* zh;
  bf16* zl;
  bf16* ach;
  bf16* acl;
  float* gx;
  int coff;
};

// EPI: 2=fwd layer; 3=bwd layer; 4=gx accum
template <int EPI>
__device__ __forceinline__ void epi_pair(int m, int n, float d0, float d1,
                                         const EpiP& ep) {
  if (EPI == 2) {
    size_t idx = (size_t)m * LH + ep.coff + n;
    float2 pc = *reinterpret_cast<const float2*>(&ep.Pc[idx]);
    float a0 = d0 + pc.x, a1 = d1 + pc.y;
    bool p0 = (a0 >= 0.f), p1 = (a1 >= 0.f);
    uchar2 f2;
    f2.x = p0 ? 1 : 0;
    f2.y = p1 ? 1 : 0;
    *reinterpret_cast<uchar2*>(&ep.F[idx]) = f2;
    float z0 = p0 ? a0 : NEG_SLOPE * a0;
    float z1 = p1 ? a1 : NEG_SLOPE * a1;
    bf16 h0, l0, h1, l1;
    bsplit(z0, h0, l0);
    bsplit(z1, h1, l1);
    __nv_bfloat162 hv, lv;
    hv.x = h0; hv.y = h1;
    lv.x = l0; lv.y = l1;
    *reinterpret_cast<__nv_bfloat162*>(&ep.zh[(size_t)m * Hh + n]) = hv;
    *reinterpret_cast<__nv_bfloat162*>(&ep.zl[(size_t)m * Hh + n]) = lv;
  } else if (EPI == 3) {
    size_t idx = (size_t)m * LH + ep.coff + n;
    uchar2 f2 = *reinterpret_cast<const uchar2*>(&ep.F[idx]);
    float f0 = f2.x ? 1.f : NEG_SLOPE;
    float f1 = f2.y ? 1.f : NEG_SLOPE;
    float ga0 = d0 * f0, ga1 = d1 * f1;
    float2 uu = *reinterpret_cast<const float2*>(&ep.U[idx]);
    float g10 = 2.f * ga0 * uu.x, g11 = 2.f * ga1 * uu.y;
    bf16 gh0, gl0, gh1, gl1, h10, l10, h11, l11;
    bsplit(ga0, gh0, gl0);
    bsplit(ga1, gh1, gl1);
    bsplit(g10, h10, l10);
    bsplit(g11, h11, l11);
    __nv_bfloat162 v;
    v.x = gh0; v.y = gh1;
    *reinterpret_cast<__nv_bfloat162*>(&ep.zh[(size_t)m * Hh + n]) = v;
    v.x = gl0; v.y = gl1;
    *reinterpret_cast<__nv_bfloat162*>(&ep.zl[(size_t)m * Hh + n]) = v;
    size_t ai = (size_t)m * 1024 + n;
    v.x = h10; v.y = h11;
    *reinterpret_cast<__nv_bfloat162*>(&ep.ach[ai]) = v;
    v.x = l10; v.y = l11;
    *reinterpret_cast<__nv_bfloat162*>(&ep.acl[ai]) = v;
    v.x = gh0; v.y = gh1;
    *reinterpret_cast<__nv_bfloat162*>(&ep.ach[ai + Hh]) = v;
    v.x = gl0; v.y = gl1;
    *reinterpret_cast<__nv_bfloat162*>(&ep.acl[ai + Hh]) = v;
  } else {  // EPI == 4
    atomicAdd(&ep.gx[(size_t)m * Dd + n], d0);
    atomicAdd(&ep.gx[(size_t)m * Dd + n + 1], d1);
  }
}

// ---------------- chain / tail GEMM (bf16, 3 products) -----------------------
// C[128,128]/CTA = (Ah+Al)[M,K] @ (Bh+Bl)[N,K]^T.
// 8 warps, warp tile 32x64. BK=32 double-buffered cp.async. 2 CTAs/SM pinned.
template <int EPI>
__global__ __launch_bounds__(256, 2) void mma_gemm(
    const bf16* __restrict__ Ah, const bf16* __restrict__ Al,
    const bf16* __restrict__ Bh, const bf16* __restrict__ Bl, int Kc, int lda,
    int ldb, EpiP ep) {
  extern __shared__ char smc[];
  const uint32_t sb = smem_u32(smc);
  const int tid = threadIdx.x, lane = tid & 31, wid = tid >> 5;
  const int m0 = blockIdx.y * 128, n0 = blockIdx.x * 128;
  const int wm = (wid & 3) * 32, wn = (wid >> 2) * 64;
  const int kstart = blockIdx.z * Kc;
  constexpr uint32_t PL = 10240;
  constexpr uint32_t STG = 40960;

  const int lr = tid >> 1;
  const int lc = (tid & 1) * 2;

  const bf16* pA0 = Ah + (size_t)(m0 + lr) * lda + lc * 8;
  const bf16* pA1 = Al + (size_t)(m0 + lr) * lda + lc * 8;
  const bf16* pB0 = Bh + (size_t)(n0 + lr) * ldb + lc * 8;
  const bf16* pB1 = Bl + (size_t)(n0 + lr) * ldb + lc * 8;

  auto stage_load = [&](int s, int k0) {
    uint32_t base = sb + (uint32_t)s * STG + (uint32_t)lr * 80 + lc * 16;
    cpa16(base, pA0 + k0);
    cpa16(base + 16, pA0 + k0 + 8);
    cpa16(base + PL, pA1 + k0);
    cpa16(base + PL + 16, pA1 + k0 + 8);
    cpa16(base + 2 * PL, pB0 + k0);
    cpa16(base + 2 * PL + 16, pB0 + k0 + 8);
    cpa16(base + 3 * PL, pB1 + k0);
    cpa16(base + 3 * PL + 16, pB1 + k0 + 8);
    cpa_commit();
  };

  float acc[2][8][4];
#pragma unroll
  for (int i = 0; i < 2; i++)
#pragma unroll
    for (int j = 0; j < 8; j++)
#pragma unroll
      for (int q = 0; q < 4; q++) acc[i][j][q] = 0.f;

  const int nk = Kc / 32;
  stage_load(0, kstart);
  cpa_wait0();
  __syncthreads();

  const int g3 = lane >> 3, r8 = lane & 7;

  for (int kb = 0; kb < nk; ++kb) {
    const int s = kb & 1;
    if (kb + 1 < nk) stage_load(s ^ 1, kstart + (kb + 1) * 32);
    const uint32_t ab = sb + (uint32_t)s * STG;
#pragma unroll
    for (int k16 = 0; k16 < 32; k16 += 16) {
      uint32_t Ahf[2][4], Alf[2][4], Bhf[8][2], Blf[8][2];
#pragma unroll
      for (int mi = 0; mi < 2; mi++) {
        uint32_t row = wm + mi * 16 + (g3 & 1) * 8 + r8;
        uint32_t col = k16 + (g3 >> 1) * 8;
        uint32_t ad = ab + row * 80 + col * 2;
        ldsm4(ad, Ahf[mi]);
        ldsm4(ad + PL, Alf[mi]);
      }
#pragma unroll
      for (int pi = 0; pi < 4; pi++) {
        uint32_t row = wn + (2 * pi + (g3 >> 1)) * 8 + r8;
        uint32_t col = k16 + (g3 & 1) * 8;
        uint32_t ad = ab + 2 * PL + row * 80 + col * 2;
        uint32_t t[4];
        ldsm4(ad, t);
        Bhf[2 * pi][0] = t[0];
        Bhf[2 * pi][1] = t[1];
        Bhf[2 * pi + 1][0] = t[2];
        Bhf[2 * pi + 1][1] = t[3];
        ldsm4(ad + PL, t);
        Blf[2 * pi][0] = t[0];
        Blf[2 * pi][1] = t[1];
        Blf[2 * pi + 1][0] = t[2];
        Blf[2 * pi + 1][1] = t[3];
      }
#pragma unroll
      for (int mi = 0; mi < 2; mi++)
#pragma unroll
        for (int ni = 0; ni < 8; ni++) {
          mma_bf16(acc[mi][ni], Ahf[mi], Bhf[ni]);
          mma_bf16(acc[mi][ni], Ahf[mi], Blf[ni]);
          mma_bf16(acc[mi][ni], Alf[mi], Bhf[ni]);
        }
    }
    cpa_wait0();
    __syncthreads();
  }

  // ---- stage accumulators to smem ----
  float* cs = reinterpret_cast<float*>(smc);
  const int g = lane >> 2, t4 = lane & 3;
#pragma unroll
  for (int mi = 0; mi < 2; mi++)
#pragma unroll
    for (int ni = 0; ni < 8; ni++) {
      int r = wm + mi * 16 + g;
      int c = wn + ni * 8 + t4 * 2;
      *reinterpret_cast<float2*>(&cs[r * 132 + c]) =
          make_float2(acc[mi][ni][0], acc[mi][ni][1]);
      *reinterpret_cast<float2*>(&cs[(r + 8) * 132 + c]) =
          make_float2(acc[mi][ni][2], acc[mi][ni][3]);
    }
  __syncthreads();

#pragma unroll 4
  for (int rr = 0; rr < 16; ++rr) {
    int row = wid * 16 + rr;
    int m = m0 + row;
#pragma unroll
    for (int i = 0; i < 2; ++i) {
      int c = 2 * lane + 64 * i;
      float d0 = cs[row * 132 + c];
      float d1 = cs[row * 132 + c + 1];
      epi_pair<EPI>(m, n0 + c, d0, d1, ep);
    }
  }
}

// ---------------- fused head GEMM slice (bf16, dual accumulators) ------------
// Slice computes U/P for global cols [coff + n0, coff + n0 + 64).
// One pass: U = x@Wq^T, P = U^2 + x@Wl^T + bl; z0/F emitted when coff==0.
__global__ __launch_bounds__(256, 2) void head_gemm(
    const bf16* __restrict__ Axh, const bf16* __restrict__ Axl,
    const bf16* __restrict__ Wqh, const bf16* __restrict__ Wql,
    const bf16* __restrict__ Wlh, const bf16* __restrict__ Wll,
    const float* __restrict__ blv, float* __restrict__ U,
    float* __restrict__ P, unsigned char* __restrict__ F,
    bf16* __restrict__ zh, bf16* __restrict__ zl, int coff) {
  extern __shared__ char smc[];
  const uint32_t sb = smem_u32(smc);
  const int tid = threadIdx.x, lane = tid & 31, wid = tid >> 5;
  const int m0 = blockIdx.y * 128, n0 = blockIdx.x * 64;
  const int wm = (wid & 3) * 32, wn = (wid >> 2) * 32;
  constexpr uint32_t PA = 10240;
  constexpr uint32_t PB = 5120;
  constexpr uint32_t STG = 2 * PA + 4 * PB;  // 40960

  const int lr = tid >> 1, lc = (tid & 1) * 2;
  const bf16* pA0 = Axh + (size_t)(m0 + lr) * Dd + lc * 8;
  const bf16* pA1 = Axl + (size_t)(m0 + lr) * Dd + lc * 8;
  const int br = (tid & 127) >> 1, bcp = (tid & 1) * 2;
  const int bw = tid >> 7;
  const bf16* pB0 = (bw ? Wlh : Wqh) + (size_t)(n0 + br) * Dd + bcp * 8;
  const bf16* pB1 = (bw ? Wll : Wql) + (size_t)(n0 + br) * Dd + bcp * 8;
  const uint32_t bOff = 2 * PA + (uint32_t)bw * 2 * PB + (uint32_t)br * 80 + bcp * 16;

  auto stage_load = [&](int s, int k0) {
    uint32_t base = sb + (uint32_t)s * STG;
    uint32_t aA = base + (uint32_t)lr * 80 + lc * 16;
    cpa16(aA, pA0 + k0);
    cpa16(aA + 16, pA0 + k0 + 8);
    cpa16(aA + PA, pA1 + k0);
    cpa16(aA + PA + 16, pA1 + k0 + 8);
    uint32_t aB = base + bOff;
    cpa16(aB, pB0 + k0);
    cpa16(aB + 16, pB0 + k0 + 8);
    cpa16(aB + PB, pB1 + k0);
    cpa16(aB + PB + 16, pB1 + k0 + 8);
    cpa_commit();
  };

  float accq[2][4][4], accl[2][4][4];
#pragma unroll
  for (int i = 0; i < 2; i++)
#pragma unroll
    for (int j = 0; j < 4; j++)
#pragma unroll
      for (int q = 0; q < 4; q++) accq[i][j][q] = accl[i][j][q] = 0.f;

  constexpr int nk = Dd / 32;
  stage_load(0, 0);
  cpa_wait0();
  __syncthreads();

  const int g3 = lane >> 3, r8 = lane & 7;

  for (int kb = 0; kb < nk; ++kb) {
    const int s = kb & 1;
    if (kb + 1 < nk) stage_load(s ^ 1, (kb + 1) * 32);
    const uint32_t ab = sb + (uint32_t)s * STG;
#pragma unroll
    for (int k16 = 0; k16 < 32; k16 += 16) {
      uint32_t Ahf[2][4], Alf[2][4];
      uint32_t Bqh_[4][2], Bql_[4][2], Blh_[4][2], Bll_[4][2];
#pragma unroll
      for (int mi = 0; mi < 2; mi++) {
        uint32_t row = wm + mi * 16 + (g3 & 1) * 8 + r8;
        uint32_t col = k16 + (g3 >> 1) * 8;
        uint32_t ad = ab + row * 80 + col * 2;
        ldsm4(ad, Ahf[mi]);
        ldsm4(ad + PA, Alf[mi]);
      }
#pragma unroll
      for (int pi = 0; pi < 2; pi++) {
        uint32_t row = wn + (2 * pi + (g3 >> 1)) * 8 + r8;
        uint32_t col = k16 + (g3 & 1) * 8;
        uint32_t adq = ab + 2 * PA + row * 80 + col * 2;
        uint32_t t[4];
        ldsm4(adq, t);
        Bqh_[2 * pi][0] = t[0]; Bqh_[2 * pi][1] = t[1];
        Bqh_[2 * pi + 1][0] = t[2]; Bqh_[2 * pi + 1][1] = t[3];
        ldsm4(adq + PB, t);
        Bql_[2 * pi][0] = t[0]; Bql_[2 * pi][1] = t[1];
        Bql_[2 * pi + 1][0] = t[2]; Bql_[2 * pi + 1][1] = t[3];
        ldsm4(adq + 2 * PB, t);
        Blh_[2 * pi][0] = t[0]; Blh_[2 * pi][1] = t[1];
        Blh_[2 * pi + 1][0] = t[2]; Blh_[2 * pi + 1][1] = t[3];
        ldsm4(adq + 3 * PB, t);
        Bll_[2 * pi][0] = t[0]; Bll_[2 * pi][1] = t[1];
        Bll_[2 * pi + 1][0] = t[2]; Bll_[2 * pi + 1][1] = t[3];
      }
#pragma unroll
      for (int mi = 0; mi < 2; mi++)
#pragma unroll
        for (int ni = 0; ni < 4; ni++) {
          mma_bf16(accq[mi][ni], Ahf[mi], Bqh_[ni]);
          mma_bf16(accq[mi][ni], Ahf[mi], Bql_[ni]);
          mma_bf16(accq[mi][ni], Alf[mi], Bqh_[ni]);
          mma_bf16(accl[mi][ni], Ahf[mi], Blh_[ni]);
          mma_bf16(accl[mi][ni], Ahf[mi], Bll_[ni]);
          mma_bf16(accl[mi][ni], Alf[mi], Blh_[ni]);
        }
    }
    cpa_wait0();
    __syncthreads();
  }

  float* cs = reinterpret_cast<float*>(smc);
  const int g = lane >> 2, t4 = lane & 3;
#pragma unroll
  for (int mi = 0; mi < 2; mi++)
#pragma unroll
    for (int ni = 0; ni < 4; ni++) {
      int r = wm + mi * 16 + g;
      int c = wn + ni * 8 + t4 * 2;
      *reinterpret_cast<float2*>(&cs[r * 132 + c]) =
          make_float2(accq[mi][ni][0], accq[mi][ni][1]);
      *reinterpret_cast<float2*>(&cs[(r + 8) * 132 + c]) =
          make_float2(accq[mi][ni][2], accq[mi][ni][3]);
      *reinterpret_cast<float2*>(&cs[r * 132 + 64 + c]) =
          make_float2(accl[mi][ni][0], accl[mi][ni][1]);
      *reinterpret_cast<float2*>(&cs[(r + 8) * 132 + 64 + c]) =
          make_float2(accl[mi][ni][2], accl[mi][ni][3]);
    }
  __syncthreads();

  const bool inZ = (coff == 0);
#pragma unroll 4
  for (int rr = 0; rr < 16; ++rr) {
    int row = wid * 16 + rr;
    int m = m0 + row;
    int c = 2 * lane;
    int n = coff + n0 + c;  // global column
    float u0 = cs[row * 132 + c], u1 = cs[row * 132 + c + 1];
    float v0 = cs[row * 132 + 64 + c], v1 = cs[row * 132 + 64 + c + 1];
    size_t idx = (size_t)m * LH + n;
    *reinterpret_cast<float2*>(&U[idx]) = make_float2(u0, u1);
    float2 b2 = *reinterpret_cast<const float2*>(&blv[n]);
    float p0 = u0 * u0 + v0 + b2.x;
    float p1 = u1 * u1 + v1 + b2.y;
    *reinterpret_cast<float2*>(&P[idx]) = make_float2(p0, p1);
    if (inZ) {
      bool s0 = (p0 >= 0.f), s1 = (p1 >= 0.f);
      uchar2 f2;
      f2.x = s0 ? 1 : 0;
      f2.y = s1 ? 1 : 0;
      *reinterpret_cast<uchar2*>(&F[idx]) = f2;
      float z0 = s0 ? p0 : NEG_SLOPE * p0;
      float z1 = s1 ? p1 : NEG_SLOPE * p1;
      bf16 h0, l0, h1, l1;
      bsplit(z0, h0, l0);
      bsplit(z1, h1, l1);
      __nv_bfloat162 hv, lv;
      hv.x = h0; hv.y = h1;
      lv.x = l0; lv.y = l1;
      *reinterpret_cast<__nv_bfloat162*>(&zh[(size_t)m * Hh + n0 + c]) = hv;
      *reinterpret_cast<__nv_bfloat162*>(&zl[(size_t)m * Hh + n0 + c]) = lv;
    }
  }
}

// ---------------- prep / elementwise ----------------------------------------
__global__ void k_split3(const float* __restrict__ x, const float* __restrict__ Wq,
                         const float* __restrict__ Wl, bf16* __restrict__ xh,
                         bf16* __restrict__ xl, bf16* __restrict__ qh,
                         bf16* __restrict__ ql, bf16* __restrict__ lh,
                         bf16* __restrict__ ll) {
  int i = blockIdx.x * 256 + threadIdx.x;
  const int n1 = Bsz * Dd, n2 = LH * Dd;
  bf16 h, l;
  if (i < n1) {
    bsplit(x[i], h, l);
    xh[i] = h; xl[i] = l;
  } else if (i < n1 + n2) {
    int j = i - n1;
    bsplit(Wq[j], h, l);
    qh[j] = h; ql[j] = l;
  } else if (i < n1 + 2 * n2) {
    int j = i - n1 - n2;
    bsplit(Wl[j], h, l);
    lh[j] = h; ll[j] = l;
  }
}

__global__ void k_split(const float* __restrict__ in, bf16* __restrict__ h,
                        bf16* __restrict__ l, int n) {
  int i = blockIdx.x * 256 + threadIdx.x;
  if (i < n) {
    bf16 hh, ll;
    bsplit(in[i], hh, ll);
    h[i] = hh;
    l[i] = ll;
  }
}

__global__ void k_wzT(const float* __restrict__ Wz, bf16* __restrict__ h,
                      bf16* __restrict__ l) {
  int i = blockIdx.x * 256 + threadIdx.x;
  int lay = i / (Hh * Hh);
  int r = i % (Hh * Hh);
  int o = r / Hh, ii = r % Hh;
  size_t dst = (size_t)lay * Hh * Hh + (size_t)ii * Hh + o;
  bf16 hh, ll;
  bsplit(Wz[i], hh, ll);
  h[dst] = hh;
  l[dst] = ll;
}

__global__ void k_bcat(const float* __restrict__ Wq, const float* __restrict__ Wl,
                       bf16* __restrict__ h, bf16* __restrict__ l) {
  int i = blockIdx.x * 256 + threadIdx.x;
  int lay = i / (Dd * 1024);
  int r = i % (Dd * 1024);
  int d = r / 1024, k = r % 1024;
  float v = (k < Hh) ? Wq[((size_t)lay * Hh + k) * Dd + d]
                     : Wl[((size_t)lay * Hh + (k - Hh)) * Dd + d];
  bf16 hh, ll;
  bsplit(v, hh, ll);
  h[i] = hh;
  l[i] = ll;
}

__global__ void k_dotzero(const float* __restrict__ x, const float* __restrict__ wq,
                          float* __restrict__ S, float* __restrict__ gx) {
  int gid = blockIdx.x * 256 + threadIdx.x;
  if (gid < Bsz * Dd) gx[gid] = 0.f;
  int w = gid / 32, lane = gid % 32;
  if (w < Bsz) {
    float s = 0.f;
    for (int d = lane; d < Dd; d += 32) s += x[(size_t)w * Dd + d] * wq[d];
#pragma unroll
    for (int o = 16; o; o >>= 1) s += __shfl_xor_sync(0xFFFFFFFFu, s, o);
    if (lane == 0) S[w] = s;
  }
}

__global__ void k_bwinit(const unsigned char* __restrict__ F,
                         const float* __restrict__ U,
                         const float* __restrict__ wz_out,
                         bf16* __restrict__ zh, bf16* __restrict__ zl,
                         bf16* __restrict__ ach, bf16* __restrict__ acl) {
  int i = blockIdx.x * 256 + threadIdx.x;
  int m = i / Hh, h = i % Hh;
  size_t idx = (size_t)m * LH + (size_t)(Ll - 1) * Hh + h;
  float f = F[idx] ? 1.f : NEG_SLOPE;
  float ga = wz_out[h] * f;
  bf16 gh, gl;
  bsplit(ga, gh, gl);
  zh[i] = gh;
  zl[i] = gl;
  float g1 = 2.f * ga * U[idx];
  bf16 h1, l1;
  bsplit(g1, h1, l1);
  size_t ai = (size_t)m * 1024 + h;
  ach[ai] = h1;
  acl[ai] = l1;
  ach[ai + Hh] = gh;
  acl[ai + Hh] = gl;
}

__global__ void k_final(const float* __restrict__ gx, const float* __restrict__ S,
                        const float* __restrict__ wq, const float* __restrict__ wl,
                        const float* __restrict__ x, float* __restrict__ out) {
  int i = blockIdx.x * 256 + threadIdx.x;
  int m = i >> 7, n = i & 127;
  out[i] = 0.5f * (gx[i] + 2.f * S[m] * wq[n] + wl[n]) + 0.5f * x[i];
}

// ---------------- host driver ------------------------------------------------
constexpr uint32_t SMEM_SZ = 81920;

extern "C" void kernel_launch(void* const* d_in, const int* in_sizes, int n_in,
                              void* d_out, int out_size) {
  const float* x = (const float*)d_in[0];
  const float* Wq = (const float*)d_in[1];
  const float* Wl = (const float*)d_in[2];
  const float* bl = (const float*)d_in[3];
  const float* Wz = (const float*)d_in[4];
  const float* wz_out = (const float*)d_in[5];
  const float* wq_out = (const float*)d_in[6];
  const float* wl_out = (const float*)d_in[7];
  float* out = (float*)d_out;

  bf16 *xh, *xl, *Wqh, *Wql, *Wlh, *Wll, *Wzh, *Wzl, *WzTh, *WzTl, *Bch, *Bcl;
  bf16 *zAh, *zAl, *zBh, *zBl;
  bf16 *Ach[2], *Acl[2];
  float *U, *P, *gx, *S;
  unsigned char* F;
  cudaGetSymbolAddress((void**)&xh, g_xh);
  cudaGetSymbolAddress((void**)&xl, g_xl);
  cudaGetSymbolAddress((void**)&Wqh, g_Wqh);
  cudaGetSymbolAddress((void**)&Wql, g_Wql);
  cudaGetSymbolAddress((void**)&Wlh, g_Wlh);
  cudaGetSymbolAddress((void**)&Wll, g_Wll);
  cudaGetSymbolAddress((void**)&Wzh, g_Wzh);
  cudaGetSymbolAddress((void**)&Wzl, g_Wzl);
  cudaGetSymbolAddress((void**)&WzTh, g_WzTh);
  cudaGetSymbolAddress((void**)&WzTl, g_WzTl);
  cudaGetSymbolAddress((void**)&Bch, g_Bch);
  cudaGetSymbolAddress((void**)&Bcl, g_Bcl);
  cudaGetSymbolAddress((void**)&U, g_U);
  cudaGetSymbolAddress((void**)&P, g_P);
  cudaGetSymbolAddress((void**)&F, g_F);
  cudaGetSymbolAddress((void**)&zAh, g_zAh);
  cudaGetSymbolAddress((void**)&zAl, g_zAl);
  cudaGetSymbolAddress((void**)&zBh, g_zBh);
  cudaGetSymbolAddress((void**)&zBl, g_zBl);
  cudaGetSymbolAddress((void**)&Ach[0], g_Ach0);
  cudaGetSymbolAddress((void**)&Acl[0], g_Acl0);
  cudaGetSymbolAddress((void**)&Ach[1], g_Ach1);
  cudaGetSymbolAddress((void**)&Acl[1], g_Acl1);
  cudaGetSymbolAddress((void**)&gx, g_gx);
  cudaGetSymbolAddress((void**)&S, g_S);

  static bool s_init = false;
  static cudaStream_t st1, st2;
  static cudaEvent_t evStart, evSplit, evWz, evWzT, evHd[10], evBw[10], evTail[10];
  if (!s_init) {
    cudaStreamCreateWithFlags(&st1, cudaStreamNonBlocking);
    cudaStreamCreateWithFlags(&st2, cudaStreamNonBlocking);
    cudaEventCreateWithFlags(&evStart, cudaEventDisableTiming);
    cudaEventCreateWithFlags(&evSplit, cudaEventDisableTiming);
    cudaEventCreateWithFlags(&evWz, cudaEventDisableTiming);
    cudaEventCreateWithFlags(&evWzT, cudaEventDisableTiming);
    for (int i = 0; i < 10; i++) {
      cudaEventCreateWithFlags(&evHd[i], cudaEventDisableTiming);
      cudaEventCreateWithFlags(&evBw[i], cudaEventDisableTiming);
      cudaEventCreateWithFlags(&evTail[i], cudaEventDisableTiming);
    }
    cudaFuncSetAttribute(mma_gemm<2>, cudaFuncAttributeMaxDynamicSharedMemorySize, SMEM_SZ);
    cudaFuncSetAttribute(mma_gemm<3>, cudaFuncAttributeMaxDynamicSharedMemorySize, SMEM_SZ);
    cudaFuncSetAttribute(mma_gemm<4>, cudaFuncAttributeMaxDynamicSharedMemorySize, SMEM_SZ);
    cudaFuncSetAttribute(head_gemm, cudaFuncAttributeMaxDynamicSharedMemorySize, SMEM_SZ);
    s_init = true;
  }

  // ---- fork side streams ----
  cudaEventRecord(evStart, 0);
  cudaStreamWaitEvent(st1, evStart, 0);
  cudaStreamWaitEvent(st2, evStart, 0);

  // s0: input/weight splits
  {
    int tot = Bsz * Dd + 2 * LH * Dd;
    k_split3<<<(tot + 255) / 256, 256>>>(x, Wq, Wl, xh, xl, Wqh, Wql, Wlh, Wll);
  }
  cudaEventRecord(evSplit, 0);

  // st2: Wz split (fwd) then transpose (bwd), tail weights, dot+gx zero
  k_split<<<((Ll - 1) * Hh * Hh + 255) / 256, 256, 0, st2>>>(
      Wz, Wzh, Wzl, (Ll - 1) * Hh * Hh);
  cudaEventRecord(evWz, st2);
  k_wzT<<<((Ll - 1) * Hh * Hh + 255) / 256, 256, 0, st2>>>(Wz, WzTh, WzTl);
  cudaEventRecord(evWzT, st2);
  k_bcat<<<(Ll * Dd * 1024 + 255) / 256, 256, 0, st2>>>(Wq, Wl, Bch, Bcl);
  k_dotzero<<<(Bsz * Dd + 255) / 256, 256, 0, st2>>>(x, wq_out, S, gx);

  // st1: head slices, one per layer, each followed by an event
  cudaStreamWaitEvent(st1, evSplit, 0);
  for (int l = 0; l < Ll; ++l) {
    head_gemm<<<dim3(Hh / 64, Bsz / 128), 256, SMEM_SZ, st1>>>(
        xh, xl, Wqh + (size_t)l * Hh * Dd, Wql + (size_t)l * Hh * Dd,
        Wlh + (size_t)l * Hh * Dd, Wll + (size_t)l * Hh * Dd, bl, U, P, F,
        zAh, zAl, l * Hh);
    cudaEventRecord(evHd[l], st1);
  }

  // s0: forward chain; layer l waits on head slice l
  bf16* zh2[2] = {zAh, zBh};
  bf16* zl2[2] = {zAl, zBl};
  cudaStreamWaitEvent(0, evWz, 0);
  for (int l = 1; l < Ll; ++l) {
    cudaStreamWaitEvent(0, evHd[l], 0);
    EpiP ep = {};
    ep.Pc = P;
    ep.F = F;
    ep.coff = l * Hh;
    ep.zh = zh2[l & 1];
    ep.zl = zl2[l & 1];
    mma_gemm<2><<<dim3(Hh / 128, Bsz / 128, 1), 256, SMEM_SZ>>>(
        zh2[(l - 1) & 1], zl2[(l - 1) & 1], Wzh + (size_t)(l - 1) * Hh * Hh,
        Wzl + (size_t)(l - 1) * Hh * Hh, Hh, Hh, Hh, ep);
  }

  // ---- backward init (layer 9) ----
  k_bwinit<<<(Bsz * Hh + 255) / 256, 256>>>(F, U, wz_out, zh2[0], zl2[0],
                                            Ach[1], Acl[1]);
  cudaEventRecord(evBw[9], 0);

  cudaStreamWaitEvent(st2, evBw[9], 0);
  {
    EpiP ep = {};
    ep.gx = gx;
    mma_gemm<4><<<dim3(1, Bsz / 128, 2), 256, SMEM_SZ, st2>>>(
        Ach[1], Acl[1], Bch + (size_t)(Ll - 1) * Dd * 1024,
        Bcl + (size_t)(Ll - 1) * Dd * 1024, 512, 1024, 1024, ep);
    cudaEventRecord(evTail[9], st2);
  }

  // ---- backward chain on s0, tails on st2 ----
  cudaStreamWaitEvent(0, evWzT, 0);
  int cur = 0;
  for (int l = Ll - 2; l >= 0; --l) {
    if (l + 2 <= 9) cudaStreamWaitEvent(0, evTail[l + 2], 0);
    {
      EpiP ep = {};
      ep.F = F;
      ep.U = U;
      ep.coff = l * Hh;
      ep.zh = zh2[cur ^ 1];
      ep.zl = zl2[cur ^ 1];
      ep.ach = Ach[l & 1];
      ep.acl = Acl[l & 1];
      mma_gemm<3><<<dim3(Hh / 128, Bsz / 128, 1), 256, SMEM_SZ>>>(
          zh2[cur], zl2[cur], WzTh + (size_t)l * Hh * Hh,
          WzTl + (size_t)l * Hh * Hh, Hh, Hh, Hh, ep);
      cur ^= 1;
    }
    cudaEventRecord(evBw[l], 0);
    cudaStreamWaitEvent(st2, evBw[l], 0);
    {
      EpiP ep = {};
      ep.gx = gx;
      mma_gemm<4><<<dim3(1, Bsz / 128, 2), 256, SMEM_SZ, st2>>>(
          Ach[l & 1], Acl[l & 1], Bch + (size_t)l * Dd * 1024,
          Bcl + (size_t)l * Dd * 1024, 512, 1024, 1024, ep);
      cudaEventRecord(evTail[l], st2);
    }
  }

  // ---- join and final combine ----
  cudaStreamWaitEvent(0, evTail[0], 0);
  k_final<<<(Bsz * Dd + 255) / 256, 256>>>(gx, S, wq_out, wl_out, x, out);
}

// round 13
// speedup vs baseline: 1.5106x; 1.0956x over previous
#include <cuda_runtime.h>
#include <cuda_bf16.h>
#include <cuda_fp16.h>
#include <cstdint>

// ===========================================================================
// ICNN forward + input-gradient via mma.sync (bf16 3-product chain/head,
// fp16 2-product tails). Round 13: Acat built by a separate memory-bound
// k_acat kernel (st2) so the chain EPI3 stays lean (<=128 regs); tails use
// fp16 pair x fp16 single weights with 16^±(9-l) power-of-2 scaling
// (validated R10: rel_err 2.94e-4). Tail tensor work 64.4 -> 43 GF.
// ===========================================================================

typedef __nv_bfloat16 bf16;
typedef __half f16;

#define NEG_SLOPE 0.2f
constexpr int Bsz = 8192;
constexpr int Dd  = 128;
constexpr int Hh  = 512;
constexpr int Ll  = 10;
constexpr int LH  = Ll * Hh;  // 5120

// ---------------- static device scratch ------------------------------------
__device__ bf16 g_xh[(size_t)Bsz * Dd], g_xl[(size_t)Bsz * Dd];
__device__ bf16 g_Wqh[(size_t)LH * Dd], g_Wql[(size_t)LH * Dd];
__device__ bf16 g_Wlh[(size_t)LH * Dd], g_Wll[(size_t)LH * Dd];
__device__ bf16 g_Wzh[(size_t)(Ll - 1) * Hh * Hh], g_Wzl[(size_t)(Ll - 1) * Hh * Hh];
__device__ bf16 g_WzTh[(size_t)(Ll - 1) * Hh * Hh], g_WzTl[(size_t)(Ll - 1) * Hh * Hh];
__device__ f16  g_Bc16[(size_t)Ll * Dd * 1024];
__device__ float g_U[(size_t)Bsz * LH];
__device__ float g_P[(size_t)Bsz * LH];
__device__ unsigned char g_F[(size_t)Bsz * LH];
__device__ bf16 g_zAh[(size_t)Bsz * Hh], g_zAl[(size_t)Bsz * Hh];
__device__ bf16 g_zBh[(size_t)Bsz * Hh], g_zBl[(size_t)Bsz * Hh];
__device__ f16 g_Ach0[(size_t)Bsz * 1024], g_Acl0[(size_t)Bsz * 1024];
__device__ f16 g_Ach1[(size_t)Bsz * 1024], g_Acl1[(size_t)Bsz * 1024];
__device__ float g_gx[(size_t)Bsz * Dd];
__device__ float g_S[Bsz];

// ---------------- helpers ---------------------------------------------------
__device__ __forceinline__ uint32_t smem_u32(const void* p) {
  uint32_t a;
  asm("{ .reg .u64 t; cvta.to.shared.u64 t, %1; cvt.u32.u64 %0, t; }"
      : "=r"(a) : "l"(p));
  return a;
}
__device__ __forceinline__ void cpa16(uint32_t s, const void* g) {
  asm volatile("cp.async.cg.shared.global [%0], [%1], 16;" ::"r"(s), "l"(g));
}
__device__ __forceinline__ void cpa_commit() {
  asm volatile("cp.async.commit_group;" ::: "memory");
}
__device__ __forceinline__ void cpa_wait0() {
  asm volatile("cp.async.wait_group 0;" ::: "memory");
}
__device__ __forceinline__ void ldsm4(uint32_t addr, uint32_t* r) {
  asm volatile("ldmatrix.sync.aligned.m8n8.x4.shared.b16 {%0,%1,%2,%3}, [%4];"
               : "=r"(r[0]), "=r"(r[1]), "=r"(r[2]), "=r"(r[3]) : "r"(addr));
}
__device__ __forceinline__ void mma_bf16(float* c, const uint32_t* a,
                                         const uint32_t* b) {
  asm volatile(
      "mma.sync.aligned.m16n8k16.row.col.f32.bf16.bf16.f32 "
      "{%0,%1,%2,%3}, {%4,%5,%6,%7}, {%8,%9}, {%0,%1,%2,%3};"
      : "+f"(c[0]), "+f"(c[1]), "+f"(c[2]), "+f"(c[3])
      : "r"(a[0]), "r"(a[1]), "r"(a[2]), "r"(a[3]), "r"(b[0]), "r"(b[1]));
}
__device__ __forceinline__ void mma_f16(float* c, const uint32_t* a,
                                        const uint32_t* b) {
  asm volatile(
      "mma.sync.aligned.m16n8k16.row.col.f32.f16.f16.f32 "
      "{%0,%1,%2,%3}, {%4,%5,%6,%7}, {%8,%9}, {%0,%1,%2,%3};"
      : "+f"(c[0]), "+f"(c[1]), "+f"(c[2]), "+f"(c[3])
      : "r"(a[0]), "r"(a[1]), "r"(a[2]), "r"(a[3]), "r"(b[0]), "r"(b[1]));
}
__device__ __forceinline__ void bsplit(float v, bf16& h, bf16& l) {
  h = __float2bfloat16(v);
  l = __float2bfloat16(v - __bfloat162float(h));
}
__device__ __forceinline__ void hsplit(float v, f16& h, f16& l) {
  h = __float2half_rn(v);
  l = __float2half_rn(v - __half2float(h));
}

// ---------------- epilogue params -------------------------------------------
struct EpiP {
  const float* Pc;
  unsigned char* F;
  bf16* zh;
  bf16* zl;
  float* gx;
  int coff;
  float tscale;  // EPI4: gx accumulate scale = 16^(9-l)
};

// EPI: 2=fwd layer; 3=bwd layer (z only); 4=gx accum (tail)
template <int EPI>
__device__ __forceinline__ void epi_pair(int m, int n, float d0, float d1,
                                         const EpiP& ep) {
  if (EPI == 2) {
    size_t idx = (size_t)m * LH + ep.coff + n;
    float2 pc = *reinterpret_cast<const float2*>(&ep.Pc[idx]);
    float a0 = d0 + pc.x, a1 = d1 + pc.y;
    bool p0 = (a0 >= 0.f), p1 = (a1 >= 0.f);
    uchar2 f2;
    f2.x = p0 ? 1 : 0;
    f2.y = p1 ? 1 : 0;
    *reinterpret_cast<uchar2*>(&ep.F[idx]) = f2;
    float z0 = p0 ? a0 : NEG_SLOPE * a0;
    float z1 = p1 ? a1 : NEG_SLOPE * a1;
    bf16 h0, l0, h1, l1;
    bsplit(z0, h0, l0);
    bsplit(z1, h1, l1);
    __nv_bfloat162 hv, lv;
    hv.x = h0; hv.y = h1;
    lv.x = l0; lv.y = l1;
    *reinterpret_cast<__nv_bfloat162*>(&ep.zh[(size_t)m * Hh + n]) = hv;
    *reinterpret_cast<__nv_bfloat162*>(&ep.zl[(size_t)m * Hh + n]) = lv;
  } else if (EPI == 3) {
    size_t idx = (size_t)m * LH + ep.coff + n;
    uchar2 f2 = *reinterpret_cast<const uchar2*>(&ep.F[idx]);
    float f0 = f2.x ? 1.f : NEG_SLOPE;
    float f1 = f2.y ? 1.f : NEG_SLOPE;
    float ga0 = d0 * f0, ga1 = d1 * f1;
    bf16 gh0, gl0, gh1, gl1;
    bsplit(ga0, gh0, gl0);
    bsplit(ga1, gh1, gl1);
    __nv_bfloat162 v;
    v.x = gh0; v.y = gh1;
    *reinterpret_cast<__nv_bfloat162*>(&ep.zh[(size_t)m * Hh + n]) = v;
    v.x = gl0; v.y = gl1;
    *reinterpret_cast<__nv_bfloat162*>(&ep.zl[(size_t)m * Hh + n]) = v;
  } else {  // EPI == 4
    atomicAdd(&ep.gx[(size_t)m * Dd + n], d0 * ep.tscale);
    atomicAdd(&ep.gx[(size_t)m * Dd + n + 1], d1 * ep.tscale);
  }
}

// ---------------- chain GEMM (bf16, 3 products) ------------------------------
template <int EPI>
__global__ __launch_bounds__(256, 2) void mma_gemm(
    const bf16* __restrict__ Ah, const bf16* __restrict__ Al,
    const bf16* __restrict__ Bh, const bf16* __restrict__ Bl, int Kc, int lda,
    int ldb, EpiP ep) {
  extern __shared__ char smc[];
  const uint32_t sb = smem_u32(smc);
  const int tid = threadIdx.x, lane = tid & 31, wid = tid >> 5;
  const int m0 = blockIdx.y * 128, n0 = blockIdx.x * 128;
  const int wm = (wid & 3) * 32, wn = (wid >> 2) * 64;
  constexpr uint32_t PL = 10240;
  constexpr uint32_t STG = 40960;

  const int lr = tid >> 1;
  const int lc = (tid & 1) * 2;

  const bf16* pA0 = Ah + (size_t)(m0 + lr) * lda + lc * 8;
  const bf16* pA1 = Al + (size_t)(m0 + lr) * lda + lc * 8;
  const bf16* pB0 = Bh + (size_t)(n0 + lr) * ldb + lc * 8;
  const bf16* pB1 = Bl + (size_t)(n0 + lr) * ldb + lc * 8;

  auto stage_load = [&](int s, int k0) {
    uint32_t base = sb + (uint32_t)s * STG + (uint32_t)lr * 80 + lc * 16;
    cpa16(base, pA0 + k0);
    cpa16(base + 16, pA0 + k0 + 8);
    cpa16(base + PL, pA1 + k0);
    cpa16(base + PL + 16, pA1 + k0 + 8);
    cpa16(base + 2 * PL, pB0 + k0);
    cpa16(base + 2 * PL + 16, pB0 + k0 + 8);
    cpa16(base + 3 * PL, pB1 + k0);
    cpa16(base + 3 * PL + 16, pB1 + k0 + 8);
    cpa_commit();
  };

  float acc[2][8][4];
#pragma unroll
  for (int i = 0; i < 2; i++)
#pragma unroll
    for (int j = 0; j < 8; j++)
#pragma unroll
      for (int q = 0; q < 4; q++) acc[i][j][q] = 0.f;

  const int nk = Kc / 32;
  stage_load(0, 0);
  cpa_wait0();
  __syncthreads();

  const int g3 = lane >> 3, r8 = lane & 7;

  for (int kb = 0; kb < nk; ++kb) {
    const int s = kb & 1;
    if (kb + 1 < nk) stage_load(s ^ 1, (kb + 1) * 32);
    const uint32_t ab = sb + (uint32_t)s * STG;
#pragma unroll
    for (int k16 = 0; k16 < 32; k16 += 16) {
      uint32_t Ahf[2][4], Alf[2][4], Bhf[8][2], Blf[8][2];
#pragma unroll
      for (int mi = 0; mi < 2; mi++) {
        uint32_t row = wm + mi * 16 + (g3 & 1) * 8 + r8;
        uint32_t col = k16 + (g3 >> 1) * 8;
        uint32_t ad = ab + row * 80 + col * 2;
        ldsm4(ad, Ahf[mi]);
        ldsm4(ad + PL, Alf[mi]);
      }
#pragma unroll
      for (int pi = 0; pi < 4; pi++) {
        uint32_t row = wn + (2 * pi + (g3 >> 1)) * 8 + r8;
        uint32_t col = k16 + (g3 & 1) * 8;
        uint32_t ad = ab + 2 * PL + row * 80 + col * 2;
        uint32_t t[4];
        ldsm4(ad, t);
        Bhf[2 * pi][0] = t[0];
        Bhf[2 * pi][1] = t[1];
        Bhf[2 * pi + 1][0] = t[2];
        Bhf[2 * pi + 1][1] = t[3];
        ldsm4(ad + PL, t);
        Blf[2 * pi][0] = t[0];
        Blf[2 * pi][1] = t[1];
        Blf[2 * pi + 1][0] = t[2];
        Blf[2 * pi + 1][1] = t[3];
      }
#pragma unroll
      for (int mi = 0; mi < 2; mi++)
#pragma unroll
        for (int ni = 0; ni < 8; ni++) {
          mma_bf16(acc[mi][ni], Ahf[mi], Bhf[ni]);
          mma_bf16(acc[mi][ni], Ahf[mi], Blf[ni]);
          mma_bf16(acc[mi][ni], Alf[mi], Bhf[ni]);
        }
    }
    cpa_wait0();
    __syncthreads();
  }

  float* cs = reinterpret_cast<float*>(smc);
  const int g = lane >> 2, t4 = lane & 3;
#pragma unroll
  for (int mi = 0; mi < 2; mi++)
#pragma unroll
    for (int ni = 0; ni < 8; ni++) {
      int r = wm + mi * 16 + g;
      int c = wn + ni * 8 + t4 * 2;
      *reinterpret_cast<float2*>(&cs[r * 132 + c]) =
          make_float2(acc[mi][ni][0], acc[mi][ni][1]);
      *reinterpret_cast<float2*>(&cs[(r + 8) * 132 + c]) =
          make_float2(acc[mi][ni][2], acc[mi][ni][3]);
    }
  __syncthreads();

#pragma unroll 4
  for (int rr = 0; rr < 16; ++rr) {
    int row = wid * 16 + rr;
    int m = m0 + row;
#pragma unroll
    for (int i = 0; i < 2; ++i) {
      int c = 2 * lane + 64 * i;
      float d0 = cs[row * 132 + c];
      float d1 = cs[row * 132 + c + 1];
      epi_pair<EPI>(m, n0 + c, d0, d1, ep);
    }
  }
}

// ---------------- tail GEMM (fp16, 2 products) -------------------------------
__global__ __launch_bounds__(256, 2) void tail_gemm(
    const f16* __restrict__ Ah, const f16* __restrict__ Al,
    const f16* __restrict__ Bm, int Kc, int lda, int ldb, EpiP ep) {
  extern __shared__ char smc[];
  const uint32_t sb = smem_u32(smc);
  const int tid = threadIdx.x, lane = tid & 31, wid = tid >> 5;
  const int m0 = blockIdx.y * 128, n0 = blockIdx.x * 64;
  const int wm = (wid & 3) * 32, wn = (wid >> 2) * 32;
  const int kstart = blockIdx.z * Kc;
  constexpr uint32_t PA = 10240;
  constexpr uint32_t PB = 5120;
  constexpr uint32_t STG = 2 * PA + PB;  // 25600

  const int lr = tid >> 1;
  const int lc = (tid & 1) * 2;
  const f16* pA0 = Ah + (size_t)(m0 + lr) * lda + lc * 8;
  const f16* pA1 = Al + (size_t)(m0 + lr) * lda + lc * 8;
  const int br = (tid & 127) >> 1, bcp = (tid & 1) * 2;
  const f16* pB = Bm + (size_t)(n0 + br) * ldb + bcp * 8;
  const uint32_t bOff = 2 * PA + (uint32_t)br * 80 + bcp * 16;

  auto stage_load = [&](int s, int k0) {
    uint32_t base = sb + (uint32_t)s * STG;
    uint32_t aA = base + (uint32_t)lr * 80 + lc * 16;
    cpa16(aA, pA0 + k0);
    cpa16(aA + 16, pA0 + k0 + 8);
    cpa16(aA + PA, pA1 + k0);
    cpa16(aA + PA + 16, pA1 + k0 + 8);
    if (tid < 128) {
      uint32_t aB = base + bOff;
      cpa16(aB, pB + k0);
      cpa16(aB + 16, pB + k0 + 8);
    }
    cpa_commit();
  };

  float acc[2][4][4];
#pragma unroll
  for (int i = 0; i < 2; i++)
#pragma unroll
    for (int j = 0; j < 4; j++)
#pragma unroll
      for (int q = 0; q < 4; q++) acc[i][j][q] = 0.f;

  const int nk = Kc / 32;
  stage_load(0, kstart);
  cpa_wait0();
  __syncthreads();

  const int g3 = lane >> 3, r8 = lane & 7;

  for (int kb = 0; kb < nk; ++kb) {
    const int s = kb & 1;
    if (kb + 1 < nk) stage_load(s ^ 1, kstart + (kb + 1) * 32);
    const uint32_t ab = sb + (uint32_t)s * STG;
#pragma unroll
    for (int k16 = 0; k16 < 32; k16 += 16) {
      uint32_t Ahf[2][4], Alf[2][4], Bf[4][2];
#pragma unroll
      for (int mi = 0; mi < 2; mi++) {
        uint32_t row = wm + mi * 16 + (g3 & 1) * 8 + r8;
        uint32_t col = k16 + (g3 >> 1) * 8;
        uint32_t ad = ab + row * 80 + col * 2;
        ldsm4(ad, Ahf[mi]);
        ldsm4(ad + PA, Alf[mi]);
      }
#pragma unroll
      for (int pi = 0; pi < 2; pi++) {
        uint32_t row = wn + (2 * pi + (g3 >> 1)) * 8 + r8;
        uint32_t col = k16 + (g3 & 1) * 8;
        uint32_t ad = ab + 2 * PA + row * 80 + col * 2;
        uint32_t t[4];
        ldsm4(ad, t);
        Bf[2 * pi][0] = t[0];
        Bf[2 * pi][1] = t[1];
        Bf[2 * pi + 1][0] = t[2];
        Bf[2 * pi + 1][1] = t[3];
      }
#pragma unroll
      for (int mi = 0; mi < 2; mi++)
#pragma unroll
        for (int ni = 0; ni < 4; ni++)
          mma_f16(acc[mi][ni], Ahf[mi], Bf[ni]);
#pragma unroll
      for (int mi = 0; mi < 2; mi++)
#pragma unroll
        for (int ni = 0; ni < 4; ni++)
          mma_f16(acc[mi][ni], Alf[mi], Bf[ni]);
    }
    cpa_wait0();
    __syncthreads();
  }

  float* cs = reinterpret_cast<float*>(smc);
  const int g = lane >> 2, t4 = lane & 3;
#pragma unroll
  for (int mi = 0; mi < 2; mi++)
#pragma unroll
    for (int ni = 0; ni < 4; ni++) {
      int r = wm + mi * 16 + g;
      int c = wn + ni * 8 + t4 * 2;
      *reinterpret_cast<float2*>(&cs[r * 68 + c]) =
          make_float2(acc[mi][ni][0], acc[mi][ni][1]);
      *reinterpret_cast<float2*>(&cs[(r + 8) * 68 + c]) =
          make_float2(acc[mi][ni][2], acc[mi][ni][3]);
    }
  __syncthreads();

#pragma unroll 4
  for (int rr = 0; rr < 16; ++rr) {
    int row = wid * 16 + rr;
    int m = m0 + row;
    int c = 2 * lane;
    float d0 = cs[row * 68 + c];
    float d1 = cs[row * 68 + c + 1];
    epi_pair<4>(m, n0 + c, d0, d1, ep);
  }
}

// ---------------- fused head GEMM slice (bf16, dual accumulators) ------------
__global__ __launch_bounds__(256, 2) void head_gemm(
    const bf16* __restrict__ Axh, const bf16* __restrict__ Axl,
    const bf16* __restrict__ Wqh, const bf16* __restrict__ Wql,
    const bf16* __restrict__ Wlh, const bf16* __restrict__ Wll,
    const float* __restrict__ blv, float* __restrict__ U,
    float* __restrict__ P, unsigned char* __restrict__ F,
    bf16* __restrict__ zh, bf16* __restrict__ zl, int coff) {
  extern __shared__ char smc[];
  const uint32_t sb = smem_u32(smc);
  const int tid = threadIdx.x, lane = tid & 31, wid = tid >> 5;
  const int m0 = blockIdx.y * 128, n0 = blockIdx.x * 64;
  const int wm = (wid & 3) * 32, wn = (wid >> 2) * 32;
  constexpr uint32_t PA = 10240;
  constexpr uint32_t PB = 5120;
  constexpr uint32_t STG = 2 * PA + 4 * PB;  // 40960

  const int lr = tid >> 1, lc = (tid & 1) * 2;
  const bf16* pA0 = Axh + (size_t)(m0 + lr) * Dd + lc * 8;
  const bf16* pA1 = Axl + (size_t)(m0 + lr) * Dd + lc * 8;
  const int br = (tid & 127) >> 1, bcp = (tid & 1) * 2;
  const int bw = tid >> 7;
  const bf16* pB0 = (bw ? Wlh : Wqh) + (size_t)(n0 + br) * Dd + bcp * 8;
  const bf16* pB1 = (bw ? Wll : Wql) + (size_t)(n0 + br) * Dd + bcp * 8;
  const uint32_t bOff = 2 * PA + (uint32_t)bw * 2 * PB + (uint32_t)br * 80 + bcp * 16;

  auto stage_load = [&](int s, int k0) {
    uint32_t base = sb + (uint32_t)s * STG;
    uint32_t aA = base + (uint32_t)lr * 80 + lc * 16;
    cpa16(aA, pA0 + k0);
    cpa16(aA + 16, pA0 + k0 + 8);
    cpa16(aA + PA, pA1 + k0);
    cpa16(aA + PA + 16, pA1 + k0 + 8);
    uint32_t aB = base + bOff;
    cpa16(aB, pB0 + k0);
    cpa16(aB + 16, pB0 + k0 + 8);
    cpa16(aB + PB, pB1 + k0);
    cpa16(aB + PB + 16, pB1 + k0 + 8);
    cpa_commit();
  };

  float accq[2][4][4], accl[2][4][4];
#pragma unroll
  for (int i = 0; i < 2; i++)
#pragma unroll
    for (int j = 0; j < 4; j++)
#pragma unroll
      for (int q = 0; q < 4; q++) accq[i][j][q] = accl[i][j][q] = 0.f;

  constexpr int nk = Dd / 32;
  stage_load(0, 0);
  cpa_wait0();
  __syncthreads();

  const int g3 = lane >> 3, r8 = lane & 7;

  for (int kb = 0; kb < nk; ++kb) {
    const int s = kb & 1;
    if (kb + 1 < nk) stage_load(s ^ 1, (kb + 1) * 32);
    const uint32_t ab = sb + (uint32_t)s * STG;
#pragma unroll
    for (int k16 = 0; k16 < 32; k16 += 16) {
      uint32_t Ahf[2][4], Alf[2][4];
      uint32_t Bqh_[4][2], Bql_[4][2], Blh_[4][2], Bll_[4][2];
#pragma unroll
      for (int mi = 0; mi < 2; mi++) {
        uint32_t row = wm + mi * 16 + (g3 & 1) * 8 + r8;
        uint32_t col = k16 + (g3 >> 1) * 8;
        uint32_t ad = ab + row * 80 + col * 2;
        ldsm4(ad, Ahf[mi]);
        ldsm4(ad + PA, Alf[mi]);
      }
#pragma unroll
      for (int pi = 0; pi < 2; pi++) {
        uint32_t row = wn + (2 * pi + (g3 >> 1)) * 8 + r8;
        uint32_t col = k16 + (g3 & 1) * 8;
        uint32_t adq = ab + 2 * PA + row * 80 + col * 2;
        uint32_t t[4];
        ldsm4(adq, t);
        Bqh_[2 * pi][0] = t[0]; Bqh_[2 * pi][1] = t[1];
        Bqh_[2 * pi + 1][0] = t[2]; Bqh_[2 * pi + 1][1] = t[3];
        ldsm4(adq + PB, t);
        Bql_[2 * pi][0] = t[0]; Bql_[2 * pi][1] = t[1];
        Bql_[2 * pi + 1][0] = t[2]; Bql_[2 * pi + 1][1] = t[3];
        ldsm4(adq + 2 * PB, t);
        Blh_[2 * pi][0] = t[0]; Blh_[2 * pi][1] = t[1];
        Blh_[2 * pi + 1][0] = t[2]; Blh_[2 * pi + 1][1] = t[3];
        ldsm4(adq + 3 * PB, t);
        Bll_[2 * pi][0] = t[0]; Bll_[2 * pi][1] = t[1];
        Bll_[2 * pi + 1][0] = t[2]; Bll_[2 * pi + 1][1] = t[3];
      }
#pragma unroll
      for (int mi = 0; mi < 2; mi++)
#pragma unroll
        for (int ni = 0; ni < 4; ni++) {
          mma_bf16(accq[mi][ni], Ahf[mi], Bqh_[ni]);
          mma_bf16(accq[mi][ni], Ahf[mi], Bql_[ni]);
          mma_bf16(accq[mi][ni], Alf[mi], Bqh_[ni]);
          mma_bf16(accl[mi][ni], Ahf[mi], Blh_[ni]);
          mma_bf16(accl[mi][ni], Ahf[mi], Bll_[ni]);
          mma_bf16(accl[mi][ni], Alf[mi], Blh_[ni]);
        }
    }
    cpa_wait0();
    __syncthreads();
  }

  float* cs = reinterpret_cast<float*>(smc);
  const int g = lane >> 2, t4 = lane & 3;
#pragma unroll
  for (int mi = 0; mi < 2; mi++)
#pragma unroll
    for (int ni = 0; ni < 4; ni++) {
      int r = wm + mi * 16 + g;
      int c = wn + ni * 8 + t4 * 2;
      *reinterpret_cast<float2*>(&cs[r * 132 + c]) =
          make_float2(accq[mi][ni][0], accq[mi][ni][1]);
      *reinterpret_cast<float2*>(&cs[(r + 8) * 132 + c]) =
          make_float2(accq[mi][ni][2], accq[mi][ni][3]);
      *reinterpret_cast<float2*>(&cs[r * 132 + 64 + c]) =
          make_float2(accl[mi][ni][0], accl[mi][ni][1]);
      *reinterpret_cast<float2*>(&cs[(r + 8) * 132 + 64 + c]) =
          make_float2(accl[mi][ni][2], accl[mi][ni][3]);
    }
  __syncthreads();

  const bool inZ = (coff == 0);
#pragma unroll 4
  for (int rr = 0; rr < 16; ++rr) {
    int row = wid * 16 + rr;
    int m = m0 + row;
    int c = 2 * lane;
    int n = coff + n0 + c;
    float u0 = cs[row * 132 + c], u1 = cs[row * 132 + c + 1];
    float v0 = cs[row * 132 + 64 + c], v1 = cs[row * 132 + 64 + c + 1];
    size_t idx = (size_t)m * LH + n;
    *reinterpret_cast<float2*>(&U[idx]) = make_float2(u0, u1);
    float2 b2 = *reinterpret_cast<const float2*>(&blv[n]);
    float p0 = u0 * u0 + v0 + b2.x;
    float p1 = u1 * u1 + v1 + b2.y;
    *reinterpret_cast<float2*>(&P[idx]) = make_float2(p0, p1);
    if (inZ) {
      bool s0 = (p0 >= 0.f), s1 = (p1 >= 0.f);
      uchar2 f2;
      f2.x = s0 ? 1 : 0;
      f2.y = s1 ? 1 : 0;
      *reinterpret_cast<uchar2*>(&F[idx]) = f2;
      float z0 = s0 ? p0 : NEG_SLOPE * p0;
      float z1 = s1 ? p1 : NEG_SLOPE * p1;
      bf16 h0, l0, h1, l1;
      bsplit(z0, h0, l0);
      bsplit(z1, h1, l1);
      __nv_bfloat162 hv, lv;
      hv.x = h0; hv.y = h1;
      lv.x = l0; lv.y = l1;
      *reinterpret_cast<__nv_bfloat162*>(&zh[(size_t)m * Hh + n0 + c]) = hv;
      *reinterpret_cast<__nv_bfloat162*>(&zl[(size_t)m * Hh + n0 + c]) = lv;
    }
  }
}

// ---------------- prep / elementwise ----------------------------------------
__global__ void k_split3(const float* __restrict__ x, const float* __restrict__ Wq,
                         const float* __restrict__ Wl, bf16* __restrict__ xh,
                         bf16* __restrict__ xl, bf16* __restrict__ qh,
                         bf16* __restrict__ ql, bf16* __restrict__ lh,
                         bf16* __restrict__ ll) {
  int i = blockIdx.x * 256 + threadIdx.x;
  const int n1 = Bsz * Dd, n2 = LH * Dd;
  bf16 h, l;
  if (i < n1) {
    bsplit(x[i], h, l);
    xh[i] = h; xl[i] = l;
  } else if (i < n1 + n2) {
    int j = i - n1;
    bsplit(Wq[j], h, l);
    qh[j] = h; ql[j] = l;
  } else if (i < n1 + 2 * n2) {
    int j = i - n1 - n2;
    bsplit(Wl[j], h, l);
    lh[j] = h; ll[j] = l;
  }
}

__global__ void k_split(const float* __restrict__ in, bf16* __restrict__ h,
                        bf16* __restrict__ l, int n) {
  int i = blockIdx.x * 256 + threadIdx.x;
  if (i < n) {
    bf16 hh, ll;
    bsplit(in[i], hh, ll);
    h[i] = hh;
    l[i] = ll;
  }
}

__global__ void k_wzT(const float* __restrict__ Wz, bf16* __restrict__ h,
                      bf16* __restrict__ l) {
  int i = blockIdx.x * 256 + threadIdx.x;
  int lay = i / (Hh * Hh);
  int r = i % (Hh * Hh);
  int o = r / Hh, ii = r % Hh;
  size_t dst = (size_t)lay * Hh * Hh + (size_t)ii * Hh + o;
  bf16 hh, ll;
  bsplit(Wz[i], hh, ll);
  h[dst] = hh;
  l[dst] = ll;
}

__global__ void k_bcat16(const float* __restrict__ Wq, const float* __restrict__ Wl,
                         f16* __restrict__ o) {
  int i = blockIdx.x * 256 + threadIdx.x;
  int lay = i / (Dd * 1024);
  int r = i % (Dd * 1024);
  int d = r / 1024, k = r % 1024;
  float v = (k < Hh) ? Wq[((size_t)lay * Hh + k) * Dd + d]
                     : Wl[((size_t)lay * Hh + (k - Hh)) * Dd + d];
  o[i] = __float2half_rn(v);
}

__global__ void k_dotzero(const float* __restrict__ x, const float* __restrict__ wq,
                          float* __restrict__ S, float* __restrict__ gx) {
  int gid = blockIdx.x * 256 + threadIdx.x;
  if (gid < Bsz * Dd) gx[gid] = 0.f;
  int w = gid / 32, lane = gid % 32;
  if (w < Bsz) {
    float s = 0.f;
    for (int d = lane; d < Dd; d += 32) s += x[(size_t)w * Dd + d] * wq[d];
#pragma unroll
    for (int o = 16; o; o >>= 1) s += __shfl_xor_sync(0xFFFFFFFFu, s, o);
    if (lane == 0) S[w] = s;
  }
}

__global__ void k_bwinit(const unsigned char* __restrict__ F,
                         const float* __restrict__ U,
                         const float* __restrict__ wz_out,
                         bf16* __restrict__ zh, bf16* __restrict__ zl,
                         f16* __restrict__ ach, f16* __restrict__ acl) {
  int i = blockIdx.x * 256 + threadIdx.x;
  int m = i / Hh, h = i % Hh;
  size_t idx = (size_t)m * LH + (size_t)(Ll - 1) * Hh + h;
  float f = F[idx] ? 1.f : NEG_SLOPE;
  float ga = wz_out[h] * f;
  bf16 gh, gl;
  bsplit(ga, gh, gl);
  zh[i] = gh;
  zl[i] = gl;
  float g1 = 2.f * ga * U[idx];  // ascale = 1 at l = 9
  f16 h1, l1;
  size_t ai = (size_t)m * 1024 + h;
  hsplit(g1, h1, l1);
  ach[ai] = h1;
  acl[ai] = l1;
  hsplit(ga, h1, l1);
  ach[ai + Hh] = h1;
  acl[ai + Hh] = l1;
}

// Build fp16 Acat for layer l from bf16 ga pair + U, scaled by ascale.
__global__ void k_acat(const bf16* __restrict__ gah, const bf16* __restrict__ gal,
                       const float* __restrict__ U, f16* __restrict__ ach,
                       f16* __restrict__ acl, int coff, float ascale) {
  int i = blockIdx.x * 256 + threadIdx.x;  // Bsz*Hh
  int m = i / Hh, h = i % Hh;
  float ga = __bfloat162float(gah[i]) + __bfloat162float(gal[i]);
  float as = ga * ascale;
  float g1 = 2.f * as * U[(size_t)m * LH + coff + h];
  f16 th, tl;
  size_t ai = (size_t)m * 1024 + h;
  hsplit(g1, th, tl);
  ach[ai] = th;
  acl[ai] = tl;
  hsplit(as, th, tl);
  ach[ai + Hh] = th;
  acl[ai + Hh] = tl;
}

__global__ void k_final(const float* __restrict__ gx, const float* __restrict__ S,
                        const float* __restrict__ wq, const float* __restrict__ wl,
                        const float* __restrict__ x, float* __restrict__ out) {
  int i = blockIdx.x * 256 + threadIdx.x;
  int m = i >> 7, n = i & 127;
  out[i] = 0.5f * (gx[i] + 2.f * S[m] * wq[n] + wl[n]) + 0.5f * x[i];
}

// ---------------- host driver ------------------------------------------------
constexpr uint32_t SMEM_SZ = 81920;
constexpr uint32_t SMEM_TAIL = 51200;

extern "C" void kernel_launch(void* const* d_in, const int* in_sizes, int n_in,
                              void* d_out, int out_size) {
  const float* x = (const float*)d_in[0];
  const float* Wq = (const float*)d_in[1];
  const float* Wl = (const float*)d_in[2];
  const float* bl = (const float*)d_in[3];
  const float* Wz = (const float*)d_in[4];
  const float* wz_out = (const float*)d_in[5];
  const float* wq_out = (const float*)d_in[6];
  const float* wl_out = (const float*)d_in[7];
  float* out = (float*)d_out;

  bf16 *xh, *xl, *Wqh, *Wql, *Wlh, *Wll, *Wzh, *Wzl, *WzTh, *WzTl;
  bf16 *zAh, *zAl, *zBh, *zBl;
  f16 *Bc16, *Ach[2], *Acl[2];
  float *U, *P, *gx, *S;
  unsigned char* F;
  cudaGetSymbolAddress((void**)&xh, g_xh);
  cudaGetSymbolAddress((void**)&xl, g_xl);
  cudaGetSymbolAddress((void**)&Wqh, g_Wqh);
  cudaGetSymbolAddress((void**)&Wql, g_Wql);
  cudaGetSymbolAddress((void**)&Wlh, g_Wlh);
  cudaGetSymbolAddress((void**)&Wll, g_Wll);
  cudaGetSymbolAddress((void**)&Wzh, g_Wzh);
  cudaGetSymbolAddress((void**)&Wzl, g_Wzl);
  cudaGetSymbolAddress((void**)&WzTh, g_WzTh);
  cudaGetSymbolAddress((void**)&WzTl, g_WzTl);
  cudaGetSymbolAddress((void**)&Bc16, g_Bc16);
  cudaGetSymbolAddress((void**)&U, g_U);
  cudaGetSymbolAddress((void**)&P, g_P);
  cudaGetSymbolAddress((void**)&F, g_F);
  cudaGetSymbolAddress((void**)&zAh, g_zAh);
  cudaGetSymbolAddress((void**)&zAl, g_zAl);
  cudaGetSymbolAddress((void**)&zBh, g_zBh);
  cudaGetSymbolAddress((void**)&zBl, g_zBl);
  cudaGetSymbolAddress((void**)&Ach[0], g_Ach0);
  cudaGetSymbolAddress((void**)&Acl[0], g_Acl0);
  cudaGetSymbolAddress((void**)&Ach[1], g_Ach1);
  cudaGetSymbolAddress((void**)&Acl[1], g_Acl1);
  cudaGetSymbolAddress((void**)&gx, g_gx);
  cudaGetSymbolAddress((void**)&S, g_S);

  static bool s_init = false;
  static cudaStream_t st1, st2;
  static cudaEvent_t evStart, evSplit, evWz, evWzT, evHd[10], evBw[10],
      evAcat[10], evTail[10];
  if (!s_init) {
    cudaStreamCreateWithFlags(&st1, cudaStreamNonBlocking);
    cudaStreamCreateWithFlags(&st2, cudaStreamNonBlocking);
    cudaEventCreateWithFlags(&evStart, cudaEventDisableTiming);
    cudaEventCreateWithFlags(&evSplit, cudaEventDisableTiming);
    cudaEventCreateWithFlags(&evWz, cudaEventDisableTiming);
    cudaEventCreateWithFlags(&evWzT, cudaEventDisableTiming);
    for (int i = 0; i < 10; i++) {
      cudaEventCreateWithFlags(&evHd[i], cudaEventDisableTiming);
      cudaEventCreateWithFlags(&evBw[i], cudaEventDisableTiming);
      cudaEventCreateWithFlags(&evAcat[i], cudaEventDisableTiming);
      cudaEventCreateWithFlags(&evTail[i], cudaEventDisableTiming);
    }
    cudaFuncSetAttribute(mma_gemm<2>, cudaFuncAttributeMaxDynamicSharedMemorySize, SMEM_SZ);
    cudaFuncSetAttribute(mma_gemm<3>, cudaFuncAttributeMaxDynamicSharedMemorySize, SMEM_SZ);
    cudaFuncSetAttribute(tail_gemm, cudaFuncAttributeMaxDynamicSharedMemorySize, SMEM_TAIL);
    cudaFuncSetAttribute(head_gemm, cudaFuncAttributeMaxDynamicSharedMemorySize, SMEM_SZ);
    s_init = true;
  }

  // ---- fork side streams ----
  cudaEventRecord(evStart, 0);
  cudaStreamWaitEvent(st1, evStart, 0);
  cudaStreamWaitEvent(st2, evStart, 0);

  // s0: input/weight splits
  {
    int tot = Bsz * Dd + 2 * LH * Dd;
    k_split3<<<(tot + 255) / 256, 256>>>(x, Wq, Wl, xh, xl, Wqh, Wql, Wlh, Wll);
  }
  cudaEventRecord(evSplit, 0);

  // st2: Wz split, WzT split, tail weights, dot+gx zero
  k_split<<<((Ll - 1) * Hh * Hh + 255) / 256, 256, 0, st2>>>(
      Wz, Wzh, Wzl, (Ll - 1) * Hh * Hh);
  cudaEventRecord(evWz, st2);
  k_wzT<<<((Ll - 1) * Hh * Hh + 255) / 256, 256, 0, st2>>>(Wz, WzTh, WzTl);
  cudaEventRecord(evWzT, st2);
  k_bcat16<<<(Ll * Dd * 1024 + 255) / 256, 256, 0, st2>>>(Wq, Wl, Bc16);
  k_dotzero<<<(Bsz * Dd + 255) / 256, 256, 0, st2>>>(x, wq_out, S, gx);

  // st1: per-layer head slices
  cudaStreamWaitEvent(st1, evSplit, 0);
  for (int l = 0; l < Ll; ++l) {
    head_gemm<<<dim3(Hh / 64, Bsz / 128), 256, SMEM_SZ, st1>>>(
        xh, xl, Wqh + (size_t)l * Hh * Dd, Wql + (size_t)l * Hh * Dd,
        Wlh + (size_t)l * Hh * Dd, Wll + (size_t)l * Hh * Dd, bl, U, P, F,
        zAh, zAl, l * Hh);
    cudaEventRecord(evHd[l], st1);
  }

  // s0: forward chain; layer l waits on head slice l
  bf16* zh2[2] = {zAh, zBh};
  bf16* zl2[2] = {zAl, zBl};
  cudaStreamWaitEvent(0, evWz, 0);
  for (int l = 1; l < Ll; ++l) {
    cudaStreamWaitEvent(0, evHd[l], 0);
    EpiP ep = {};
    ep.Pc = P;
    ep.F = F;
    ep.coff = l * Hh;
    ep.zh = zh2[l & 1];
    ep.zl = zl2[l & 1];
    mma_gemm<2><<<dim3(Hh / 128, Bsz / 128, 1), 256, SMEM_SZ>>>(
        zh2[(l - 1) & 1], zl2[(l - 1) & 1], Wzh + (size_t)(l - 1) * Hh * Hh,
        Wzl + (size_t)(l - 1) * Hh * Hh, Hh, Hh, Hh, ep);
  }

  // ---- backward init (layer 9): ga9 -> zh2[0]; fp16 Acat buf[1] direct ----
  k_bwinit<<<(Bsz * Hh + 255) / 256, 256>>>(F, U, wz_out, zh2[0], zl2[0],
                                            Ach[1], Acl[1]);
  cudaEventRecord(evBw[9], 0);

  cudaStreamWaitEvent(st2, evBw[9], 0);
  {
    EpiP ep = {};
    ep.gx = gx;
    ep.tscale = 1.f;
    tail_gemm<<<dim3(Dd / 64, Bsz / 128, 2), 256, SMEM_TAIL, st2>>>(
        Ach[1], Acl[1], Bc16 + (size_t)(Ll - 1) * Dd * 1024, 512, 1024, 1024,
        ep);
    cudaEventRecord(evTail[9], st2);
  }

  // ---- backward chain on s0; k_acat + tails on st2 ----
  cudaStreamWaitEvent(0, evWzT, 0);
  int cur = 0;  // zh2[cur] holds ga_{l+1}
  for (int l = Ll - 2; l >= 0; --l) {
    // z-buffer reuse guard: layer l writes buffer holding ga_{l+2};
    // k_acat(l+2) must have finished reading it.
    if (l + 2 <= Ll - 2) cudaStreamWaitEvent(0, evAcat[l + 2], 0);
    {
      EpiP ep = {};
      ep.F = F;
      ep.coff = l * Hh;
      ep.zh = zh2[cur ^ 1];
      ep.zl = zl2[cur ^ 1];
      mma_gemm<3><<<dim3(Hh / 128, Bsz / 128, 1), 256, SMEM_SZ>>>(
          zh2[cur], zl2[cur], WzTh + (size_t)l * Hh * Hh,
          WzTl + (size_t)l * Hh * Hh, Hh, Hh, Hh, ep);
    }
    cudaEventRecord(evBw[l], 0);
    // st2: build fp16 Acat for layer l, then tail l
    cudaStreamWaitEvent(st2, evBw[l], 0);
    {
      float as = 1.f, ts = 1.f;
      for (int t = 0; t < 9 - l; ++t) { as *= 0.0625f; ts *= 16.f; }
      k_acat<<<(Bsz * Hh + 255) / 256, 256, 0, st2>>>(
          zh2[cur ^ 1], zl2[cur ^ 1], U, Ach[l & 1], Acl[l & 1], l * Hh, as);
      cudaEventRecord(evAcat[l], st2);
      EpiP ep = {};
      ep.gx = gx;
      ep.tscale = ts;
      tail_gemm<<<dim3(Dd / 64, Bsz / 128, 2), 256, SMEM_TAIL, st2>>>(
          Ach[l & 1], Acl[l & 1], Bc16 + (size_t)l * Dd * 1024, 512, 1024,
          1024, ep);
      cudaEventRecord(evTail[l], st2);
    }
    cur ^= 1;
  }

  // ---- join and final combine ----
  cudaStreamWaitEvent(0, evTail[0], 0);
  k_final<<<(Bsz * Dd + 255) / 256, 256>>>(gx, S, wq_out, wl_out, x, out);
}

// round 14
// speedup vs baseline: 1.5168x; 1.0041x over previous
#include <cuda_runtime.h>
#include <cuda_bf16.h>
#include <cuda_fp16.h>
#include <cstdint>

// ===========================================================================
// ICNN forward + input-gradient via mma.sync (bf16 3-product chain/head,
// fp16 2-product tails). Round 14: end-game deserialization — acat0+tail0
// run on stream 0 (no event hops) with tail0 K-split x4 on the otherwise
// idle chip; k_final needs only st2's last event. Core GEMMs identical R13.
// ===========================================================================

typedef __nv_bfloat16 bf16;
typedef __half f16;

#define NEG_SLOPE 0.2f
constexpr int Bsz = 8192;
constexpr int Dd  = 128;
constexpr int Hh  = 512;
constexpr int Ll  = 10;
constexpr int LH  = Ll * Hh;  // 5120

// ---------------- static device scratch ------------------------------------
__device__ bf16 g_xh[(size_t)Bsz * Dd], g_xl[(size_t)Bsz * Dd];
__device__ bf16 g_Wqh[(size_t)LH * Dd], g_Wql[(size_t)LH * Dd];
__device__ bf16 g_Wlh[(size_t)LH * Dd], g_Wll[(size_t)LH * Dd];
__device__ bf16 g_Wzh[(size_t)(Ll - 1) * Hh * Hh], g_Wzl[(size_t)(Ll - 1) * Hh * Hh];
__device__ bf16 g_WzTh[(size_t)(Ll - 1) * Hh * Hh], g_WzTl[(size_t)(Ll - 1) * Hh * Hh];
__device__ f16  g_Bc16[(size_t)Ll * Dd * 1024];
__device__ float g_U[(size_t)Bsz * LH];
__device__ float g_P[(size_t)Bsz * LH];
__device__ unsigned char g_F[(size_t)Bsz * LH];
__device__ bf16 g_zAh[(size_t)Bsz * Hh], g_zAl[(size_t)Bsz * Hh];
__device__ bf16 g_zBh[(size_t)Bsz * Hh], g_zBl[(size_t)Bsz * Hh];
__device__ f16 g_Ach0[(size_t)Bsz * 1024], g_Acl0[(size_t)Bsz * 1024];
__device__ f16 g_Ach1[(size_t)Bsz * 1024], g_Acl1[(size_t)Bsz * 1024];
__device__ float g_gx[(size_t)Bsz * Dd];
__device__ float g_S[Bsz];

// ---------------- helpers ---------------------------------------------------
__device__ __forceinline__ uint32_t smem_u32(const void* p) {
  uint32_t a;
  asm("{ .reg .u64 t; cvta.to.shared.u64 t, %1; cvt.u32.u64 %0, t; }"
      : "=r"(a) : "l"(p));
  return a;
}
__device__ __forceinline__ void cpa16(uint32_t s, const void* g) {
  asm volatile("cp.async.cg.shared.global [%0], [%1], 16;" ::"r"(s), "l"(g));
}
__device__ __forceinline__ void cpa_commit() {
  asm volatile("cp.async.commit_group;" ::: "memory");
}
__device__ __forceinline__ void cpa_wait0() {
  asm volatile("cp.async.wait_group 0;" ::: "memory");
}
__device__ __forceinline__ void ldsm4(uint32_t addr, uint32_t* r) {
  asm volatile("ldmatrix.sync.aligned.m8n8.x4.shared.b16 {%0,%1,%2,%3}, [%4];"
               : "=r"(r[0]), "=r"(r[1]), "=r"(r[2]), "=r"(r[3]) : "r"(addr));
}
__device__ __forceinline__ void mma_bf16(float* c, const uint32_t* a,
                                         const uint32_t* b) {
  asm volatile(
      "mma.sync.aligned.m16n8k16.row.col.f32.bf16.bf16.f32 "
      "{%0,%1,%2,%3}, {%4,%5,%6,%7}, {%8,%9}, {%0,%1,%2,%3};"
      : "+f"(c[0]), "+f"(c[1]), "+f"(c[2]), "+f"(c[3])
      : "r"(a[0]), "r"(a[1]), "r"(a[2]), "r"(a[3]), "r"(b[0]), "r"(b[1]));
}
__device__ __forceinline__ void mma_f16(float* c, const uint32_t* a,
                                        const uint32_t* b) {
  asm volatile(
      "mma.sync.aligned.m16n8k16.row.col.f32.f16.f16.f32 "
      "{%0,%1,%2,%3}, {%4,%5,%6,%7}, {%8,%9}, {%0,%1,%2,%3};"
      : "+f"(c[0]), "+f"(c[1]), "+f"(c[2]), "+f"(c[3])
      : "r"(a[0]), "r"(a[1]), "r"(a[2]), "r"(a[3]), "r"(b[0]), "r"(b[1]));
}
__device__ __forceinline__ void bsplit(float v, bf16& h, bf16& l) {
  h = __float2bfloat16(v);
  l = __float2bfloat16(v - __bfloat162float(h));
}
__device__ __forceinline__ void hsplit(float v, f16& h, f16& l) {
  h = __float2half_rn(v);
  l = __float2half_rn(v - __half2float(h));
}

// ---------------- epilogue params -------------------------------------------
struct EpiP {
  const float* Pc;
  unsigned char* F;
  bf16* zh;
  bf16* zl;
  float* gx;
  int coff;
  float tscale;  // EPI4: gx accumulate scale = 16^(9-l)
};

// EPI: 2=fwd layer; 3=bwd layer (z only); 4=gx accum (tail)
template <int EPI>
__device__ __forceinline__ void epi_pair(int m, int n, float d0, float d1,
                                         const EpiP& ep) {
  if (EPI == 2) {
    size_t idx = (size_t)m * LH + ep.coff + n;
    float2 pc = *reinterpret_cast<const float2*>(&ep.Pc[idx]);
    float a0 = d0 + pc.x, a1 = d1 + pc.y;
    bool p0 = (a0 >= 0.f), p1 = (a1 >= 0.f);
    uchar2 f2;
    f2.x = p0 ? 1 : 0;
    f2.y = p1 ? 1 : 0;
    *reinterpret_cast<uchar2*>(&ep.F[idx]) = f2;
    float z0 = p0 ? a0 : NEG_SLOPE * a0;
    float z1 = p1 ? a1 : NEG_SLOPE * a1;
    bf16 h0, l0, h1, l1;
    bsplit(z0, h0, l0);
    bsplit(z1, h1, l1);
    __nv_bfloat162 hv, lv;
    hv.x = h0; hv.y = h1;
    lv.x = l0; lv.y = l1;
    *reinterpret_cast<__nv_bfloat162*>(&ep.zh[(size_t)m * Hh + n]) = hv;
    *reinterpret_cast<__nv_bfloat162*>(&ep.zl[(size_t)m * Hh + n]) = lv;
  } else if (EPI == 3) {
    size_t idx = (size_t)m * LH + ep.coff + n;
    uchar2 f2 = *reinterpret_cast<const uchar2*>(&ep.F[idx]);
    float f0 = f2.x ? 1.f : NEG_SLOPE;
    float f1 = f2.y ? 1.f : NEG_SLOPE;
    float ga0 = d0 * f0, ga1 = d1 * f1;
    bf16 gh0, gl0, gh1, gl1;
    bsplit(ga0, gh0, gl0);
    bsplit(ga1, gh1, gl1);
    __nv_bfloat162 v;
    v.x = gh0; v.y = gh1;
    *reinterpret_cast<__nv_bfloat162*>(&ep.zh[(size_t)m * Hh + n]) = v;
    v.x = gl0; v.y = gl1;
    *reinterpret_cast<__nv_bfloat162*>(&ep.zl[(size_t)m * Hh + n]) = v;
  } else {  // EPI == 4
    atomicAdd(&ep.gx[(size_t)m * Dd + n], d0 * ep.tscale);
    atomicAdd(&ep.gx[(size_t)m * Dd + n + 1], d1 * ep.tscale);
  }
}

// ---------------- chain GEMM (bf16, 3 products) ------------------------------
template <int EPI>
__global__ __launch_bounds__(256, 2) void mma_gemm(
    const bf16* __restrict__ Ah, const bf16* __restrict__ Al,
    const bf16* __restrict__ Bh, const bf16* __restrict__ Bl, int Kc, int lda,
    int ldb, EpiP ep) {
  extern __shared__ char smc[];
  const uint32_t sb = smem_u32(smc);
  const int tid = threadIdx.x, lane = tid & 31, wid = tid >> 5;
  const int m0 = blockIdx.y * 128, n0 = blockIdx.x * 128;
  const int wm = (wid & 3) * 32, wn = (wid >> 2) * 64;
  constexpr uint32_t PL = 10240;
  constexpr uint32_t STG = 40960;

  const int lr = tid >> 1;
  const int lc = (tid & 1) * 2;

  const bf16* pA0 = Ah + (size_t)(m0 + lr) * lda + lc * 8;
  const bf16* pA1 = Al + (size_t)(m0 + lr) * lda + lc * 8;
  const bf16* pB0 = Bh + (size_t)(n0 + lr) * ldb + lc * 8;
  const bf16* pB1 = Bl + (size_t)(n0 + lr) * ldb + lc * 8;

  auto stage_load = [&](int s, int k0) {
    uint32_t base = sb + (uint32_t)s * STG + (uint32_t)lr * 80 + lc * 16;
    cpa16(base, pA0 + k0);
    cpa16(base + 16, pA0 + k0 + 8);
    cpa16(base + PL, pA1 + k0);
    cpa16(base + PL + 16, pA1 + k0 + 8);
    cpa16(base + 2 * PL, pB0 + k0);
    cpa16(base + 2 * PL + 16, pB0 + k0 + 8);
    cpa16(base + 3 * PL, pB1 + k0);
    cpa16(base + 3 * PL + 16, pB1 + k0 + 8);
    cpa_commit();
  };

  float acc[2][8][4];
#pragma unroll
  for (int i = 0; i < 2; i++)
#pragma unroll
    for (int j = 0; j < 8; j++)
#pragma unroll
      for (int q = 0; q < 4; q++) acc[i][j][q] = 0.f;

  const int nk = Kc / 32;
  stage_load(0, 0);
  cpa_wait0();
  __syncthreads();

  const int g3 = lane >> 3, r8 = lane & 7;

  for (int kb = 0; kb < nk; ++kb) {
    const int s = kb & 1;
    if (kb + 1 < nk) stage_load(s ^ 1, (kb + 1) * 32);
    const uint32_t ab = sb + (uint32_t)s * STG;
#pragma unroll
    for (int k16 = 0; k16 < 32; k16 += 16) {
      uint32_t Ahf[2][4], Alf[2][4], Bhf[8][2], Blf[8][2];
#pragma unroll
      for (int mi = 0; mi < 2; mi++) {
        uint32_t row = wm + mi * 16 + (g3 & 1) * 8 + r8;
        uint32_t col = k16 + (g3 >> 1) * 8;
        uint32_t ad = ab + row * 80 + col * 2;
        ldsm4(ad, Ahf[mi]);
        ldsm4(ad + PL, Alf[mi]);
      }
#pragma unroll
      for (int pi = 0; pi < 4; pi++) {
        uint32_t row = wn + (2 * pi + (g3 >> 1)) * 8 + r8;
        uint32_t col = k16 + (g3 & 1) * 8;
        uint32_t ad = ab + 2 * PL + row * 80 + col * 2;
        uint32_t t[4];
        ldsm4(ad, t);
        Bhf[2 * pi][0] = t[0];
        Bhf[2 * pi][1] = t[1];
        Bhf[2 * pi + 1][0] = t[2];
        Bhf[2 * pi + 1][1] = t[3];
        ldsm4(ad + PL, t);
        Blf[2 * pi][0] = t[0];
        Blf[2 * pi][1] = t[1];
        Blf[2 * pi + 1][0] = t[2];
        Blf[2 * pi + 1][1] = t[3];
      }
#pragma unroll
      for (int mi = 0; mi < 2; mi++)
#pragma unroll
        for (int ni = 0; ni < 8; ni++) {
          mma_bf16(acc[mi][ni], Ahf[mi], Bhf[ni]);
          mma_bf16(acc[mi][ni], Ahf[mi], Blf[ni]);
          mma_bf16(acc[mi][ni], Alf[mi], Bhf[ni]);
        }
    }
    cpa_wait0();
    __syncthreads();
  }

  float* cs = reinterpret_cast<float*>(smc);
  const int g = lane >> 2, t4 = lane & 3;
#pragma unroll
  for (int mi = 0; mi < 2; mi++)
#pragma unroll
    for (int ni = 0; ni < 8; ni++) {
      int r = wm + mi * 16 + g;
      int c = wn + ni * 8 + t4 * 2;
      *reinterpret_cast<float2*>(&cs[r * 132 + c]) =
          make_float2(acc[mi][ni][0], acc[mi][ni][1]);
      *reinterpret_cast<float2*>(&cs[(r + 8) * 132 + c]) =
          make_float2(acc[mi][ni][2], acc[mi][ni][3]);
    }
  __syncthreads();

#pragma unroll 4
  for (int rr = 0; rr < 16; ++rr) {
    int row = wid * 16 + rr;
    int m = m0 + row;
#pragma unroll
    for (int i = 0; i < 2; ++i) {
      int c = 2 * lane + 64 * i;
      float d0 = cs[row * 132 + c];
      float d1 = cs[row * 132 + c + 1];
      epi_pair<EPI>(m, n0 + c, d0, d1, ep);
    }
  }
}

// ---------------- tail GEMM (fp16, 2 products) -------------------------------
__global__ __launch_bounds__(256, 2) void tail_gemm(
    const f16* __restrict__ Ah, const f16* __restrict__ Al,
    const f16* __restrict__ Bm, int Kc, int lda, int ldb, EpiP ep) {
  extern __shared__ char smc[];
  const uint32_t sb = smem_u32(smc);
  const int tid = threadIdx.x, lane = tid & 31, wid = tid >> 5;
  const int m0 = blockIdx.y * 128, n0 = blockIdx.x * 64;
  const int wm = (wid & 3) * 32, wn = (wid >> 2) * 32;
  const int kstart = blockIdx.z * Kc;
  constexpr uint32_t PA = 10240;
  constexpr uint32_t PB = 5120;
  constexpr uint32_t STG = 2 * PA + PB;  // 25600

  const int lr = tid >> 1;
  const int lc = (tid & 1) * 2;
  const f16* pA0 = Ah + (size_t)(m0 + lr) * lda + lc * 8;
  const f16* pA1 = Al + (size_t)(m0 + lr) * lda + lc * 8;
  const int br = (tid & 127) >> 1, bcp = (tid & 1) * 2;
  const f16* pB = Bm + (size_t)(n0 + br) * ldb + bcp * 8;
  const uint32_t bOff = 2 * PA + (uint32_t)br * 80 + bcp * 16;

  auto stage_load = [&](int s, int k0) {
    uint32_t base = sb + (uint32_t)s * STG;
    uint32_t aA = base + (uint32_t)lr * 80 + lc * 16;
    cpa16(aA, pA0 + k0);
    cpa16(aA + 16, pA0 + k0 + 8);
    cpa16(aA + PA, pA1 + k0);
    cpa16(aA + PA + 16, pA1 + k0 + 8);
    if (tid < 128) {
      uint32_t aB = base + bOff;
      cpa16(aB, pB + k0);
      cpa16(aB + 16, pB + k0 + 8);
    }
    cpa_commit();
  };

  float acc[2][4][4];
#pragma unroll
  for (int i = 0; i < 2; i++)
#pragma unroll
    for (int j = 0; j < 4; j++)
#pragma unroll
      for (int q = 0; q < 4; q++) acc[i][j][q] = 0.f;

  const int nk = Kc / 32;
  stage_load(0, kstart);
  cpa_wait0();
  __syncthreads();

  const int g3 = lane >> 3, r8 = lane & 7;

  for (int kb = 0; kb < nk; ++kb) {
    const int s = kb & 1;
    if (kb + 1 < nk) stage_load(s ^ 1, kstart + (kb + 1) * 32);
    const uint32_t ab = sb + (uint32_t)s * STG;
#pragma unroll
    for (int k16 = 0; k16 < 32; k16 += 16) {
      uint32_t Ahf[2][4], Alf[2][4], Bf[4][2];
#pragma unroll
      for (int mi = 0; mi < 2; mi++) {
        uint32_t row = wm + mi * 16 + (g3 & 1) * 8 + r8;
        uint32_t col = k16 + (g3 >> 1) * 8;
        uint32_t ad = ab + row * 80 + col * 2;
        ldsm4(ad, Ahf[mi]);
        ldsm4(ad + PA, Alf[mi]);
      }
#pragma unroll
      for (int pi = 0; pi < 2; pi++) {
        uint32_t row = wn + (2 * pi + (g3 >> 1)) * 8 + r8;
        uint32_t col = k16 + (g3 & 1) * 8;
        uint32_t ad = ab + 2 * PA + row * 80 + col * 2;
        uint32_t t[4];
        ldsm4(ad, t);
        Bf[2 * pi][0] = t[0];
        Bf[2 * pi][1] = t[1];
        Bf[2 * pi + 1][0] = t[2];
        Bf[2 * pi + 1][1] = t[3];
      }
#pragma unroll
      for (int mi = 0; mi < 2; mi++)
#pragma unroll
        for (int ni = 0; ni < 4; ni++)
          mma_f16(acc[mi][ni], Ahf[mi], Bf[ni]);
#pragma unroll
      for (int mi = 0; mi < 2; mi++)
#pragma unroll
        for (int ni = 0; ni < 4; ni++)
          mma_f16(acc[mi][ni], Alf[mi], Bf[ni]);
    }
    cpa_wait0();
    __syncthreads();
  }

  float* cs = reinterpret_cast<float*>(smc);
  const int g = lane >> 2, t4 = lane & 3;
#pragma unroll
  for (int mi = 0; mi < 2; mi++)
#pragma unroll
    for (int ni = 0; ni < 4; ni++) {
      int r = wm + mi * 16 + g;
      int c = wn + ni * 8 + t4 * 2;
      *reinterpret_cast<float2*>(&cs[r * 68 + c]) =
          make_float2(acc[mi][ni][0], acc[mi][ni][1]);
      *reinterpret_cast<float2*>(&cs[(r + 8) * 68 + c]) =
          make_float2(acc[mi][ni][2], acc[mi][ni][3]);
    }
  __syncthreads();

#pragma unroll 4
  for (int rr = 0; rr < 16; ++rr) {
    int row = wid * 16 + rr;
    int m = m0 + row;
    int c = 2 * lane;
    float d0 = cs[row * 68 + c];
    float d1 = cs[row * 68 + c + 1];
    epi_pair<4>(m, n0 + c, d0, d1, ep);
  }
}

// ---------------- fused head GEMM slice (bf16, dual accumulators) ------------
__global__ __launch_bounds__(256, 2) void head_gemm(
    const bf16* __restrict__ Axh, const bf16* __restrict__ Axl,
    const bf16* __restrict__ Wqh, const bf16* __restrict__ Wql,
    const bf16* __restrict__ Wlh, const bf16* __restrict__ Wll,
    const float* __restrict__ blv, float* __restrict__ U,
    float* __restrict__ P, unsigned char* __restrict__ F,
    bf16* __restrict__ zh, bf16* __restrict__ zl, int coff) {
  extern __shared__ char smc[];
  const uint32_t sb = smem_u32(smc);
  const int tid = threadIdx.x, lane = tid & 31, wid = tid >> 5;
  const int m0 = blockIdx.y * 128, n0 = blockIdx.x * 64;
  const int wm = (wid & 3) * 32, wn = (wid >> 2) * 32;
  constexpr uint32_t PA = 10240;
  constexpr uint32_t PB = 5120;
  constexpr uint32_t STG = 2 * PA + 4 * PB;  // 40960

  const int lr = tid >> 1, lc = (tid & 1) * 2;
  const bf16* pA0 = Axh + (size_t)(m0 + lr) * Dd + lc * 8;
  const bf16* pA1 = Axl + (size_t)(m0 + lr) * Dd + lc * 8;
  const int br = (tid & 127) >> 1, bcp = (tid & 1) * 2;
  const int bw = tid >> 7;
  const bf16* pB0 = (bw ? Wlh : Wqh) + (size_t)(n0 + br) * Dd + bcp * 8;
  const bf16* pB1 = (bw ? Wll : Wql) + (size_t)(n0 + br) * Dd + bcp * 8;
  const uint32_t bOff = 2 * PA + (uint32_t)bw * 2 * PB + (uint32_t)br * 80 + bcp * 16;

  auto stage_load = [&](int s, int k0) {
    uint32_t base = sb + (uint32_t)s * STG;
    uint32_t aA = base + (uint32_t)lr * 80 + lc * 16;
    cpa16(aA, pA0 + k0);
    cpa16(aA + 16, pA0 + k0 + 8);
    cpa16(aA + PA, pA1 + k0);
    cpa16(aA + PA + 16, pA1 + k0 + 8);
    uint32_t aB = base + bOff;
    cpa16(aB, pB0 + k0);
    cpa16(aB + 16, pB0 + k0 + 8);
    cpa16(aB + PB, pB1 + k0);
    cpa16(aB + PB + 16, pB1 + k0 + 8);
    cpa_commit();
  };

  float accq[2][4][4], accl[2][4][4];
#pragma unroll
  for (int i = 0; i < 2; i++)
#pragma unroll
    for (int j = 0; j < 4; j++)
#pragma unroll
      for (int q = 0; q < 4; q++) accq[i][j][q] = accl[i][j][q] = 0.f;

  constexpr int nk = Dd / 32;
  stage_load(0, 0);
  cpa_wait0();
  __syncthreads();

  const int g3 = lane >> 3, r8 = lane & 7;

  for (int kb = 0; kb < nk; ++kb) {
    const int s = kb & 1;
    if (kb + 1 < nk) stage_load(s ^ 1, (kb + 1) * 32);
    const uint32_t ab = sb + (uint32_t)s * STG;
#pragma unroll
    for (int k16 = 0; k16 < 32; k16 += 16) {
      uint32_t Ahf[2][4], Alf[2][4];
      uint32_t Bqh_[4][2], Bql_[4][2], Blh_[4][2], Bll_[4][2];
#pragma unroll
      for (int mi = 0; mi < 2; mi++) {
        uint32_t row = wm + mi * 16 + (g3 & 1) * 8 + r8;
        uint32_t col = k16 + (g3 >> 1) * 8;
        uint32_t ad = ab + row * 80 + col * 2;
        ldsm4(ad, Ahf[mi]);
        ldsm4(ad + PA, Alf[mi]);
      }
#pragma unroll
      for (int pi = 0; pi < 2; pi++) {
        uint32_t row = wn + (2 * pi + (g3 >> 1)) * 8 + r8;
        uint32_t col = k16 + (g3 & 1) * 8;
        uint32_t adq = ab + 2 * PA + row * 80 + col * 2;
        uint32_t t[4];
        ldsm4(adq, t);
        Bqh_[2 * pi][0] = t[0]; Bqh_[2 * pi][1] = t[1];
        Bqh_[2 * pi + 1][0] = t[2]; Bqh_[2 * pi + 1][1] = t[3];
        ldsm4(adq + PB, t);
        Bql_[2 * pi][0] = t[0]; Bql_[2 * pi][1] = t[1];
        Bql_[2 * pi + 1][0] = t[2]; Bql_[2 * pi + 1][1] = t[3];
        ldsm4(adq + 2 * PB, t);
        Blh_[2 * pi][0] = t[0]; Blh_[2 * pi][1] = t[1];
        Blh_[2 * pi + 1][0] = t[2]; Blh_[2 * pi + 1][1] = t[3];
        ldsm4(adq + 3 * PB, t);
        Bll_[2 * pi][0] = t[0]; Bll_[2 * pi][1] = t[1];
        Bll_[2 * pi + 1][0] = t[2]; Bll_[2 * pi + 1][1] = t[3];
      }
#pragma unroll
      for (int mi = 0; mi < 2; mi++)
#pragma unroll
        for (int ni = 0; ni < 4; ni++) {
          mma_bf16(accq[mi][ni], Ahf[mi], Bqh_[ni]);
          mma_bf16(accq[mi][ni], Ahf[mi], Bql_[ni]);
          mma_bf16(accq[mi][ni], Alf[mi], Bqh_[ni]);
          mma_bf16(accl[mi][ni], Ahf[mi], Blh_[ni]);
          mma_bf16(accl[mi][ni], Ahf[mi], Bll_[ni]);
          mma_bf16(accl[mi][ni], Alf[mi], Blh_[ni]);
        }
    }
    cpa_wait0();
    __syncthreads();
  }

  float* cs = reinterpret_cast<float*>(smc);
  const int g = lane >> 2, t4 = lane & 3;
#pragma unroll
  for (int mi = 0; mi < 2; mi++)
#pragma unroll
    for (int ni = 0; ni < 4; ni++) {
      int r = wm + mi * 16 + g;
      int c = wn + ni * 8 + t4 * 2;
      *reinterpret_cast<float2*>(&cs[r * 132 + c]) =
          make_float2(accq[mi][ni][0], accq[mi][ni][1]);
      *reinterpret_cast<float2*>(&cs[(r + 8) * 132 + c]) =
          make_float2(accq[mi][ni][2], accq[mi][ni][3]);
      *reinterpret_cast<float2*>(&cs[r * 132 + 64 + c]) =
          make_float2(accl[mi][ni][0], accl[mi][ni][1]);
      *reinterpret_cast<float2*>(&cs[(r + 8) * 132 + 64 + c]) =
          make_float2(accl[mi][ni][2], accl[mi][ni][3]);
    }
  __syncthreads();

  const bool inZ = (coff == 0);
#pragma unroll 4
  for (int rr = 0; rr < 16; ++rr) {
    int row = wid * 16 + rr;
    int m = m0 + row;
    int c = 2 * lane;
    int n = coff + n0 + c;
    float u0 = cs[row * 132 + c], u1 = cs[row * 132 + c + 1];
    float v0 = cs[row * 132 + 64 + c], v1 = cs[row * 132 + 64 + c + 1];
    size_t idx = (size_t)m * LH + n;
    *reinterpret_cast<float2*>(&U[idx]) = make_float2(u0, u1);
    float2 b2 = *reinterpret_cast<const float2*>(&blv[n]);
    float p0 = u0 * u0 + v0 + b2.x;
    float p1 = u1 * u1 + v1 + b2.y;
    *reinterpret_cast<float2*>(&P[idx]) = make_float2(p0, p1);
    if (inZ) {
      bool s0 = (p0 >= 0.f), s1 = (p1 >= 0.f);
      uchar2 f2;
      f2.x = s0 ? 1 : 0;
      f2.y = s1 ? 1 : 0;
      *reinterpret_cast<uchar2*>(&F[idx]) = f2;
      float z0 = s0 ? p0 : NEG_SLOPE * p0;
      float z1 = s1 ? p1 : NEG_SLOPE * p1;
      bf16 h0, l0, h1, l1;
      bsplit(z0, h0, l0);
      bsplit(z1, h1, l1);
      __nv_bfloat162 hv, lv;
      hv.x = h0; hv.y = h1;
      lv.x = l0; lv.y = l1;
      *reinterpret_cast<__nv_bfloat162*>(&zh[(size_t)m * Hh + n0 + c]) = hv;
      *reinterpret_cast<__nv_bfloat162*>(&zl[(size_t)m * Hh + n0 + c]) = lv;
    }
  }
}

// ---------------- prep / elementwise ----------------------------------------
__global__ void k_split3(const float* __restrict__ x, const float* __restrict__ Wq,
                         const float* __restrict__ Wl, bf16* __restrict__ xh,
                         bf16* __restrict__ xl, bf16* __restrict__ qh,
                         bf16* __restrict__ ql, bf16* __restrict__ lh,
                         bf16* __restrict__ ll) {
  int i = blockIdx.x * 256 + threadIdx.x;
  const int n1 = Bsz * Dd, n2 = LH * Dd;
  bf16 h, l;
  if (i < n1) {
    bsplit(x[i], h, l);
    xh[i] = h; xl[i] = l;
  } else if (i < n1 + n2) {
    int j = i - n1;
    bsplit(Wq[j], h, l);
    qh[j] = h; ql[j] = l;
  } else if (i < n1 + 2 * n2) {
    int j = i - n1 - n2;
    bsplit(Wl[j], h, l);
    lh[j] = h; ll[j] = l;
  }
}

__global__ void k_split(const float* __restrict__ in, bf16* __restrict__ h,
                        bf16* __restrict__ l, int n) {
  int i = blockIdx.x * 256 + threadIdx.x;
  if (i < n) {
    bf16 hh, ll;
    bsplit(in[i], hh, ll);
    h[i] = hh;
    l[i] = ll;
  }
}

__global__ void k_wzT(const float* __restrict__ Wz, bf16* __restrict__ h,
                      bf16* __restrict__ l) {
  int i = blockIdx.x * 256 + threadIdx.x;
  int lay = i / (Hh * Hh);
  int r = i % (Hh * Hh);
  int o = r / Hh, ii = r % Hh;
  size_t dst = (size_t)lay * Hh * Hh + (size_t)ii * Hh + o;
  bf16 hh, ll;
  bsplit(Wz[i], hh, ll);
  h[dst] = hh;
  l[dst] = ll;
}

__global__ void k_bcat16(const float* __restrict__ Wq, const float* __restrict__ Wl,
                         f16* __restrict__ o) {
  int i = blockIdx.x * 256 + threadIdx.x;
  int lay = i / (Dd * 1024);
  int r = i % (Dd * 1024);
  int d = r / 1024, k = r % 1024;
  float v = (k < Hh) ? Wq[((size_t)lay * Hh + k) * Dd + d]
                     : Wl[((size_t)lay * Hh + (k - Hh)) * Dd + d];
  o[i] = __float2half_rn(v);
}

__global__ void k_dotzero(const float* __restrict__ x, const float* __restrict__ wq,
                          float* __restrict__ S, float* __restrict__ gx) {
  int gid = blockIdx.x * 256 + threadIdx.x;
  if (gid < Bsz * Dd) gx[gid] = 0.f;
  int w = gid / 32, lane = gid % 32;
  if (w < Bsz) {
    float s = 0.f;
    for (int d = lane; d < Dd; d += 32) s += x[(size_t)w * Dd + d] * wq[d];
#pragma unroll
    for (int o = 16; o; o >>= 1) s += __shfl_xor_sync(0xFFFFFFFFu, s, o);
    if (lane == 0) S[w] = s;
  }
}

__global__ void k_bwinit(const unsigned char* __restrict__ F,
                         const float* __restrict__ U,
                         const float* __restrict__ wz_out,
                         bf16* __restrict__ zh, bf16* __restrict__ zl,
                         f16* __restrict__ ach, f16* __restrict__ acl) {
  int i = blockIdx.x * 256 + threadIdx.x;
  int m = i / Hh, h = i % Hh;
  size_t idx = (size_t)m * LH + (size_t)(Ll - 1) * Hh + h;
  float f = F[idx] ? 1.f : NEG_SLOPE;
  float ga = wz_out[h] * f;
  bf16 gh, gl;
  bsplit(ga, gh, gl);
  zh[i] = gh;
  zl[i] = gl;
  float g1 = 2.f * ga * U[idx];  // ascale = 1 at l = 9
  f16 h1, l1;
  size_t ai = (size_t)m * 1024 + h;
  hsplit(g1, h1, l1);
  ach[ai] = h1;
  acl[ai] = l1;
  hsplit(ga, h1, l1);
  ach[ai + Hh] = h1;
  acl[ai + Hh] = l1;
}

// Build fp16 Acat for layer l from bf16 ga pair + U, scaled by ascale.
__global__ void k_acat(const bf16* __restrict__ gah, const bf16* __restrict__ gal,
                       const float* __restrict__ U, f16* __restrict__ ach,
                       f16* __restrict__ acl, int coff, float ascale) {
  int i = blockIdx.x * 256 + threadIdx.x;  // Bsz*Hh
  int m = i / Hh, h = i % Hh;
  float ga = __bfloat162float(gah[i]) + __bfloat162float(gal[i]);
  float as = ga * ascale;
  float g1 = 2.f * as * U[(size_t)m * LH + coff + h];
  f16 th, tl;
  size_t ai = (size_t)m * 1024 + h;
  hsplit(g1, th, tl);
  ach[ai] = th;
  acl[ai] = tl;
  hsplit(as, th, tl);
  ach[ai + Hh] = th;
  acl[ai + Hh] = tl;
}

__global__ void k_final(const float* __restrict__ gx, const float* __restrict__ S,
                        const float* __restrict__ wq, const float* __restrict__ wl,
                        const float* __restrict__ x, float* __restrict__ out) {
  int i = blockIdx.x * 256 + threadIdx.x;
  int m = i >> 7, n = i & 127;
  out[i] = 0.5f * (gx[i] + 2.f * S[m] * wq[n] + wl[n]) + 0.5f * x[i];
}

// ---------------- host driver ------------------------------------------------
constexpr uint32_t SMEM_SZ = 81920;
constexpr uint32_t SMEM_TAIL = 51200;

extern "C" void kernel_launch(void* const* d_in, const int* in_sizes, int n_in,
                              void* d_out, int out_size) {
  const float* x = (const float*)d_in[0];
  const float* Wq = (const float*)d_in[1];
  const float* Wl = (const float*)d_in[2];
  const float* bl = (const float*)d_in[3];
  const float* Wz = (const float*)d_in[4];
  const float* wz_out = (const float*)d_in[5];
  const float* wq_out = (const float*)d_in[6];
  const float* wl_out = (const float*)d_in[7];
  float* out = (float*)d_out;

  bf16 *xh, *xl, *Wqh, *Wql, *Wlh, *Wll, *Wzh, *Wzl, *WzTh, *WzTl;
  bf16 *zAh, *zAl, *zBh, *zBl;
  f16 *Bc16, *Ach[2], *Acl[2];
  float *U, *P, *gx, *S;
  unsigned char* F;
  cudaGetSymbolAddress((void**)&xh, g_xh);
  cudaGetSymbolAddress((void**)&xl, g_xl);
  cudaGetSymbolAddress((void**)&Wqh, g_Wqh);
  cudaGetSymbolAddress((void**)&Wql, g_Wql);
  cudaGetSymbolAddress((void**)&Wlh, g_Wlh);
  cudaGetSymbolAddress((void**)&Wll, g_Wll);
  cudaGetSymbolAddress((void**)&Wzh, g_Wzh);
  cudaGetSymbolAddress((void**)&Wzl, g_Wzl);
  cudaGetSymbolAddress((void**)&WzTh, g_WzTh);
  cudaGetSymbolAddress((void**)&WzTl, g_WzTl);
  cudaGetSymbolAddress((void**)&Bc16, g_Bc16);
  cudaGetSymbolAddress((void**)&U, g_U);
  cudaGetSymbolAddress((void**)&P, g_P);
  cudaGetSymbolAddress((void**)&F, g_F);
  cudaGetSymbolAddress((void**)&zAh, g_zAh);
  cudaGetSymbolAddress((void**)&zAl, g_zAl);
  cudaGetSymbolAddress((void**)&zBh, g_zBh);
  cudaGetSymbolAddress((void**)&zBl, g_zBl);
  cudaGetSymbolAddress((void**)&Ach[0], g_Ach0);
  cudaGetSymbolAddress((void**)&Acl[0], g_Acl0);
  cudaGetSymbolAddress((void**)&Ach[1], g_Ach1);
  cudaGetSymbolAddress((void**)&Acl[1], g_Acl1);
  cudaGetSymbolAddress((void**)&gx, g_gx);
  cudaGetSymbolAddress((void**)&S, g_S);

  static bool s_init = false;
  static cudaStream_t st1, st2;
  static cudaEvent_t evStart, evSplit, evWz, evWzT, evHd[10], evBw[10],
      evAcat[10], evT2;
  if (!s_init) {
    cudaStreamCreateWithFlags(&st1, cudaStreamNonBlocking);
    cudaStreamCreateWithFlags(&st2, cudaStreamNonBlocking);
    cudaEventCreateWithFlags(&evStart, cudaEventDisableTiming);
    cudaEventCreateWithFlags(&evSplit, cudaEventDisableTiming);
    cudaEventCreateWithFlags(&evWz, cudaEventDisableTiming);
    cudaEventCreateWithFlags(&evWzT, cudaEventDisableTiming);
    cudaEventCreateWithFlags(&evT2, cudaEventDisableTiming);
    for (int i = 0; i < 10; i++) {
      cudaEventCreateWithFlags(&evHd[i], cudaEventDisableTiming);
      cudaEventCreateWithFlags(&evBw[i], cudaEventDisableTiming);
      cudaEventCreateWithFlags(&evAcat[i], cudaEventDisableTiming);
    }
    cudaFuncSetAttribute(mma_gemm<2>, cudaFuncAttributeMaxDynamicSharedMemorySize, SMEM_SZ);
    cudaFuncSetAttribute(mma_gemm<3>, cudaFuncAttributeMaxDynamicSharedMemorySize, SMEM_SZ);
    cudaFuncSetAttribute(tail_gemm, cudaFuncAttributeMaxDynamicSharedMemorySize, SMEM_TAIL);
    cudaFuncSetAttribute(head_gemm, cudaFuncAttributeMaxDynamicSharedMemorySize, SMEM_SZ);
    s_init = true;
  }

  // ---- fork side streams ----
  cudaEventRecord(evStart, 0);
  cudaStreamWaitEvent(st1, evStart, 0);
  cudaStreamWaitEvent(st2, evStart, 0);

  // s0: input/weight splits
  {
    int tot = Bsz * Dd + 2 * LH * Dd;
    k_split3<<<(tot + 255) / 256, 256>>>(x, Wq, Wl, xh, xl, Wqh, Wql, Wlh, Wll);
  }
  cudaEventRecord(evSplit, 0);

  // st2: Wz split, WzT split, tail weights, dot+gx zero
  k_split<<<((Ll - 1) * Hh * Hh + 255) / 256, 256, 0, st2>>>(
      Wz, Wzh, Wzl, (Ll - 1) * Hh * Hh);
  cudaEventRecord(evWz, st2);
  k_wzT<<<((Ll - 1) * Hh * Hh + 255) / 256, 256, 0, st2>>>(Wz, WzTh, WzTl);
  cudaEventRecord(evWzT, st2);
  k_bcat16<<<(Ll * Dd * 1024 + 255) / 256, 256, 0, st2>>>(Wq, Wl, Bc16);
  k_dotzero<<<(Bsz * Dd + 255) / 256, 256, 0, st2>>>(x, wq_out, S, gx);

  // st1: per-layer head slices
  cudaStreamWaitEvent(st1, evSplit, 0);
  for (int l = 0; l < Ll; ++l) {
    head_gemm<<<dim3(Hh / 64, Bsz / 128), 256, SMEM_SZ, st1>>>(
        xh, xl, Wqh + (size_t)l * Hh * Dd, Wql + (size_t)l * Hh * Dd,
        Wlh + (size_t)l * Hh * Dd, Wll + (size_t)l * Hh * Dd, bl, U, P, F,
        zAh, zAl, l * Hh);
    cudaEventRecord(evHd[l], st1);
  }

  // s0: forward chain; layer l waits on head slice l
  bf16* zh2[2] = {zAh, zBh};
  bf16* zl2[2] = {zAl, zBl};
  cudaStreamWaitEvent(0, evWz, 0);
  for (int l = 1; l < Ll; ++l) {
    cudaStreamWaitEvent(0, evHd[l], 0);
    EpiP ep = {};
    ep.Pc = P;
    ep.F = F;
    ep.coff = l * Hh;
    ep.zh = zh2[l & 1];
    ep.zl = zl2[l & 1];
    mma_gemm<2><<<dim3(Hh / 128, Bsz / 128, 1), 256, SMEM_SZ>>>(
        zh2[(l - 1) & 1], zl2[(l - 1) & 1], Wzh + (size_t)(l - 1) * Hh * Hh,
        Wzl + (size_t)(l - 1) * Hh * Hh, Hh, Hh, Hh, ep);
  }

  // ---- backward init (layer 9): ga9 -> zh2[0]; fp16 Acat buf[1] direct ----
  k_bwinit<<<(Bsz * Hh + 255) / 256, 256>>>(F, U, wz_out, zh2[0], zl2[0],
                                            Ach[1], Acl[1]);
  cudaEventRecord(evBw[9], 0);

  cudaStreamWaitEvent(st2, evBw[9], 0);
  {
    EpiP ep = {};
    ep.gx = gx;
    ep.tscale = 1.f;
    tail_gemm<<<dim3(Dd / 64, Bsz / 128, 2), 256, SMEM_TAIL, st2>>>(
        Ach[1], Acl[1], Bc16 + (size_t)(Ll - 1) * Dd * 1024, 512, 1024, 1024,
        ep);
  }

  // ---- backward chain on s0; k_acat + tails on st2 (layers 8..1) ----
  cudaStreamWaitEvent(0, evWzT, 0);
  int cur = 0;  // zh2[cur] holds ga_{l+1}
  for (int l = Ll - 2; l >= 0; --l) {
    if (l + 2 <= Ll - 2) cudaStreamWaitEvent(0, evAcat[l + 2], 0);
    {
      EpiP ep = {};
      ep.F = F;
      ep.coff = l * Hh;
      ep.zh = zh2[cur ^ 1];
      ep.zl = zl2[cur ^ 1];
      mma_gemm<3><<<dim3(Hh / 128, Bsz / 128, 1), 256, SMEM_SZ>>>(
          zh2[cur], zl2[cur], WzTh + (size_t)l * Hh * Hh,
          WzTl + (size_t)l * Hh * Hh, Hh, Hh, Hh, ep);
    }
    cudaEventRecord(evBw[l], 0);
    float as = 1.f, ts = 1.f;
    for (int t = 0; t < 9 - l; ++t) { as *= 0.0625f; ts *= 16.f; }
    if (l > 0) {
      // st2: build fp16 Acat for layer l, then tail l
      cudaStreamWaitEvent(st2, evBw[l], 0);
      k_acat<<<(Bsz * Hh + 255) / 256, 256, 0, st2>>>(
          zh2[cur ^ 1], zl2[cur ^ 1], U, Ach[l & 1], Acl[l & 1], l * Hh, as);
      cudaEventRecord(evAcat[l], st2);
      EpiP ep = {};
      ep.gx = gx;
      ep.tscale = ts;
      tail_gemm<<<dim3(Dd / 64, Bsz / 128, 2), 256, SMEM_TAIL, st2>>>(
          Ach[l & 1], Acl[l & 1], Bc16 + (size_t)l * Dd * 1024, 512, 1024,
          1024, ep);
      if (l == 1) cudaEventRecord(evT2, st2);
    } else {
      // l == 0: run on stream 0 — chip is idle, no event hops; K-split x4.
      k_acat<<<(Bsz * Hh + 255) / 256, 256>>>(
          zh2[cur ^ 1], zl2[cur ^ 1], U, Ach[0], Acl[0], 0, as);
      EpiP ep = {};
      ep.gx = gx;
      ep.tscale = ts;
      tail_gemm<<<dim3(Dd / 64, Bsz / 128, 4), 256, SMEM_TAIL>>>(
          Ach[0], Acl[0], Bc16, 256, 1024, 1024, ep);
    }
    cur ^= 1;
  }

  // ---- join (st2 FIFO: evT2 covers tails 9..1) and final combine ----
  cudaStreamWaitEvent(0, evT2, 0);
  k_final<<<(Bsz * Dd + 255) / 256, 256>>>(gx, S, wq_out, wl_out, x, out);
}

// round 15
// speedup vs baseline: 1.6224x; 1.0696x over previous
#include <cuda_runtime.h>
#include <cuda_bf16.h>
#include <cuda_fp16.h>
#include <cstdint>

// ===========================================================================
// ICNN forward + input-gradient via mma.sync.
// fwd chain + head: bf16 pairs, 3 products (mask-critical, kept exact-ish).
// bwd chain: fp16 pair x single-fp16 WzT, 2 products — linear all-positive
//   recursion (Wz>=0, ga>=0, masks fixed by fwd) => no amplification hazard;
//   per-layer 16^-1 scaling (t_l = ga_l*16^-(9-l)) keeps fp16 in range.
// tails: fp16 pair x fp16 weights, 2 products (validated).
// ===========================================================================

typedef __nv_bfloat16 bf16;
typedef __half f16;

#define NEG_SLOPE 0.2f
constexpr int Bsz = 8192;
constexpr int Dd  = 128;
constexpr int Hh  = 512;
constexpr int Ll  = 10;
constexpr int LH  = Ll * Hh;  // 5120

// ---------------- static device scratch ------------------------------------
__device__ bf16 g_xh[(size_t)Bsz * Dd], g_xl[(size_t)Bsz * Dd];
__device__ bf16 g_Wqh[(size_t)LH * Dd], g_Wql[(size_t)LH * Dd];
__device__ bf16 g_Wlh[(size_t)LH * Dd], g_Wll[(size_t)LH * Dd];
__device__ bf16 g_Wzh[(size_t)(Ll - 1) * Hh * Hh], g_Wzl[(size_t)(Ll - 1) * Hh * Hh];
__device__ f16  g_WzT16[(size_t)(Ll - 1) * Hh * Hh];
__device__ f16  g_Bc16[(size_t)Ll * Dd * 1024];
__device__ float g_U[(size_t)Bsz * LH];
__device__ float g_P[(size_t)Bsz * LH];
__device__ unsigned char g_F[(size_t)Bsz * LH];
__device__ bf16 g_zAh[(size_t)Bsz * Hh], g_zAl[(size_t)Bsz * Hh];
__device__ bf16 g_zBh[(size_t)Bsz * Hh], g_zBl[(size_t)Bsz * Hh];
__device__ f16 g_tAh[(size_t)Bsz * Hh], g_tAl[(size_t)Bsz * Hh];
__device__ f16 g_tBh[(size_t)Bsz * Hh], g_tBl[(size_t)Bsz * Hh];
__device__ f16 g_Ach0[(size_t)Bsz * 1024], g_Acl0[(size_t)Bsz * 1024];
__device__ f16 g_Ach1[(size_t)Bsz * 1024], g_Acl1[(size_t)Bsz * 1024];
__device__ float g_gx[(size_t)Bsz * Dd];
__device__ float g_S[Bsz];

// ---------------- helpers ---------------------------------------------------
__device__ __forceinline__ uint32_t smem_u32(const void* p) {
  uint32_t a;
  asm("{ .reg .u64 t; cvta.to.shared.u64 t, %1; cvt.u32.u64 %0, t; }"
      : "=r"(a) : "l"(p));
  return a;
}
__device__ __forceinline__ void cpa16(uint32_t s, const void* g) {
  asm volatile("cp.async.cg.shared.global [%0], [%1], 16;" ::"r"(s), "l"(g));
}
__device__ __forceinline__ void cpa_commit() {
  asm volatile("cp.async.commit_group;" ::: "memory");
}
__device__ __forceinline__ void cpa_wait0() {
  asm volatile("cp.async.wait_group 0;" ::: "memory");
}
__device__ __forceinline__ void ldsm4(uint32_t addr, uint32_t* r) {
  asm volatile("ldmatrix.sync.aligned.m8n8.x4.shared.b16 {%0,%1,%2,%3}, [%4];"
               : "=r"(r[0]), "=r"(r[1]), "=r"(r[2]), "=r"(r[3]) : "r"(addr));
}
__device__ __forceinline__ void mma_bf16(float* c, const uint32_t* a,
                                         const uint32_t* b) {
  asm volatile(
      "mma.sync.aligned.m16n8k16.row.col.f32.bf16.bf16.f32 "
      "{%0,%1,%2,%3}, {%4,%5,%6,%7}, {%8,%9}, {%0,%1,%2,%3};"
      : "+f"(c[0]), "+f"(c[1]), "+f"(c[2]), "+f"(c[3])
      : "r"(a[0]), "r"(a[1]), "r"(a[2]), "r"(a[3]), "r"(b[0]), "r"(b[1]));
}
__device__ __forceinline__ void mma_f16(float* c, const uint32_t* a,
                                        const uint32_t* b) {
  asm volatile(
      "mma.sync.aligned.m16n8k16.row.col.f32.f16.f16.f32 "
      "{%0,%1,%2,%3}, {%4,%5,%6,%7}, {%8,%9}, {%0,%1,%2,%3};"
      : "+f"(c[0]), "+f"(c[1]), "+f"(c[2]), "+f"(c[3])
      : "r"(a[0]), "r"(a[1]), "r"(a[2]), "r"(a[3]), "r"(b[0]), "r"(b[1]));
}
__device__ __forceinline__ void bsplit(float v, bf16& h, bf16& l) {
  h = __float2bfloat16(v);
  l = __float2bfloat16(v - __bfloat162float(h));
}
__device__ __forceinline__ void hsplit(float v, f16& h, f16& l) {
  h = __float2half_rn(v);
  l = __float2half_rn(v - __half2float(h));
}

// ---------------- epilogue params -------------------------------------------
struct EpiP {
  const float* Pc;
  unsigned char* F;
  bf16* zh;
  bf16* zl;
  f16* th;
  f16* tl;
  float* gx;
  int coff;
  float tscale;  // EPI4: gx accumulate scale = 16^(9-l)
};

// EPI: 2=fwd layer (bf16 z); 4=gx accum; 5=bwd layer (fp16 t, x f/16)
template <int EPI>
__device__ __forceinline__ void epi_pair(int m, int n, float d0, float d1,
                                         const EpiP& ep) {
  if (EPI == 2) {
    size_t idx = (size_t)m * LH + ep.coff + n;
    float2 pc = *reinterpret_cast<const float2*>(&ep.Pc[idx]);
    float a0 = d0 + pc.x, a1 = d1 + pc.y;
    bool p0 = (a0 >= 0.f), p1 = (a1 >= 0.f);
    uchar2 f2;
    f2.x = p0 ? 1 : 0;
    f2.y = p1 ? 1 : 0;
    *reinterpret_cast<uchar2*>(&ep.F[idx]) = f2;
    float z0 = p0 ? a0 : NEG_SLOPE * a0;
    float z1 = p1 ? a1 : NEG_SLOPE * a1;
    bf16 h0, l0, h1, l1;
    bsplit(z0, h0, l0);
    bsplit(z1, h1, l1);
    __nv_bfloat162 hv, lv;
    hv.x = h0; hv.y = h1;
    lv.x = l0; lv.y = l1;
    *reinterpret_cast<__nv_bfloat162*>(&ep.zh[(size_t)m * Hh + n]) = hv;
    *reinterpret_cast<__nv_bfloat162*>(&ep.zl[(size_t)m * Hh + n]) = lv;
  } else if (EPI == 5) {
    size_t idx = (size_t)m * LH + ep.coff + n;
    uchar2 f2 = *reinterpret_cast<const uchar2*>(&ep.F[idx]);
    float f0 = f2.x ? 1.f : NEG_SLOPE;
    float f1 = f2.y ? 1.f : NEG_SLOPE;
    float t0 = d0 * f0 * 0.0625f, t1 = d1 * f1 * 0.0625f;
    f16 h0, l0, h1, l1;
    hsplit(t0, h0, l0);
    hsplit(t1, h1, l1);
    __half2 hv, lv;
    hv.x = h0; hv.y = h1;
    lv.x = l0; lv.y = l1;
    *reinterpret_cast<__half2*>(&ep.th[(size_t)m * Hh + n]) = hv;
    *reinterpret_cast<__half2*>(&ep.tl[(size_t)m * Hh + n]) = lv;
  } else {  // EPI == 4
    atomicAdd(&ep.gx[(size_t)m * Dd + n], d0 * ep.tscale);
    atomicAdd(&ep.gx[(size_t)m * Dd + n + 1], d1 * ep.tscale);
  }
}

// ---------------- fwd chain GEMM (bf16, 3 products) --------------------------
template <int EPI>
__global__ __launch_bounds__(256, 2) void mma_gemm(
    const bf16* __restrict__ Ah, const bf16* __restrict__ Al,
    const bf16* __restrict__ Bh, const bf16* __restrict__ Bl, int Kc, int lda,
    int ldb, EpiP ep) {
  extern __shared__ char smc[];
  const uint32_t sb = smem_u32(smc);
  const int tid = threadIdx.x, lane = tid & 31, wid = tid >> 5;
  const int m0 = blockIdx.y * 128, n0 = blockIdx.x * 128;
  const int wm = (wid & 3) * 32, wn = (wid >> 2) * 64;
  constexpr uint32_t PL = 10240;
  constexpr uint32_t STG = 40960;

  const int lr = tid >> 1;
  const int lc = (tid & 1) * 2;

  const bf16* pA0 = Ah + (size_t)(m0 + lr) * lda + lc * 8;
  const bf16* pA1 = Al + (size_t)(m0 + lr) * lda + lc * 8;
  const bf16* pB0 = Bh + (size_t)(n0 + lr) * ldb + lc * 8;
  const bf16* pB1 = Bl + (size_t)(n0 + lr) * ldb + lc * 8;

  auto stage_load = [&](int s, int k0) {
    uint32_t base = sb + (uint32_t)s * STG + (uint32_t)lr * 80 + lc * 16;
    cpa16(base, pA0 + k0);
    cpa16(base + 16, pA0 + k0 + 8);
    cpa16(base + PL, pA1 + k0);
    cpa16(base + PL + 16, pA1 + k0 + 8);
    cpa16(base + 2 * PL, pB0 + k0);
    cpa16(base + 2 * PL + 16, pB0 + k0 + 8);
    cpa16(base + 3 * PL, pB1 + k0);
    cpa16(base + 3 * PL + 16, pB1 + k0 + 8);
    cpa_commit();
  };

  float acc[2][8][4];
#pragma unroll
  for (int i = 0; i < 2; i++)
#pragma unroll
    for (int j = 0; j < 8; j++)
#pragma unroll
      for (int q = 0; q < 4; q++) acc[i][j][q] = 0.f;

  const int nk = Kc / 32;
  stage_load(0, 0);
  cpa_wait0();
  __syncthreads();

  const int g3 = lane >> 3, r8 = lane & 7;

  for (int kb = 0; kb < nk; ++kb) {
    const int s = kb & 1;
    if (kb + 1 < nk) stage_load(s ^ 1, (kb + 1) * 32);
    const uint32_t ab = sb + (uint32_t)s * STG;
#pragma unroll
    for (int k16 = 0; k16 < 32; k16 += 16) {
      uint32_t Ahf[2][4], Alf[2][4], Bhf[8][2], Blf[8][2];
#pragma unroll
      for (int mi = 0; mi < 2; mi++) {
        uint32_t row = wm + mi * 16 + (g3 & 1) * 8 + r8;
        uint32_t col = k16 + (g3 >> 1) * 8;
        uint32_t ad = ab + row * 80 + col * 2;
        ldsm4(ad, Ahf[mi]);
        ldsm4(ad + PL, Alf[mi]);
      }
#pragma unroll
      for (int pi = 0; pi < 4; pi++) {
        uint32_t row = wn + (2 * pi + (g3 >> 1)) * 8 + r8;
        uint32_t col = k16 + (g3 & 1) * 8;
        uint32_t ad = ab + 2 * PL + row * 80 + col * 2;
        uint32_t t[4];
        ldsm4(ad, t);
        Bhf[2 * pi][0] = t[0];
        Bhf[2 * pi][1] = t[1];
        Bhf[2 * pi + 1][0] = t[2];
        Bhf[2 * pi + 1][1] = t[3];
        ldsm4(ad + PL, t);
        Blf[2 * pi][0] = t[0];
        Blf[2 * pi][1] = t[1];
        Blf[2 * pi + 1][0] = t[2];
        Blf[2 * pi + 1][1] = t[3];
      }
#pragma unroll
      for (int mi = 0; mi < 2; mi++)
#pragma unroll
        for (int ni = 0; ni < 8; ni++) {
          mma_bf16(acc[mi][ni], Ahf[mi], Bhf[ni]);
          mma_bf16(acc[mi][ni], Ahf[mi], Blf[ni]);
          mma_bf16(acc[mi][ni], Alf[mi], Bhf[ni]);
        }
    }
    cpa_wait0();
    __syncthreads();
  }

  float* cs = reinterpret_cast<float*>(smc);
  const int g = lane >> 2, t4 = lane & 3;
#pragma unroll
  for (int mi = 0; mi < 2; mi++)
#pragma unroll
    for (int ni = 0; ni < 8; ni++) {
      int r = wm + mi * 16 + g;
      int c = wn + ni * 8 + t4 * 2;
      *reinterpret_cast<float2*>(&cs[r * 132 + c]) =
          make_float2(acc[mi][ni][0], acc[mi][ni][1]);
      *reinterpret_cast<float2*>(&cs[(r + 8) * 132 + c]) =
          make_float2(acc[mi][ni][2], acc[mi][ni][3]);
    }
  __syncthreads();

#pragma unroll 4
  for (int rr = 0; rr < 16; ++rr) {
    int row = wid * 16 + rr;
    int m = m0 + row;
#pragma unroll
    for (int i = 0; i < 2; ++i) {
      int c = 2 * lane + 64 * i;
      float d0 = cs[row * 132 + c];
      float d1 = cs[row * 132 + c + 1];
      epi_pair<EPI>(m, n0 + c, d0, d1, ep);
    }
  }
}

// ---------------- bwd chain GEMM (fp16, 2 products, N=128 tile) --------------
__global__ __launch_bounds__(256, 2) void bwd_gemm(
    const f16* __restrict__ Th, const f16* __restrict__ Tl,
    const f16* __restrict__ Bm, int Kc, int lda, int ldb, EpiP ep) {
  extern __shared__ char smc[];
  const uint32_t sb = smem_u32(smc);
  const int tid = threadIdx.x, lane = tid & 31, wid = tid >> 5;
  const int m0 = blockIdx.y * 128, n0 = blockIdx.x * 128;
  const int wm = (wid & 3) * 32, wn = (wid >> 2) * 64;
  constexpr uint32_t PL = 10240;
  constexpr uint32_t STG = 30720;  // Ah, Al, B

  const int lr = tid >> 1;
  const int lc = (tid & 1) * 2;

  const f16* pA0 = Th + (size_t)(m0 + lr) * lda + lc * 8;
  const f16* pA1 = Tl + (size_t)(m0 + lr) * lda + lc * 8;
  const f16* pB = Bm + (size_t)(n0 + lr) * ldb + lc * 8;

  auto stage_load = [&](int s, int k0) {
    uint32_t base = sb + (uint32_t)s * STG + (uint32_t)lr * 80 + lc * 16;
    cpa16(base, pA0 + k0);
    cpa16(base + 16, pA0 + k0 + 8);
    cpa16(base + PL, pA1 + k0);
    cpa16(base + PL + 16, pA1 + k0 + 8);
    cpa16(base + 2 * PL, pB + k0);
    cpa16(base + 2 * PL + 16, pB + k0 + 8);
    cpa_commit();
  };

  float acc[2][8][4];
#pragma unroll
  for (int i = 0; i < 2; i++)
#pragma unroll
    for (int j = 0; j < 8; j++)
#pragma unroll
      for (int q = 0; q < 4; q++) acc[i][j][q] = 0.f;

  const int nk = Kc / 32;
  stage_load(0, 0);
  cpa_wait0();
  __syncthreads();

  const int g3 = lane >> 3, r8 = lane & 7;

  for (int kb = 0; kb < nk; ++kb) {
    const int s = kb & 1;
    if (kb + 1 < nk) stage_load(s ^ 1, (kb + 1) * 32);
    const uint32_t ab = sb + (uint32_t)s * STG;
#pragma unroll
    for (int k16 = 0; k16 < 32; k16 += 16) {
      uint32_t Ahf[2][4], Alf[2][4], Bf[8][2];
#pragma unroll
      for (int mi = 0; mi < 2; mi++) {
        uint32_t row = wm + mi * 16 + (g3 & 1) * 8 + r8;
        uint32_t col = k16 + (g3 >> 1) * 8;
        uint32_t ad = ab + row * 80 + col * 2;
        ldsm4(ad, Ahf[mi]);
        ldsm4(ad + PL, Alf[mi]);
      }
#pragma unroll
      for (int pi = 0; pi < 4; pi++) {
        uint32_t row = wn + (2 * pi + (g3 >> 1)) * 8 + r8;
        uint32_t col = k16 + (g3 & 1) * 8;
        uint32_t ad = ab + 2 * PL + row * 80 + col * 2;
        uint32_t t[4];
        ldsm4(ad, t);
        Bf[2 * pi][0] = t[0];
        Bf[2 * pi][1] = t[1];
        Bf[2 * pi + 1][0] = t[2];
        Bf[2 * pi + 1][1] = t[3];
      }
#pragma unroll
      for (int mi = 0; mi < 2; mi++)
#pragma unroll
        for (int ni = 0; ni < 8; ni++)
          mma_f16(acc[mi][ni], Ahf[mi], Bf[ni]);
#pragma unroll
      for (int mi = 0; mi < 2; mi++)
#pragma unroll
        for (int ni = 0; ni < 8; ni++)
          mma_f16(acc[mi][ni], Alf[mi], Bf[ni]);
    }
    cpa_wait0();
    __syncthreads();
  }

  float* cs = reinterpret_cast<float*>(smc);
  const int g = lane >> 2, t4 = lane & 3;
#pragma unroll
  for (int mi = 0; mi < 2; mi++)
#pragma unroll
    for (int ni = 0; ni < 8; ni++) {
      int r = wm + mi * 16 + g;
      int c = wn + ni * 8 + t4 * 2;
      *reinterpret_cast<float2*>(&cs[r * 132 + c]) =
          make_float2(acc[mi][ni][0], acc[mi][ni][1]);
      *reinterpret_cast<float2*>(&cs[(r + 8) * 132 + c]) =
          make_float2(acc[mi][ni][2], acc[mi][ni][3]);
    }
  __syncthreads();

#pragma unroll 4
  for (int rr = 0; rr < 16; ++rr) {
    int row = wid * 16 + rr;
    int m = m0 + row;
#pragma unroll
    for (int i = 0; i < 2; ++i) {
      int c = 2 * lane + 64 * i;
      float d0 = cs[row * 132 + c];
      float d1 = cs[row * 132 + c + 1];
      epi_pair<5>(m, n0 + c, d0, d1, ep);
    }
  }
}

// ---------------- tail GEMM (fp16, 2 products, N=64 tile) --------------------
__global__ __launch_bounds__(256, 2) void tail_gemm(
    const f16* __restrict__ Ah, const f16* __restrict__ Al,
    const f16* __restrict__ Bm, int Kc, int lda, int ldb, EpiP ep) {
  extern __shared__ char smc[];
  const uint32_t sb = smem_u32(smc);
  const int tid = threadIdx.x, lane = tid & 31, wid = tid >> 5;
  const int m0 = blockIdx.y * 128, n0 = blockIdx.x * 64;
  const int wm = (wid & 3) * 32, wn = (wid >> 2) * 32;
  const int kstart = blockIdx.z * Kc;
  constexpr uint32_t PA = 10240;
  constexpr uint32_t PB = 5120;
  constexpr uint32_t STG = 2 * PA + PB;  // 25600

  const int lr = tid >> 1;
  const int lc = (tid & 1) * 2;
  const f16* pA0 = Ah + (size_t)(m0 + lr) * lda + lc * 8;
  const f16* pA1 = Al + (size_t)(m0 + lr) * lda + lc * 8;
  const int br = (tid & 127) >> 1, bcp = (tid & 1) * 2;
  const f16* pB = Bm + (size_t)(n0 + br) * ldb + bcp * 8;
  const uint32_t bOff = 2 * PA + (uint32_t)br * 80 + bcp * 16;

  auto stage_load = [&](int s, int k0) {
    uint32_t base = sb + (uint32_t)s * STG;
    uint32_t aA = base + (uint32_t)lr * 80 + lc * 16;
    cpa16(aA, pA0 + k0);
    cpa16(aA + 16, pA0 + k0 + 8);
    cpa16(aA + PA, pA1 + k0);
    cpa16(aA + PA + 16, pA1 + k0 + 8);
    if (tid < 128) {
      uint32_t aB = base + bOff;
      cpa16(aB, pB + k0);
      cpa16(aB + 16, pB + k0 + 8);
    }
    cpa_commit();
  };

  float acc[2][4][4];
#pragma unroll
  for (int i = 0; i < 2; i++)
#pragma unroll
    for (int j = 0; j < 4; j++)
#pragma unroll
      for (int q = 0; q < 4; q++) acc[i][j][q] = 0.f;

  const int nk = Kc / 32;
  stage_load(0, kstart);
  cpa_wait0();
  __syncthreads();

  const int g3 = lane >> 3, r8 = lane & 7;

  for (int kb = 0; kb < nk; ++kb) {
    const int s = kb & 1;
    if (kb + 1 < nk) stage_load(s ^ 1, kstart + (kb + 1) * 32);
    const uint32_t ab = sb + (uint32_t)s * STG;
#pragma unroll
    for (int k16 = 0; k16 < 32; k16 += 16) {
      uint32_t Ahf[2][4], Alf[2][4], Bf[4][2];
#pragma unroll
      for (int mi = 0; mi < 2; mi++) {
        uint32_t row = wm + mi * 16 + (g3 & 1) * 8 + r8;
        uint32_t col = k16 + (g3 >> 1) * 8;
        uint32_t ad = ab + row * 80 + col * 2;
        ldsm4(ad, Ahf[mi]);
        ldsm4(ad + PA, Alf[mi]);
      }
#pragma unroll
      for (int pi = 0; pi < 2; pi++) {
        uint32_t row = wn + (2 * pi + (g3 >> 1)) * 8 + r8;
        uint32_t col = k16 + (g3 & 1) * 8;
        uint32_t ad = ab + 2 * PA + row * 80 + col * 2;
        uint32_t t[4];
        ldsm4(ad, t);
        Bf[2 * pi][0] = t[0];
        Bf[2 * pi][1] = t[1];
        Bf[2 * pi + 1][0] = t[2];
        Bf[2 * pi + 1][1] = t[3];
      }
#pragma unroll
      for (int mi = 0; mi < 2; mi++)
#pragma unroll
        for (int ni = 0; ni < 4; ni++)
          mma_f16(acc[mi][ni], Ahf[mi], Bf[ni]);
#pragma unroll
      for (int mi = 0; mi < 2; mi++)
#pragma unroll
        for (int ni = 0; ni < 4; ni++)
          mma_f16(acc[mi][ni], Alf[mi], Bf[ni]);
    }
    cpa_wait0();
    __syncthreads();
  }

  float* cs = reinterpret_cast<float*>(smc);
  const int g = lane >> 2, t4 = lane & 3;
#pragma unroll
  for (int mi = 0; mi < 2; mi++)
#pragma unroll
    for (int ni = 0; ni < 4; ni++) {
      int r = wm + mi * 16 + g;
      int c = wn + ni * 8 + t4 * 2;
      *reinterpret_cast<float2*>(&cs[r * 68 + c]) =
          make_float2(acc[mi][ni][0], acc[mi][ni][1]);
      *reinterpret_cast<float2*>(&cs[(r + 8) * 68 + c]) =
          make_float2(acc[mi][ni][2], acc[mi][ni][3]);
    }
  __syncthreads();

#pragma unroll 4
  for (int rr = 0; rr < 16; ++rr) {
    int row = wid * 16 + rr;
    int m = m0 + row;
    int c = 2 * lane;
    float d0 = cs[row * 68 + c];
    float d1 = cs[row * 68 + c + 1];
    epi_pair<4>(m, n0 + c, d0, d1, ep);
  }
}

// ---------------- fused head GEMM slice (bf16, dual accumulators) ------------
__global__ __launch_bounds__(256, 2) void head_gemm(
    const bf16* __restrict__ Axh, const bf16* __restrict__ Axl,
    const bf16* __restrict__ Wqh, const bf16* __restrict__ Wql,
    const bf16* __restrict__ Wlh, const bf16* __restrict__ Wll,
    const float* __restrict__ blv, float* __restrict__ U,
    float* __restrict__ P, unsigned char* __restrict__ F,
    bf16* __restrict__ zh, bf16* __restrict__ zl, int coff) {
  extern __shared__ char smc[];
  const uint32_t sb = smem_u32(smc);
  const int tid = threadIdx.x, lane = tid & 31, wid = tid >> 5;
  const int m0 = blockIdx.y * 128, n0 = blockIdx.x * 64;
  const int wm = (wid & 3) * 32, wn = (wid >> 2) * 32;
  constexpr uint32_t PA = 10240;
  constexpr uint32_t PB = 5120;
  constexpr uint32_t STG = 2 * PA + 4 * PB;  // 40960

  const int lr = tid >> 1, lc = (tid & 1) * 2;
  const bf16* pA0 = Axh + (size_t)(m0 + lr) * Dd + lc * 8;
  const bf16* pA1 = Axl + (size_t)(m0 + lr) * Dd + lc * 8;
  const int br = (tid & 127) >> 1, bcp = (tid & 1) * 2;
  const int bw = tid >> 7;
  const bf16* pB0 = (bw ? Wlh : Wqh) + (size_t)(n0 + br) * Dd + bcp * 8;
  const bf16* pB1 = (bw ? Wll : Wql) + (size_t)(n0 + br) * Dd + bcp * 8;
  const uint32_t bOff = 2 * PA + (uint32_t)bw * 2 * PB + (uint32_t)br * 80 + bcp * 16;

  auto stage_load = [&](int s, int k0) {
    uint32_t base = sb + (uint32_t)s * STG;
    uint32_t aA = base + (uint32_t)lr * 80 + lc * 16;
    cpa16(aA, pA0 + k0);
    cpa16(aA + 16, pA0 + k0 + 8);
    cpa16(aA + PA, pA1 + k0);
    cpa16(aA + PA + 16, pA1 + k0 + 8);
    uint32_t aB = base + bOff;
    cpa16(aB, pB0 + k0);
    cpa16(aB + 16, pB0 + k0 + 8);
    cpa16(aB + PB, pB1 + k0);
    cpa16(aB + PB + 16, pB1 + k0 + 8);
    cpa_commit();
  };

  float accq[2][4][4], accl[2][4][4];
#pragma unroll
  for (int i = 0; i < 2; i++)
#pragma unroll
    for (int j = 0; j < 4; j++)
#pragma unroll
      for (int q = 0; q < 4; q++) accq[i][j][q] = accl[i][j][q] = 0.f;

  constexpr int nk = Dd / 32;
  stage_load(0, 0);
  cpa_wait0();
  __syncthreads();

  const int g3 = lane >> 3, r8 = lane & 7;

  for (int kb = 0; kb < nk; ++kb) {
    const int s = kb & 1;
    if (kb + 1 < nk) stage_load(s ^ 1, (kb + 1) * 32);
    const uint32_t ab = sb + (uint32_t)s * STG;
#pragma unroll
    for (int k16 = 0; k16 < 32; k16 += 16) {
      uint32_t Ahf[2][4], Alf[2][4];
      uint32_t Bqh_[4][2], Bql_[4][2], Blh_[4][2], Bll_[4][2];
#pragma unroll
      for (int mi = 0; mi < 2; mi++) {
        uint32_t row = wm + mi * 16 + (g3 & 1) * 8 + r8;
        uint32_t col = k16 + (g3 >> 1) * 8;
        uint32_t ad = ab + row * 80 + col * 2;
        ldsm4(ad, Ahf[mi]);
        ldsm4(ad + PA, Alf[mi]);
      }
#pragma unroll
      for (int pi = 0; pi < 2; pi++) {
        uint32_t row = wn + (2 * pi + (g3 >> 1)) * 8 + r8;
        uint32_t col = k16 + (g3 & 1) * 8;
        uint32_t adq = ab + 2 * PA + row * 80 + col * 2;
        uint32_t t[4];
        ldsm4(adq, t);
        Bqh_[2 * pi][0] = t[0]; Bqh_[2 * pi][1] = t[1];
        Bqh_[2 * pi + 1][0] = t[2]; Bqh_[2 * pi + 1][1] = t[3];
        ldsm4(adq + PB, t);
        Bql_[2 * pi][0] = t[0]; Bql_[2 * pi][1] = t[1];
        Bql_[2 * pi + 1][0] = t[2]; Bql_[2 * pi + 1][1] = t[3];
        ldsm4(adq + 2 * PB, t);
        Blh_[2 * pi][0] = t[0]; Blh_[2 * pi][1] = t[1];
        Blh_[2 * pi + 1][0] = t[2]; Blh_[2 * pi + 1][1] = t[3];
        ldsm4(adq + 3 * PB, t);
        Bll_[2 * pi][0] = t[0]; Bll_[2 * pi][1] = t[1];
        Bll_[2 * pi + 1][0] = t[2]; Bll_[2 * pi + 1][1] = t[3];
      }
#pragma unroll
      for (int mi = 0; mi < 2; mi++)
#pragma unroll
        for (int ni = 0; ni < 4; ni++) {
          mma_bf16(accq[mi][ni], Ahf[mi], Bqh_[ni]);
          mma_bf16(accq[mi][ni], Ahf[mi], Bql_[ni]);
          mma_bf16(accq[mi][ni], Alf[mi], Bqh_[ni]);
          mma_bf16(accl[mi][ni], Ahf[mi], Blh_[ni]);
          mma_bf16(accl[mi][ni], Ahf[mi], Bll_[ni]);
          mma_bf16(accl[mi][ni], Alf[mi], Blh_[ni]);
        }
    }
    cpa_wait0();
    __syncthreads();
  }

  float* cs = reinterpret_cast<float*>(smc);
  const int g = lane >> 2, t4 = lane & 3;
#pragma unroll
  for (int mi = 0; mi < 2; mi++)
#pragma unroll
    for (int ni = 0; ni < 4; ni++) {
      int r = wm + mi * 16 + g;
      int c = wn + ni * 8 + t4 * 2;
      *reinterpret_cast<float2*>(&cs[r * 132 + c]) =
          make_float2(accq[mi][ni][0], accq[mi][ni][1]);
      *reinterpret_cast<float2*>(&cs[(r + 8) * 132 + c]) =
          make_float2(accq[mi][ni][2], accq[mi][ni][3]);
      *reinterpret_cast<float2*>(&cs[r * 132 + 64 + c]) =
          make_float2(accl[mi][ni][0], accl[mi][ni][1]);
      *reinterpret_cast<float2*>(&cs[(r + 8) * 132 + 64 + c]) =
          make_float2(accl[mi][ni][2], accl[mi][ni][3]);
    }
  __syncthreads();

  const bool inZ = (coff == 0);
#pragma unroll 4
  for (int rr = 0; rr < 16; ++rr) {
    int row = wid * 16 + rr;
    int m = m0 + row;
    int c = 2 * lane;
    int n = coff + n0 + c;
    float u0 = cs[row * 132 + c], u1 = cs[row * 132 + c + 1];
    float v0 = cs[row * 132 + 64 + c], v1 = cs[row * 132 + 64 + c + 1];
    size_t idx = (size_t)m * LH + n;
    *reinterpret_cast<float2*>(&U[idx]) = make_float2(u0, u1);
    float2 b2 = *reinterpret_cast<const float2*>(&blv[n]);
    float p0 = u0 * u0 + v0 + b2.x;
    float p1 = u1 * u1 + v1 + b2.y;
    *reinterpret_cast<float2*>(&P[idx]) = make_float2(p0, p1);
    if (inZ) {
      bool s0 = (p0 >= 0.f), s1 = (p1 >= 0.f);
      uchar2 f2;
      f2.x = s0 ? 1 : 0;
      f2.y = s1 ? 1 : 0;
      *reinterpret_cast<uchar2*>(&F[idx]) = f2;
      float z0 = s0 ? p0 : NEG_SLOPE * p0;
      float z1 = s1 ? p1 : NEG_SLOPE * p1;
      bf16 h0, l0, h1, l1;
      bsplit(z0, h0, l0);
      bsplit(z1, h1, l1);
      __nv_bfloat162 hv, lv;
      hv.x = h0; hv.y = h1;
      lv.x = l0; lv.y = l1;
      *reinterpret_cast<__nv_bfloat162*>(&zh[(size_t)m * Hh + n0 + c]) = hv;
      *reinterpret_cast<__nv_bfloat162*>(&zl[(size_t)m * Hh + n0 + c]) = lv;
    }
  }
}

// ---------------- prep / elementwise ----------------------------------------
__global__ void k_split3(const float* __restrict__ x, const float* __restrict__ Wq,
                         const float* __restrict__ Wl, bf16* __restrict__ xh,
                         bf16* __restrict__ xl, bf16* __restrict__ qh,
                         bf16* __restrict__ ql, bf16* __restrict__ lh,
                         bf16* __restrict__ ll) {
  int i = blockIdx.x * 256 + threadIdx.x;
  const int n1 = Bsz * Dd, n2 = LH * Dd;
  bf16 h, l;
  if (i < n1) {
    bsplit(x[i], h, l);
    xh[i] = h; xl[i] = l;
  } else if (i < n1 + n2) {
    int j = i - n1;
    bsplit(Wq[j], h, l);
    qh[j] = h; ql[j] = l;
  } else if (i < n1 + 2 * n2) {
    int j = i - n1 - n2;
    bsplit(Wl[j], h, l);
    lh[j] = h; ll[j] = l;
  }
}

__global__ void k_split(const float* __restrict__ in, bf16* __restrict__ h,
                        bf16* __restrict__ l, int n) {
  int i = blockIdx.x * 256 + threadIdx.x;
  if (i < n) {
    bf16 hh, ll;
    bsplit(in[i], hh, ll);
    h[i] = hh;
    l[i] = ll;
  }
}

__global__ void k_wzT16(const float* __restrict__ Wz, f16* __restrict__ o) {
  int i = blockIdx.x * 256 + threadIdx.x;
  int lay = i / (Hh * Hh);
  int r = i % (Hh * Hh);
  int oo = r / Hh, ii = r % Hh;
  o[(size_t)lay * Hh * Hh + (size_t)ii * Hh + oo] = __float2half_rn(Wz[i]);
}

__global__ void k_bcat16(const float* __restrict__ Wq, const float* __restrict__ Wl,
                         f16* __restrict__ o) {
  int i = blockIdx.x * 256 + threadIdx.x;
  int lay = i / (Dd * 1024);
  int r = i % (Dd * 1024);
  int d = r / 1024, k = r % 1024;
  float v = (k < Hh) ? Wq[((size_t)lay * Hh + k) * Dd + d]
                     : Wl[((size_t)lay * Hh + (k - Hh)) * Dd + d];
  o[i] = __float2half_rn(v);
}

__global__ void k_dotzero(const float* __restrict__ x, const float* __restrict__ wq,
                          float* __restrict__ S, float* __restrict__ gx) {
  int gid = blockIdx.x * 256 + threadIdx.x;
  if (gid < Bsz * Dd) gx[gid] = 0.f;
  int w = gid / 32, lane = gid % 32;
  if (w < Bsz) {
    float s = 0.f;
    for (int d = lane; d < Dd; d += 32) s += x[(size_t)w * Dd + d] * wq[d];
#pragma unroll
    for (int o = 16; o; o >>= 1) s += __shfl_xor_sync(0xFFFFFFFFu, s, o);
    if (lane == 0) S[w] = s;
  }
}

// bwinit: t9 = ga9 (scale 16^0) as fp16 pair; Acat[1] direct.
__global__ void k_bwinit(const unsigned char* __restrict__ F,
                         const float* __restrict__ U,
                         const float* __restrict__ wz_out,
                         f16* __restrict__ th, f16* __restrict__ tl,
                         f16* __restrict__ ach, f16* __restrict__ acl) {
  int i = blockIdx.x * 256 + threadIdx.x;
  int m = i / Hh, h = i % Hh;
  size_t idx = (size_t)m * LH + (size_t)(Ll - 1) * Hh + h;
  float f = F[idx] ? 1.f : NEG_SLOPE;
  float ga = wz_out[h] * f;
  f16 hh, ll;
  hsplit(ga, hh, ll);
  th[i] = hh;
  tl[i] = ll;
  float g1 = 2.f * ga * U[idx];
  f16 h1, l1;
  size_t ai = (size_t)m * 1024 + h;
  hsplit(g1, h1, l1);
  ach[ai] = h1;
  acl[ai] = l1;
  ach[ai + Hh] = hh;
  acl[ai + Hh] = ll;
}

// Build fp16 Acat for layer l from fp16 t pair + U (t already scaled).
__global__ void k_acat(const f16* __restrict__ th, const f16* __restrict__ tl,
                       const float* __restrict__ U, f16* __restrict__ ach,
                       f16* __restrict__ acl, int coff) {
  int i = blockIdx.x * 256 + threadIdx.x;  // Bsz*Hh
  int m = i / Hh, h = i % Hh;
  float as = __half2float(th[i]) + __half2float(tl[i]);
  float g1 = 2.f * as * U[(size_t)m * LH + coff + h];
  f16 a, b;
  size_t ai = (size_t)m * 1024 + h;
  hsplit(g1, a, b);
  ach[ai] = a;
  acl[ai] = b;
  hsplit(as, a, b);
  ach[ai + Hh] = a;
  acl[ai + Hh] = b;
}

__global__ void k_final(const float* __restrict__ gx, const float* __restrict__ S,
                        const float* __restrict__ wq, const float* __restrict__ wl,
                        const float* __restrict__ x, float* __restrict__ out) {
  int i = blockIdx.x * 256 + threadIdx.x;
  int m = i >> 7, n = i & 127;
  out[i] = 0.5f * (gx[i] + 2.f * S[m] * wq[n] + wl[n]) + 0.5f * x[i];
}

// ---------------- host driver ------------------------------------------------
constexpr uint32_t SMEM_SZ = 81920;
constexpr uint32_t SMEM_BWD = 67584;   // max(2*30720, 128*132*4=67584)
constexpr uint32_t SMEM_TAIL = 51200;

extern "C" void kernel_launch(void* const* d_in, const int* in_sizes, int n_in,
                              void* d_out, int out_size) {
  const float* x = (const float*)d_in[0];
  const float* Wq = (const float*)d_in[1];
  const float* Wl = (const float*)d_in[2];
  const float* bl = (const float*)d_in[3];
  const float* Wz = (const float*)d_in[4];
  const float* wz_out = (const float*)d_in[5];
  const float* wq_out = (const float*)d_in[6];
  const float* wl_out = (const float*)d_in[7];
  float* out = (float*)d_out;

  bf16 *xh, *xl, *Wqh, *Wql, *Wlh, *Wll, *Wzh, *Wzl;
  bf16 *zAh, *zAl, *zBh, *zBl;
  f16 *WzT16, *Bc16, *Ach[2], *Acl[2];
  f16 *tAh, *tAl, *tBh, *tBl;
  float *U, *P, *gx, *S;
  unsigned char* F;
  cudaGetSymbolAddress((void**)&xh, g_xh);
  cudaGetSymbolAddress((void**)&xl, g_xl);
  cudaGetSymbolAddress((void**)&Wqh, g_Wqh);
  cudaGetSymbolAddress((void**)&Wql, g_Wql);
  cudaGetSymbolAddress((void**)&Wlh, g_Wlh);
  cudaGetSymbolAddress((void**)&Wll, g_Wll);
  cudaGetSymbolAddress((void**)&Wzh, g_Wzh);
  cudaGetSymbolAddress((void**)&Wzl, g_Wzl);
  cudaGetSymbolAddress((void**)&WzT16, g_WzT16);
  cudaGetSymbolAddress((void**)&Bc16, g_Bc16);
  cudaGetSymbolAddress((void**)&U, g_U);
  cudaGetSymbolAddress((void**)&P, g_P);
  cudaGetSymbolAddress((void**)&F, g_F);
  cudaGetSymbolAddress((void**)&zAh, g_zAh);
  cudaGetSymbolAddress((void**)&zAl, g_zAl);
  cudaGetSymbolAddress((void**)&zBh, g_zBh);
  cudaGetSymbolAddress((void**)&zBl, g_zBl);
  cudaGetSymbolAddress((void**)&tAh, g_tAh);
  cudaGetSymbolAddress((void**)&tAl, g_tAl);
  cudaGetSymbolAddress((void**)&tBh, g_tBh);
  cudaGetSymbolAddress((void**)&tBl, g_tBl);
  cudaGetSymbolAddress((void**)&Ach[0], g_Ach0);
  cudaGetSymbolAddress((void**)&Acl[0], g_Acl0);
  cudaGetSymbolAddress((void**)&Ach[1], g_Ach1);
  cudaGetSymbolAddress((void**)&Acl[1], g_Acl1);
  cudaGetSymbolAddress((void**)&gx, g_gx);
  cudaGetSymbolAddress((void**)&S, g_S);

  static bool s_init = false;
  static cudaStream_t st1, st2;
  static cudaEvent_t evStart, evSplit, evWz, evWzT, evHd[10], evBw[10],
      evAcat[10], evT2;
  if (!s_init) {
    cudaStreamCreateWithFlags(&st1, cudaStreamNonBlocking);
    cudaStreamCreateWithFlags(&st2, cudaStreamNonBlocking);
    cudaEventCreateWithFlags(&evStart, cudaEventDisableTiming);
    cudaEventCreateWithFlags(&evSplit, cudaEventDisableTiming);
    cudaEventCreateWithFlags(&evWz, cudaEventDisableTiming);
    cudaEventCreateWithFlags(&evWzT, cudaEventDisableTiming);
    cudaEventCreateWithFlags(&evT2, cudaEventDisableTiming);
    for (int i = 0; i < 10; i++) {
      cudaEventCreateWithFlags(&evHd[i], cudaEventDisableTiming);
      cudaEventCreateWithFlags(&evBw[i], cudaEventDisableTiming);
      cudaEventCreateWithFlags(&evAcat[i], cudaEventDisableTiming);
    }
    cudaFuncSetAttribute(mma_gemm<2>, cudaFuncAttributeMaxDynamicSharedMemorySize, SMEM_SZ);
    cudaFuncSetAttribute(bwd_gemm, cudaFuncAttributeMaxDynamicSharedMemorySize, SMEM_BWD);
    cudaFuncSetAttribute(tail_gemm, cudaFuncAttributeMaxDynamicSharedMemorySize, SMEM_TAIL);
    cudaFuncSetAttribute(head_gemm, cudaFuncAttributeMaxDynamicSharedMemorySize, SMEM_SZ);
    s_init = true;
  }

  // ---- fork side streams ----
  cudaEventRecord(evStart, 0);
  cudaStreamWaitEvent(st1, evStart, 0);
  cudaStreamWaitEvent(st2, evStart, 0);

  // s0: input/weight splits
  {
    int tot = Bsz * Dd + 2 * LH * Dd;
    k_split3<<<(tot + 255) / 256, 256>>>(x, Wq, Wl, xh, xl, Wqh, Wql, Wlh, Wll);
  }
  cudaEventRecord(evSplit, 0);

  // st2: Wz split (fwd bf16), WzT fp16, tail weights, dot+gx zero
  k_split<<<((Ll - 1) * Hh * Hh + 255) / 256, 256, 0, st2>>>(
      Wz, Wzh, Wzl, (Ll - 1) * Hh * Hh);
  cudaEventRecord(evWz, st2);
  k_wzT16<<<((Ll - 1) * Hh * Hh + 255) / 256, 256, 0, st2>>>(Wz, WzT16);
  cudaEventRecord(evWzT, st2);
  k_bcat16<<<(Ll * Dd * 1024 + 255) / 256, 256, 0, st2>>>(Wq, Wl, Bc16);
  k_dotzero<<<(Bsz * Dd + 255) / 256, 256, 0, st2>>>(x, wq_out, S, gx);

  // st1: per-layer head slices
  cudaStreamWaitEvent(st1, evSplit, 0);
  for (int l = 0; l < Ll; ++l) {
    head_gemm<<<dim3(Hh / 64, Bsz / 128), 256, SMEM_SZ, st1>>>(
        xh, xl, Wqh + (size_t)l * Hh * Dd, Wql + (size_t)l * Hh * Dd,
        Wlh + (size_t)l * Hh * Dd, Wll + (size_t)l * Hh * Dd, bl, U, P, F,
        zAh, zAl, l * Hh);
    cudaEventRecord(evHd[l], st1);
  }

  // s0: forward chain; layer l waits on head slice l
  bf16* zh2[2] = {zAh, zBh};
  bf16* zl2[2] = {zAl, zBl};
  cudaStreamWaitEvent(0, evWz, 0);
  for (int l = 1; l < Ll; ++l) {
    cudaStreamWaitEvent(0, evHd[l], 0);
    EpiP ep = {};
    ep.Pc = P;
    ep.F = F;
    ep.coff = l * Hh;
    ep.zh = zh2[l & 1];
    ep.zl = zl2[l & 1];
    mma_gemm<2><<<dim3(Hh / 128, Bsz / 128, 1), 256, SMEM_SZ>>>(
        zh2[(l - 1) & 1], zl2[(l - 1) & 1], Wzh + (size_t)(l - 1) * Hh * Hh,
        Wzl + (size_t)(l - 1) * Hh * Hh, Hh, Hh, Hh, ep);
  }

  // ---- backward init (layer 9): t9 -> tA; fp16 Acat buf[1] direct ----
  f16* th2[2] = {tAh, tBh};
  f16* tl2[2] = {tAl, tBl};
  k_bwinit<<<(Bsz * Hh + 255) / 256, 256>>>(F, U, wz_out, tAh, tAl, Ach[1],
                                            Acl[1]);
  cudaEventRecord(evBw[9], 0);

  cudaStreamWaitEvent(st2, evBw[9], 0);
  {
    EpiP ep = {};
    ep.gx = gx;
    ep.tscale = 1.f;
    tail_gemm<<<dim3(Dd / 64, Bsz / 128, 2), 256, SMEM_TAIL, st2>>>(
        Ach[1], Acl[1], Bc16 + (size_t)(Ll - 1) * Dd * 1024, 512, 1024, 1024,
        ep);
  }

  // ---- backward chain (fp16, 2 products) on s0; acat + tails on st2 ----
  cudaStreamWaitEvent(0, evWzT, 0);
  int cur = 0;  // th2[cur] holds t_{l+1}
  for (int l = Ll - 2; l >= 0; --l) {
    if (l + 2 <= Ll - 2) cudaStreamWaitEvent(0, evAcat[l + 2], 0);
    {
      EpiP ep = {};
      ep.F = F;
      ep.coff = l * Hh;
      ep.th = th2[cur ^ 1];
      ep.tl = tl2[cur ^ 1];
      bwd_gemm<<<dim3(Hh / 128, Bsz / 128, 1), 256, SMEM_BWD>>>(
          th2[cur], tl2[cur], WzT16 + (size_t)l * Hh * Hh, Hh, Hh, Hh, ep);
    }
    cudaEventRecord(evBw[l], 0);
    float ts = 1.f;
    for (int t = 0; t < 9 - l; ++t) ts *= 16.f;
    if (l > 0) {
      cudaStreamWaitEvent(st2, evBw[l], 0);
      k_acat<<<(Bsz * Hh + 255) / 256, 256, 0, st2>>>(
          th2[cur ^ 1], tl2[cur ^ 1], U, Ach[l & 1], Acl[l & 1], l * Hh);
      cudaEventRecord(evAcat[l], st2);
      EpiP ep = {};
      ep.gx = gx;
      ep.tscale = ts;
      tail_gemm<<<dim3(Dd / 64, Bsz / 128, 2), 256, SMEM_TAIL, st2>>>(
          Ach[l & 1], Acl[l & 1], Bc16 + (size_t)l * Dd * 1024, 512, 1024,
          1024, ep);
      if (l == 1) cudaEventRecord(evT2, st2);
    } else {
      // l == 0 on stream 0: no event hops; K-split x4 on idle chip.
      k_acat<<<(Bsz * Hh + 255) / 256, 256>>>(th2[cur ^ 1], tl2[cur ^ 1], U,
                                              Ach[0], Acl[0], 0);
      EpiP ep = {};
      ep.gx = gx;
      ep.tscale = ts;
      tail_gemm<<<dim3(Dd / 64, Bsz / 128, 4), 256, SMEM_TAIL>>>(
          Ach[0], Acl[0], Bc16, 256, 1024, 1024, ep);
    }
    cur ^= 1;
  }

  // ---- join (st2 FIFO: evT2 covers tails 9..1) and final combine ----
  cudaStreamWaitEvent(0, evT2, 0);
  k_final<<<(Bsz * Dd + 255) / 256, 256>>>(gx, S, wq_out, wl_out, x, out);
}